// round 10
// baseline (speedup 1.0000x reference)
#include <cuda_runtime.h>
#include <cuda.h>
#include <cuda_bf16.h>
#include <cstdint>

#define SLEN 2048
#define BATCH 4
#define DMODEL 1024
#define NHEAD 16
#define DKH 64
#define DFFN 4096
#define NTOK (SLEN*BATCH)   // 8192
#define LN_EPS 1e-5f
#define QSCALE 0.18033688011112042f   // 0.125 * log2(e)

// ---------------- scratch (device globals) ----------------------------------
__device__ __align__(1024) float g_Y[2*NTOK*DMODEL];
__device__ __align__(1024) float g_X1[NTOK*DMODEL];
__device__ __align__(1024) float g_M[2*NTOK*DMODEL];
__device__ __align__(1024) float g_ACC[2*NTOK*DMODEL];
__device__ __align__(1024) float g_L[2*NTOK*NHEAD];

__device__ __align__(1024) __nv_bfloat16 g_Xhi[NTOK*DMODEL],  g_Xlo[NTOK*DMODEL];
__device__ __align__(1024) __nv_bfloat16 g_X1hi[NTOK*DMODEL], g_X1lo[NTOK*DMODEL];
__device__ __align__(1024) __nv_bfloat16 g_CTXhi[NTOK*DMODEL],g_CTXlo[NTOK*DMODEL];
__device__ __align__(1024) __nv_bfloat16 g_Qhi[NTOK*DMODEL],  g_Qlo[NTOK*DMODEL];
__device__ __align__(1024) __nv_bfloat16 g_Khi[NTOK*DMODEL],  g_Klo[NTOK*DMODEL];
__device__ __align__(1024) __nv_bfloat16 g_Vhi[NTOK*DMODEL],  g_Vlo[NTOK*DMODEL];
__device__ __align__(1024) __nv_bfloat16 g_VThi[NTOK*DMODEL], g_VTlo[NTOK*DMODEL];
__device__ __align__(1024) __nv_bfloat16 g_HIDhi[NTOK*DFFN],  g_HIDlo[NTOK*DFFN];
__device__ __align__(1024) __nv_bfloat16 g_WQKVhi[3*DMODEL*DMODEL], g_WQKVlo[3*DMODEL*DMODEL];
__device__ __align__(1024) __nv_bfloat16 g_WOhi[DMODEL*DMODEL], g_WOlo[DMODEL*DMODEL];
__device__ __align__(1024) __nv_bfloat16 g_W1hi[DFFN*DMODEL],   g_W1lo[DFFN*DMODEL];
__device__ __align__(1024) __nv_bfloat16 g_W2hi[DMODEL*DFFN],   g_W2lo[DMODEL*DFFN];

// ---------------- PTX helpers (base-ISA only) --------------------------------
__device__ __forceinline__ uint32_t smem_to_u32(const void* p) {
    uint32_t a;
    asm("{ .reg .u64 t; cvta.to.shared.u64 t, %1; cvt.u32.u64 %0, t; }" : "=r"(a) : "l"(p));
    return a;
}
#define MBARRIER_INIT(mbar, cnt) \
    asm volatile("mbarrier.init.shared.b64 [%0], %1;" :: "r"((uint32_t)(mbar)), "r"((uint32_t)(cnt)) : "memory")
#define MBARRIER_EXPECT_TX(mbar, bytes) \
    asm volatile("mbarrier.arrive.expect_tx.shared.b64 _, [%0], %1;" :: "r"((uint32_t)(mbar)), "r"((uint32_t)(bytes)) : "memory")
#define MBARRIER_ARRIVE(mbar) \
    asm volatile("mbarrier.arrive.shared.b64 _, [%0];" :: "r"((uint32_t)(mbar)) : "memory")
#define FENCE_ASYNC_SHARED() asm volatile("fence.proxy.async.shared::cta;" ::: "memory")

#define MBARRIER_WAIT_PARITY(mbar_smem_addr, phase_parity) do { \
    uint32_t _mbar = (uint32_t)(mbar_smem_addr); \
    uint32_t _parity = (uint32_t)(phase_parity); \
    uint32_t _done; \
    asm volatile("{ .reg .pred p; mbarrier.try_wait.parity.acquire.cta.shared::cta.b64 p, [%1], %2; selp.b32 %0, 1, 0, p; }" \
        : "=r"(_done) : "r"(_mbar), "r"(_parity) : "memory"); \
    if (!_done) { \
        asm volatile("{ .reg .pred P1; WAIT_LOOP_%=: mbarrier.try_wait.parity.acquire.cta.shared::cta.b64 P1, [%0], %1, 0x989680; @P1 bra.uni WAIT_DONE_%=; bra.uni WAIT_LOOP_%=; WAIT_DONE_%=: }" \
            :: "r"(_mbar), "r"(_parity) : "memory"); \
    } \
} while(0)

__device__ __forceinline__ void tma_load_2d(uint32_t dst_smem, const CUtensorMap* m,
                                            int x, int y, uint32_t mbar) {
    asm volatile(
        "cp.async.bulk.tensor.2d.shared::cta.global.tile.mbarrier::complete_tx::bytes "
        "[%0], [%1, {%2, %3}], [%4];"
        :: "r"(dst_smem), "l"(m), "r"(x), "r"(y), "r"(mbar) : "memory");
}

__device__ __forceinline__ void mma_bf16(float* d, const uint32_t* a, const uint32_t* b) {
    asm volatile(
        "mma.sync.aligned.m16n8k16.row.col.f32.bf16.bf16.f32 "
        "{%0,%1,%2,%3},{%4,%5,%6,%7},{%8,%9},{%0,%1,%2,%3};"
        : "+f"(d[0]), "+f"(d[1]), "+f"(d[2]), "+f"(d[3])
        : "r"(a[0]), "r"(a[1]), "r"(a[2]), "r"(a[3]), "r"(b[0]), "r"(b[1]));
}

__device__ __forceinline__ void ldsm_x4(uint32_t* r, uint32_t addr) {
    asm volatile("ldmatrix.sync.aligned.m8n8.x4.shared.b16 {%0,%1,%2,%3}, [%4];"
        : "=r"(r[0]), "=r"(r[1]), "=r"(r[2]), "=r"(r[3]) : "r"(addr));
}

__device__ __forceinline__ float ex2f(float x) {
    float y; asm("ex2.approx.f32 %0, %1;" : "=f"(y) : "f"(x)); return y;
}

// fast hi/lo split: hi = truncated-bf16 pair via PRMT, lo = packed via cvt.bf16x2
__device__ __forceinline__ void split_pack2(float a, float b, uint32_t& hi, uint32_t& lo) {
    uint32_t ua = __float_as_uint(a), ub = __float_as_uint(b);
    uint32_t h;
    asm("prmt.b32 %0, %1, %2, 0x7632;" : "=r"(h) : "r"(ua), "r"(ub));
    float la = a - __uint_as_float(ua & 0xffff0000u);
    float lb = b - __uint_as_float(ub & 0xffff0000u);
    uint32_t l;
    asm("cvt.rn.bf16x2.f32 %0, %1, %2;" : "=r"(l) : "f"(lb), "f"(la));
    hi = h; lo = l;
}

// ---------------- fused fp32 -> bf16 hi/lo split (multi-segment) -------------
#define CVT_SEGS 7
#define CVT_CHUNK 512
struct CvtArgs {
    const float* src[CVT_SEGS];
    __nv_bfloat16* hi[CVT_SEGS];
    __nv_bfloat16* lo[CVT_SEGS];
    int blk_end[CVT_SEGS];
    int n4[CVT_SEGS];
};

__global__ void __launch_bounds__(256) cvt_multi_kernel(const __grid_constant__ CvtArgs a)
{
    int seg = 0;
#pragma unroll
    for (int k = 0; k < CVT_SEGS - 1; k++)
        if (blockIdx.x >= (unsigned)a.blk_end[k]) seg = k + 1;
    const int local = blockIdx.x - (seg ? a.blk_end[seg - 1] : 0);
    const float* src = a.src[seg];
    __nv_bfloat16* hi = a.hi[seg];
    __nv_bfloat16* lo = a.lo[seg];
    const int n4 = a.n4[seg];
#pragma unroll
    for (int p = 0; p < 2; p++) {
        int i = local * CVT_CHUNK + p * 256 + threadIdx.x;
        if (i < n4) {
            float4 v = ((const float4*)src)[i];
            uint2 uh, ul;
            split_pack2(v.x, v.y, uh.x, ul.x);
            split_pack2(v.z, v.w, uh.y, ul.y);
            ((uint2*)hi)[i] = uh;
            ((uint2*)lo)[i] = ul;
        }
    }
}

// ---------------- split-bf16 GEMM mainloop: 64x128 tile, occ 2 ---------------
#define ST_AHI 0
#define ST_ALO 8192
#define ST_BHI 16384
#define ST_BLO 32768
#define ST_BYTES 49152
#define NPIPE 2
#define GEMM_SMEM (NPIPE*ST_BYTES + 64)

__device__ __forceinline__ void gemm_mainloop(
    const CUtensorMap* mAhi, const CUtensorMap* mAlo,
    const CUtensorMap* mBhi, const CUtensorMap* mBlo,
    int bm, int bn, int s0, int nst, char* smem, float acc[][4][4])
{
    const uint32_t sbase = smem_to_u32(smem);
    const uint32_t mbb = sbase + NPIPE * ST_BYTES;
    const int tid = threadIdx.x;
    const int wid = tid >> 5;
    const int lane = tid & 31;
    const int wm = wid & 1;
    const int wn = wid >> 1;

    if (tid == 0) {
#pragma unroll
        for (int i = 0; i < NPIPE; i++) {
            MBARRIER_INIT(mbb + i * 8, 1);        // full
            MBARRIER_INIT(mbb + 16 + i * 8, 8);   // empty (8 warps)
        }
    }
    FENCE_ASYNC_SHARED();
    __syncthreads();

    if (tid == 0) {
#pragma unroll
        for (int s = 0; s < NPIPE; s++) {
            uint32_t mb = mbb + s * 8;
            uint32_t dst = sbase + s * ST_BYTES;
            MBARRIER_EXPECT_TX(mb, ST_BYTES);
            tma_load_2d(dst + ST_AHI, mAhi, (s0 + s) * 64, bm, mb);
            tma_load_2d(dst + ST_ALO, mAlo, (s0 + s) * 64, bm, mb);
            tma_load_2d(dst + ST_BHI, mBhi, (s0 + s) * 64, bn, mb);
            tma_load_2d(dst + ST_BLO, mBlo, (s0 + s) * 64, bn, mb);
        }
    }

    const uint32_t m16 = (lane & 7) * 16;
    const int rA = (lane & 7) + ((lane >> 3) & 1) * 8;
    const uint32_t hA = ((lane >> 4) & 1) * 16;
    const int rB = (lane & 7) + ((lane >> 4) & 1) * 8;
    const uint32_t hB = ((lane >> 3) & 1) * 16;
    uint32_t aoff[2], boff[2];
#pragma unroll
    for (int t = 0; t < 2; t++) aoff[t] = (uint32_t)(wm * 32 + t * 16 + rA) * 128;
#pragma unroll
    for (int jp = 0; jp < 2; jp++) boff[jp] = (uint32_t)(wn * 32 + jp * 16 + rB) * 128;

    int buf = 0, ph = 0;
    for (int s = 0; s < nst; s++) {
        MBARRIER_WAIT_PARITY(mbb + buf * 8, ph);
        const uint32_t sb = sbase + buf * ST_BYTES;

#pragma unroll
        for (int ks = 0; ks < 4; ks++) {
            const uint32_t cA = (ks * 32 + hA) ^ m16;
            const uint32_t cB = (ks * 32 + hB) ^ m16;
            uint32_t ah[2][4], al[2][4];
#pragma unroll
            for (int t = 0; t < 2; t++) {
                ldsm_x4(ah[t], sb + ST_AHI + aoff[t] + cA);
                ldsm_x4(al[t], sb + ST_ALO + aoff[t] + cA);
            }
            uint32_t bh[2][4], bl[2][4];
#pragma unroll
            for (int jp = 0; jp < 2; jp++) {
                ldsm_x4(bh[jp], sb + ST_BHI + boff[jp] + cB);
                ldsm_x4(bl[jp], sb + ST_BLO + boff[jp] + cB);
            }
#pragma unroll
            for (int t = 0; t < 2; t++)
#pragma unroll
                for (int jp = 0; jp < 2; jp++) {
                    mma_bf16(acc[t][2*jp],   ah[t], &bh[jp][0]);
                    mma_bf16(acc[t][2*jp],   ah[t], &bl[jp][0]);
                    mma_bf16(acc[t][2*jp],   al[t], &bh[jp][0]);
                    mma_bf16(acc[t][2*jp+1], ah[t], &bh[jp][2]);
                    mma_bf16(acc[t][2*jp+1], ah[t], &bl[jp][2]);
                    mma_bf16(acc[t][2*jp+1], al[t], &bh[jp][2]);
                }
        }

        if (lane == 0) MBARRIER_ARRIVE(mbb + 16 + buf * 8);
        if (tid == 0 && s + NPIPE < nst) {
            MBARRIER_WAIT_PARITY(mbb + 16 + buf * 8, ph);
            uint32_t mb = mbb + buf * 8;
            uint32_t dst = sbase + buf * ST_BYTES;
            MBARRIER_EXPECT_TX(mb, ST_BYTES);
            tma_load_2d(dst + ST_AHI, mAhi, (s0 + s + NPIPE) * 64, bm, mb);
            tma_load_2d(dst + ST_ALO, mAlo, (s0 + s + NPIPE) * 64, bm, mb);
            tma_load_2d(dst + ST_BHI, mBhi, (s0 + s + NPIPE) * 64, bn, mb);
            tma_load_2d(dst + ST_BLO, mBlo, (s0 + s + NPIPE) * 64, bn, mb);
        }
        if (++buf == NPIPE) { buf = 0; ph ^= 1; }
    }
}

// ---------------- generic GEMM kernel (64x128 out per CTA; optional split-K) -
template<int WRITE_F32, int WRITE_HILO, int RELU>
__global__ void __launch_bounds__(256, 2) gemm_mma_kernel(
    const __grid_constant__ CUtensorMap mAhi,
    const __grid_constant__ CUtensorMap mAlo,
    const __grid_constant__ CUtensorMap mBhi,
    const __grid_constant__ CUtensorMap mBlo,
    const float* __restrict__ bias,
    float* __restrict__ C, __nv_bfloat16* __restrict__ Chi, __nv_bfloat16* __restrict__ Clo,
    int N, int K)
{
    extern __shared__ char smem[];
    const int bm = blockIdx.y * 64;
    const int bn = blockIdx.x * 128;
    const int kz = blockIdx.z;
    const int kpart = K / gridDim.z;
    float acc[2][4][4];
#pragma unroll
    for (int t = 0; t < 2; t++)
#pragma unroll
        for (int j = 0; j < 4; j++)
#pragma unroll
            for (int q = 0; q < 4; q++) acc[t][j][q] = 0.f;

    gemm_mainloop(&mAhi, &mAlo, &mBhi, &mBlo, bm, bn,
                  kz * (kpart >> 6), kpart >> 6, smem, acc);

    float* Cout = C + (size_t)kz * NTOK * N;
    const int lane = threadIdx.x & 31;
    const int wid = threadIdx.x >> 5;
    const int g = lane >> 2, tq = lane & 3;
    const int wm = wid & 1, wn = wid >> 1;
#pragma unroll
    for (int t = 0; t < 2; t++) {
        int row = bm + wm * 32 + t * 16 + g;
#pragma unroll
        for (int j = 0; j < 4; j++) {
            int col = bn + wn * 32 + j * 8 + tq * 2;
            // bias added only in the z=0 plane for split-K
            float bx = 0.f, by = 0.f;
            if (kz == 0) { float2 bj = *(const float2*)&bias[col]; bx = bj.x; by = bj.y; }
            float v0 = acc[t][j][0] + bx;
            float v1 = acc[t][j][1] + by;
            float v2 = acc[t][j][2] + bx;
            float v3 = acc[t][j][3] + by;
            if (RELU) {
                v0 = fmaxf(v0, 0.f); v1 = fmaxf(v1, 0.f);
                v2 = fmaxf(v2, 0.f); v3 = fmaxf(v3, 0.f);
            }
            if (WRITE_F32) {
                *(float2*)&Cout[(size_t)row * N + col]       = make_float2(v0, v1);
                *(float2*)&Cout[(size_t)(row + 8) * N + col] = make_float2(v2, v3);
            }
            if (WRITE_HILO) {
                uint32_t h01, l01, h23, l23;
                split_pack2(v0, v1, h01, l01);
                split_pack2(v2, v3, h23, l23);
                *(uint32_t*)&Chi[(size_t)row * N + col]       = h01;
                *(uint32_t*)&Chi[(size_t)(row + 8) * N + col] = h23;
                *(uint32_t*)&Clo[(size_t)row * N + col]       = l01;
                *(uint32_t*)&Clo[(size_t)(row + 8) * N + col] = l23;
            }
        }
    }
}

// ---------------- fused QKV GEMM (N=3072 packed; scatter epilogue) -----------
__global__ void __launch_bounds__(256, 2) gemm_qkv_kernel(
    const __grid_constant__ CUtensorMap mAhi,
    const __grid_constant__ CUtensorMap mAlo,
    const __grid_constant__ CUtensorMap mBhi,
    const __grid_constant__ CUtensorMap mBlo,
    const float* __restrict__ bQ, const float* __restrict__ bK, const float* __restrict__ bV,
    __nv_bfloat16* __restrict__ Qhi, __nv_bfloat16* __restrict__ Qlo,
    __nv_bfloat16* __restrict__ Khi, __nv_bfloat16* __restrict__ Klo,
    __nv_bfloat16* __restrict__ Vhi, __nv_bfloat16* __restrict__ Vlo)
{
    extern __shared__ char smem[];
    const int bm = blockIdx.y * 64;
    const int bn = blockIdx.x * 128;
    float acc[2][4][4];
#pragma unroll
    for (int t = 0; t < 2; t++)
#pragma unroll
        for (int j = 0; j < 4; j++)
#pragma unroll
            for (int q = 0; q < 4; q++) acc[t][j][q] = 0.f;

    gemm_mainloop(&mAhi, &mAlo, &mBhi, &mBlo, bm, bn, 0, DMODEL >> 6, smem, acc);

    const int part = blockIdx.x >> 3;          // 0=Q 1=K 2=V
    const int nb = (blockIdx.x & 7) * 128;
    const float* bias = (part == 0) ? bQ : (part == 1) ? bK : bV;
    __nv_bfloat16* Ohi = (part == 0) ? Qhi : (part == 1) ? Khi : Vhi;
    __nv_bfloat16* Olo = (part == 0) ? Qlo : (part == 1) ? Klo : Vlo;
    const float scl = (part == 0) ? QSCALE : 1.0f;

    const int lane = threadIdx.x & 31;
    const int wid = threadIdx.x >> 5;
    const int g = lane >> 2, tq = lane & 3;
    const int wm = wid & 1, wn = wid >> 1;
#pragma unroll
    for (int t = 0; t < 2; t++) {
        int row = bm + wm * 32 + t * 16 + g;
#pragma unroll
        for (int j = 0; j < 4; j++) {
            int col = nb + wn * 32 + j * 8 + tq * 2;
            float2 bj = *(const float2*)&bias[col];
            float v0 = (acc[t][j][0] + bj.x) * scl;
            float v1 = (acc[t][j][1] + bj.y) * scl;
            float v2 = (acc[t][j][2] + bj.x) * scl;
            float v3 = (acc[t][j][3] + bj.y) * scl;
            uint32_t h01, l01, h23, l23;
            split_pack2(v0, v1, h01, l01);
            split_pack2(v2, v3, h23, l23);
            *(uint32_t*)&Ohi[(size_t)row * DMODEL + col]       = h01;
            *(uint32_t*)&Ohi[(size_t)(row + 8) * DMODEL + col] = h23;
            *(uint32_t*)&Olo[(size_t)row * DMODEL + col]       = l01;
            *(uint32_t*)&Olo[(size_t)(row + 8) * DMODEL + col] = l23;
        }
    }
}

// ---------------- V transpose: V[s*4+b][d] -> VT[(b*DM+d)][s] -----------------
__global__ void __launch_bounds__(256) transpose_v_kernel(
    const __nv_bfloat16* __restrict__ Vhi, const __nv_bfloat16* __restrict__ Vlo,
    __nv_bfloat16* __restrict__ VThi, __nv_bfloat16* __restrict__ VTlo)
{
    __shared__ __nv_bfloat16 sh[32][64 + 4];
    __shared__ __nv_bfloat16 sl[32][64 + 4];
    const int tid = threadIdx.x;
    const int s0 = blockIdx.x * 32;
    const int d0 = blockIdx.y * 64;
    const int b  = blockIdx.z;

#pragma unroll
    for (int p = 0; p < 2; p++) {
        int idx = tid + p * 256;
        int srow = idx >> 4;
        int dq = idx & 15;
        size_t ga = ((size_t)(s0 + srow) * BATCH + b) * DMODEL + d0 + dq * 4;
        uint2 vh = *(const uint2*)(Vhi + ga);
        uint2 vl = *(const uint2*)(Vlo + ga);
        *(uint2*)&sh[srow][dq * 4] = vh;
        *(uint2*)&sl[srow][dq * 4] = vl;
    }
    __syncthreads();
#pragma unroll
    for (int p = 0; p < 2; p++) {
        int idx = tid + p * 256;
        int drow = idx >> 3;
        int sq = idx & 7;
        __nv_bfloat16 oh[4], ol[4];
#pragma unroll
        for (int k = 0; k < 4; k++) {
            oh[k] = sh[sq * 4 + k][drow];
            ol[k] = sl[sq * 4 + k][drow];
        }
        size_t ga = ((size_t)(b * DMODEL + d0 + drow)) * SLEN + s0 + sq * 4;
        *(uint2*)(VThi + ga) = *(uint2*)oh;
        *(uint2*)(VTlo + ga) = *(uint2*)ol;
    }
}

// ---------------- Flash attention (split-S=2, no-max exp2 softmax) -----------
#define ATT_QHI 0
#define ATT_QLO 16384
#define ATT_ST0 32768
#define ATT_STSZ 32768
#define ATT_CTRL (ATT_ST0 + 2*ATT_STSZ)
#define ATT_SMEM (ATT_CTRL + 64)
#define NKT2 (SLEN/64/2)   // 16 key tiles per split half

__global__ void __launch_bounds__(256, 2) attn_mma_kernel(
    const __grid_constant__ CUtensorMap mQhi, const __grid_constant__ CUtensorMap mQlo,
    const __grid_constant__ CUtensorMap mKhi, const __grid_constant__ CUtensorMap mKlo,
    const __grid_constant__ CUtensorMap mVhi, const __grid_constant__ CUtensorMap mVlo,
    float* __restrict__ ACC, float* __restrict__ Lsum)
{
    extern __shared__ char smem[];
    const uint32_t sbase = smem_to_u32(smem);
    const uint32_t mbb = sbase + ATT_CTRL;
    const int tid = threadIdx.x;
    const int w = tid >> 5;
    const int lane = tid & 31;
    const int g = lane >> 2;
    const int t = lane & 3;
    const int q0 = blockIdx.x * 128;
    const int b = blockIdx.y >> 4;
    const int h = blockIdx.y & 15;
    const int z = blockIdx.z;
    const int key0 = z * (SLEN / 2);
    const int xqk = b * DMODEL + h * 64;

    if (tid == 0) {
        MBARRIER_INIT(mbb + 0, 1);
        MBARRIER_INIT(mbb + 8, 1);
        MBARRIER_INIT(mbb + 16, 8);
        MBARRIER_INIT(mbb + 24, 8);
    }
    FENCE_ASYNC_SHARED();
    __syncthreads();

    if (tid == 0) {
        MBARRIER_EXPECT_TX(mbb + 0, ATT_STSZ + 32768);
        tma_load_2d(sbase + ATT_QHI, &mQhi, xqk, q0, mbb + 0);
        tma_load_2d(sbase + ATT_QLO, &mQlo, xqk, q0, mbb + 0);
        tma_load_2d(sbase + ATT_ST0 + 0,     &mKhi, xqk, key0, mbb + 0);
        tma_load_2d(sbase + ATT_ST0 + 8192,  &mKlo, xqk, key0, mbb + 0);
        tma_load_2d(sbase + ATT_ST0 + 16384, &mVhi, key0, xqk, mbb + 0);
        tma_load_2d(sbase + ATT_ST0 + 24576, &mVlo, key0, xqk, mbb + 0);
        MBARRIER_EXPECT_TX(mbb + 8, ATT_STSZ);
        tma_load_2d(sbase + ATT_ST0 + ATT_STSZ + 0,     &mKhi, xqk, key0 + 64, mbb + 8);
        tma_load_2d(sbase + ATT_ST0 + ATT_STSZ + 8192,  &mKlo, xqk, key0 + 64, mbb + 8);
        tma_load_2d(sbase + ATT_ST0 + ATT_STSZ + 16384, &mVhi, key0 + 64, xqk, mbb + 8);
        tma_load_2d(sbase + ATT_ST0 + ATT_STSZ + 24576, &mVlo, key0 + 64, xqk, mbb + 8);
    }

    const uint32_t m16 = (lane & 7) * 16;
    const int rA = (lane & 7) + ((lane >> 3) & 1) * 8;
    const uint32_t hA = ((lane >> 4) & 1) * 16;
    const int rB = (lane & 7) + ((lane >> 4) & 1) * 8;
    const uint32_t hB = ((lane >> 3) & 1) * 16;
    const uint32_t qoff = (uint32_t)(w * 16 + rA) * 128;
    uint32_t kvoff[4];
#pragma unroll
    for (int jp = 0; jp < 4; jp++) kvoff[jp] = (uint32_t)(jp * 16 + rB) * 128;

    float l_i[2] = {0.f, 0.f};
    float acc[8][4];
#pragma unroll
    for (int j = 0; j < 8; j++)
#pragma unroll
        for (int q = 0; q < 4; q++) acc[j][q] = 0.f;

    for (int s = 0; s < NKT2; s++) {
        const int buf = s & 1;
        const int ph = (s >> 1) & 1;
        MBARRIER_WAIT_PARITY(mbb + buf * 8, ph);
        const uint32_t Kbu = sbase + ATT_ST0 + buf * ATT_STSZ;
        const uint32_t Vbu = Kbu + 16384;

        float sc[8][4];
#pragma unroll
        for (int j = 0; j < 8; j++)
#pragma unroll
            for (int q = 0; q < 4; q++) sc[j][q] = 0.f;

#pragma unroll
        for (int ks = 0; ks < 4; ks++) {
            const uint32_t cA = (ks * 32 + hA) ^ m16;
            const uint32_t cB = (ks * 32 + hB) ^ m16;
            uint32_t qh[4], ql[4];
            ldsm_x4(qh, sbase + ATT_QHI + qoff + cA);
            ldsm_x4(ql, sbase + ATT_QLO + qoff + cA);
#pragma unroll
            for (int jp = 0; jp < 4; jp++) {
                uint32_t kh[4], kl[4];
                ldsm_x4(kh, Kbu + kvoff[jp] + cB);
                ldsm_x4(kl, Kbu + 8192 + kvoff[jp] + cB);
                mma_bf16(sc[2*jp],   qh, &kh[0]);
                mma_bf16(sc[2*jp],   qh, &kl[0]);
                mma_bf16(sc[2*jp],   ql, &kh[0]);
                mma_bf16(sc[2*jp+1], qh, &kh[2]);
                mma_bf16(sc[2*jp+1], qh, &kl[2]);
                mma_bf16(sc[2*jp+1], ql, &kh[2]);
            }
        }

        float s0 = 0.f, s1 = 0.f;
#pragma unroll
        for (int j = 0; j < 8; j++) {
            sc[j][0] = ex2f(sc[j][0]);
            sc[j][1] = ex2f(sc[j][1]);
            sc[j][2] = ex2f(sc[j][2]);
            sc[j][3] = ex2f(sc[j][3]);
            s0 += sc[j][0] + sc[j][1];
            s1 += sc[j][2] + sc[j][3];
        }
        l_i[0] += s0;
        l_i[1] += s1;

#pragma unroll
        for (int ks = 0; ks < 4; ks++) {
            uint32_t pah[4], pal[4];
            split_pack2(sc[2*ks][0],   sc[2*ks][1],   pah[0], pal[0]);
            split_pack2(sc[2*ks][2],   sc[2*ks][3],   pah[1], pal[1]);
            split_pack2(sc[2*ks+1][0], sc[2*ks+1][1], pah[2], pal[2]);
            split_pack2(sc[2*ks+1][2], sc[2*ks+1][3], pah[3], pal[3]);
            const uint32_t cB = (ks * 32 + hB) ^ m16;
#pragma unroll
            for (int jp = 0; jp < 4; jp++) {
                uint32_t vh[4], vl[4];
                ldsm_x4(vh, Vbu + kvoff[jp] + cB);
                ldsm_x4(vl, Vbu + 8192 + kvoff[jp] + cB);
                mma_bf16(acc[2*jp],   pah, &vh[0]);
                mma_bf16(acc[2*jp],   pah, &vl[0]);
                mma_bf16(acc[2*jp],   pal, &vh[0]);
                mma_bf16(acc[2*jp+1], pah, &vh[2]);
                mma_bf16(acc[2*jp+1], pah, &vl[2]);
                mma_bf16(acc[2*jp+1], pal, &vh[2]);
            }
        }

        if (lane == 0) MBARRIER_ARRIVE(mbb + 16 + buf * 8);
        if (tid == 0 && s + 2 < NKT2) {
            MBARRIER_WAIT_PARITY(mbb + 16 + buf * 8, ph);
            uint32_t mb = mbb + buf * 8;
            uint32_t dst = sbase + ATT_ST0 + buf * ATT_STSZ;
            MBARRIER_EXPECT_TX(mb, ATT_STSZ);
            tma_load_2d(dst + 0,     &mKhi, xqk, key0 + (s + 2) * 64, mb);
            tma_load_2d(dst + 8192,  &mKlo, xqk, key0 + (s + 2) * 64, mb);
            tma_load_2d(dst + 16384, &mVhi, key0 + (s + 2) * 64, xqk, mb);
            tma_load_2d(dst + 24576, &mVlo, key0 + (s + 2) * 64, xqk, mb);
        }
    }

    float l0 = l_i[0], l1 = l_i[1];
    l0 += __shfl_xor_sync(0xffffffffu, l0, 1);
    l0 += __shfl_xor_sync(0xffffffffu, l0, 2);
    l1 += __shfl_xor_sync(0xffffffffu, l1, 1);
    l1 += __shfl_xor_sync(0xffffffffu, l1, 2);

    const int row0 = q0 + w * 16 + g;
    const int row1 = row0 + 8;
    const size_t tok0 = (size_t)row0 * BATCH + b;
    const size_t tok1 = (size_t)row1 * BATCH + b;
    float* accp = ACC + (size_t)z * NTOK * DMODEL;
    if (t == 0) {
        Lsum[(size_t)z * NTOK * NHEAD + tok0 * NHEAD + h] = l0;
        Lsum[(size_t)z * NTOK * NHEAD + tok1 * NHEAD + h] = l1;
    }
#pragma unroll
    for (int j = 0; j < 8; j++) {
        const int col = h * 64 + j * 8 + t * 2;
        *(float2*)&accp[tok0 * DMODEL + col] = make_float2(acc[j][0], acc[j][1]);
        *(float2*)&accp[tok1 * DMODEL + col] = make_float2(acc[j][2], acc[j][3]);
    }
}

// ---------------- attention combine: ctx = (acc0+acc1)/(l0+l1) -> hi/lo ------
__global__ void __launch_bounds__(256) attn_combine_kernel(
    const float* __restrict__ ACC, const float* __restrict__ Lsum,
    __nv_bfloat16* __restrict__ Ohi, __nv_bfloat16* __restrict__ Olo)
{
    const int i4 = blockIdx.x * 256 + threadIdx.x;   // over NTOK*DMODEL/4
    const int tok = i4 >> 8;           // DMODEL/4 = 256
    const int d = (i4 & 255) * 4;
    const int h = d >> 6;
    const float l = Lsum[(size_t)tok * NHEAD + h] +
                    Lsum[(size_t)NTOK * NHEAD + (size_t)tok * NHEAD + h];
    const float inv = 1.0f / l;
    float4 a0 = *(const float4*)&ACC[(size_t)tok * DMODEL + d];
    float4 a1 = *(const float4*)&ACC[(size_t)NTOK * DMODEL + (size_t)tok * DMODEL + d];
    float v0 = (a0.x + a1.x) * inv;
    float v1 = (a0.y + a1.y) * inv;
    float v2 = (a0.z + a1.z) * inv;
    float v3 = (a0.w + a1.w) * inv;
    uint2 uh, ul;
    split_pack2(v0, v1, uh.x, ul.x);
    split_pack2(v2, v3, uh.y, ul.y);
    *(uint2*)&Ohi[(size_t)tok * DMODEL + d] = uh;
    *(uint2*)&Olo[(size_t)tok * DMODEL + d] = ul;
}

// ---------------- fused residual add + LayerNorm (two-plane A) ---------------
template<int HILO>
__global__ void __launch_bounds__(256) add_ln_kernel(
    const float* __restrict__ A0, const float* __restrict__ A1,
    const float* __restrict__ R,
    const float* __restrict__ gam, const float* __restrict__ bet,
    float* __restrict__ out, __nv_bfloat16* __restrict__ Ohi,
    __nv_bfloat16* __restrict__ Olo)
{
    __shared__ float red_s[8];
    __shared__ float red_ss[8];
    __shared__ float s_mu, s_rstd;
    const int row = blockIdx.x;
    const int t = threadIdx.x;
    float4 v = ((const float4*)(A0 + (size_t)row * DMODEL))[t];
    float4 u = ((const float4*)(A1 + (size_t)row * DMODEL))[t];
    float4 w = ((const float4*)(R + (size_t)row * DMODEL))[t];
    v.x += u.x + w.x; v.y += u.y + w.y; v.z += u.z + w.z; v.w += u.w + w.w;
    float s = v.x + v.y + v.z + v.w;
    float ss = v.x * v.x + v.y * v.y + v.z * v.z + v.w * v.w;
#pragma unroll
    for (int off = 16; off >= 1; off >>= 1) {
        s  += __shfl_xor_sync(0xffffffffu, s, off);
        ss += __shfl_xor_sync(0xffffffffu, ss, off);
    }
    if ((t & 31) == 0) { red_s[t >> 5] = s; red_ss[t >> 5] = ss; }
    __syncthreads();
    if (t == 0) {
        float ts = 0.f, tss = 0.f;
#pragma unroll
        for (int i = 0; i < 8; i++) { ts += red_s[i]; tss += red_ss[i]; }
        float mu = ts * (1.0f / DMODEL);
        float var = tss * (1.0f / DMODEL) - mu * mu;
        s_mu = mu;
        s_rstd = rsqrtf(var + LN_EPS);
    }
    __syncthreads();
    float mu = s_mu, rs = s_rstd;
    float4 g = ((const float4*)gam)[t], bb = ((const float4*)bet)[t];
    float4 o;
    o.x = (v.x - mu) * rs * g.x + bb.x;
    o.y = (v.y - mu) * rs * g.y + bb.y;
    o.z = (v.z - mu) * rs * g.z + bb.z;
    o.w = (v.w - mu) * rs * g.w + bb.w;
    ((float4*)(out + (size_t)row * DMODEL))[t] = o;
    if (HILO) {
        uint2 uh, ul;
        split_pack2(o.x, o.y, uh.x, ul.x);
        split_pack2(o.z, o.w, uh.y, ul.y);
        ((uint2*)(Ohi + (size_t)row * DMODEL))[t] = uh;
        ((uint2*)(Olo + (size_t)row * DMODEL))[t] = ul;
    }
}

// ---------------- host: tensormap + launch ------------------------------------
typedef CUresult (*EncodeFn)(
    CUtensorMap*, CUtensorMapDataType, cuuint32_t, void*,
    const cuuint64_t*, const cuuint64_t*, const cuuint32_t*, const cuuint32_t*,
    CUtensorMapInterleave, CUtensorMapSwizzle, CUtensorMapL2promotion,
    CUtensorMapFloatOOBfill);

static void make_desc(EncodeFn enc, CUtensorMap* out, void* ptr,
                      uint64_t rows, uint64_t K, uint32_t box1)
{
    cuuint64_t dims[2]    = {K, rows};
    cuuint64_t strides[1] = {K * 2};
    cuuint32_t box[2]     = {64, box1};
    cuuint32_t estr[2]    = {1, 1};
    enc(out, CU_TENSOR_MAP_DATA_TYPE_BFLOAT16, 2, ptr, dims, strides, box, estr,
        CU_TENSOR_MAP_INTERLEAVE_NONE, CU_TENSOR_MAP_SWIZZLE_128B,
        CU_TENSOR_MAP_L2_PROMOTION_L2_128B, CU_TENSOR_MAP_FLOAT_OOB_FILL_NONE);
}

extern "C" void kernel_launch(void* const* d_in, const int* in_sizes, int n_in,
                              void* d_out, int out_size)
{
    const float* X    = (const float*)d_in[0];
    const float* WQw  = (const float*)d_in[1];
    const float* WQb  = (const float*)d_in[2];
    const float* WKw  = (const float*)d_in[3];
    const float* WKb  = (const float*)d_in[4];
    const float* WVw  = (const float*)d_in[5];
    const float* WVb  = (const float*)d_in[6];
    const float* WOw  = (const float*)d_in[7];
    const float* WOb  = (const float*)d_in[8];
    const float* ln1g = (const float*)d_in[9];
    const float* ln1b = (const float*)d_in[10];
    const float* W1   = (const float*)d_in[11];
    const float* b1   = (const float*)d_in[12];
    const float* W2   = (const float*)d_in[13];
    const float* b2   = (const float*)d_in[14];
    const float* ln2g = (const float*)d_in[15];
    const float* ln2b = (const float*)d_in[16];
    float* out = (float*)d_out;

    float *Y, *X1, *M, *ACC, *L;
    cudaGetSymbolAddress((void**)&Y,   g_Y);
    cudaGetSymbolAddress((void**)&X1,  g_X1);
    cudaGetSymbolAddress((void**)&M,   g_M);
    cudaGetSymbolAddress((void**)&ACC, g_ACC);
    cudaGetSymbolAddress((void**)&L,   g_L);

    __nv_bfloat16 *Xhi,*Xlo,*X1hi,*X1lo,*CTXhi,*CTXlo,*HIDhi,*HIDlo;
    __nv_bfloat16 *Qhi,*Qlo,*Khi,*Klo,*Vhi,*Vlo,*VThi,*VTlo;
    __nv_bfloat16 *WQKVhi,*WQKVlo,*WOhi,*WOlo,*W1hi,*W1lo,*W2hi,*W2lo;
    cudaGetSymbolAddress((void**)&Xhi,  g_Xhi);  cudaGetSymbolAddress((void**)&Xlo,  g_Xlo);
    cudaGetSymbolAddress((void**)&X1hi, g_X1hi); cudaGetSymbolAddress((void**)&X1lo, g_X1lo);
    cudaGetSymbolAddress((void**)&CTXhi,g_CTXhi);cudaGetSymbolAddress((void**)&CTXlo,g_CTXlo);
    cudaGetSymbolAddress((void**)&Qhi,  g_Qhi);  cudaGetSymbolAddress((void**)&Qlo,  g_Qlo);
    cudaGetSymbolAddress((void**)&Khi,  g_Khi);  cudaGetSymbolAddress((void**)&Klo,  g_Klo);
    cudaGetSymbolAddress((void**)&Vhi,  g_Vhi);  cudaGetSymbolAddress((void**)&Vlo,  g_Vlo);
    cudaGetSymbolAddress((void**)&VThi, g_VThi); cudaGetSymbolAddress((void**)&VTlo, g_VTlo);
    cudaGetSymbolAddress((void**)&HIDhi,g_HIDhi);cudaGetSymbolAddress((void**)&HIDlo,g_HIDlo);
    cudaGetSymbolAddress((void**)&WQKVhi, g_WQKVhi); cudaGetSymbolAddress((void**)&WQKVlo, g_WQKVlo);
    cudaGetSymbolAddress((void**)&WOhi, g_WOhi); cudaGetSymbolAddress((void**)&WOlo, g_WOlo);
    cudaGetSymbolAddress((void**)&W1hi, g_W1hi); cudaGetSymbolAddress((void**)&W1lo, g_W1lo);
    cudaGetSymbolAddress((void**)&W2hi, g_W2hi); cudaGetSymbolAddress((void**)&W2lo, g_W2lo);

    EncodeFn enc = nullptr;
    {
        void* fp = nullptr;
        cudaDriverEntryPointQueryResult qr;
        cudaGetDriverEntryPoint("cuTensorMapEncodeTiled", &fp, cudaEnableDefault, &qr);
        enc = (EncodeFn)fp;
    }

    CUtensorMap dXhi, dXlo, dWQKVhi, dWQKVlo, dCTXhi, dCTXlo, dWOhi, dWOlo;
    CUtensorMap dX1hi, dX1lo, dW1hi, dW1lo, dHIDhi, dHIDlo, dW2hi, dW2lo;
    make_desc(enc, &dXhi,  Xhi,  NTOK, DMODEL, 64);   make_desc(enc, &dXlo,  Xlo,  NTOK, DMODEL, 64);
    make_desc(enc, &dWQKVhi, WQKVhi, 3*DMODEL, DMODEL, 128);
    make_desc(enc, &dWQKVlo, WQKVlo, 3*DMODEL, DMODEL, 128);
    make_desc(enc, &dCTXhi,CTXhi,NTOK, DMODEL, 64);   make_desc(enc, &dCTXlo,CTXlo,NTOK, DMODEL, 64);
    make_desc(enc, &dWOhi, WOhi, DMODEL, DMODEL, 128);make_desc(enc, &dWOlo, WOlo, DMODEL, DMODEL, 128);
    make_desc(enc, &dX1hi, X1hi, NTOK, DMODEL, 64);   make_desc(enc, &dX1lo, X1lo, NTOK, DMODEL, 64);
    make_desc(enc, &dW1hi, W1hi, DFFN, DMODEL, 128);  make_desc(enc, &dW1lo, W1lo, DFFN, DMODEL, 128);
    make_desc(enc, &dHIDhi,HIDhi,NTOK, DFFN, 64);     make_desc(enc, &dHIDlo,HIDlo,NTOK, DFFN, 64);
    make_desc(enc, &dW2hi, W2hi, DMODEL, DFFN, 128);  make_desc(enc, &dW2lo, W2lo, DMODEL, DFFN, 128);

    CUtensorMap dQhi, dQlo, dKhi, dKlo, dVThi, dVTlo;
    make_desc(enc, &dQhi, Qhi, SLEN, BATCH*DMODEL, 128);
    make_desc(enc, &dQlo, Qlo, SLEN, BATCH*DMODEL, 128);
    make_desc(enc, &dKhi, Khi, SLEN, BATCH*DMODEL, 64);
    make_desc(enc, &dKlo, Klo, SLEN, BATCH*DMODEL, 64);
    make_desc(enc, &dVThi, VThi, BATCH*DMODEL, SLEN, 64);
    make_desc(enc, &dVTlo, VTlo, BATCH*DMODEL, SLEN, 64);

    cudaFuncSetAttribute(gemm_mma_kernel<1,0,0>, cudaFuncAttributeMaxDynamicSharedMemorySize, GEMM_SMEM);
    cudaFuncSetAttribute(gemm_mma_kernel<0,1,1>, cudaFuncAttributeMaxDynamicSharedMemorySize, GEMM_SMEM);
    cudaFuncSetAttribute(gemm_qkv_kernel, cudaFuncAttributeMaxDynamicSharedMemorySize, GEMM_SMEM);
    cudaFuncSetAttribute(attn_mma_kernel, cudaFuncAttributeMaxDynamicSharedMemorySize, ATT_SMEM);

    // ---- fused fp32 -> bf16 hi/lo split: 7 segments, one launch ----
    {
        CvtArgs a;
        const float* srcs[CVT_SEGS] = {X, WQw, WKw, WVw, WOw, W1, W2};
        __nv_bfloat16* his[CVT_SEGS] = {Xhi, WQKVhi, WQKVhi + DMODEL*DMODEL,
                                        WQKVhi + 2*DMODEL*DMODEL, WOhi, W1hi, W2hi};
        __nv_bfloat16* los[CVT_SEGS] = {Xlo, WQKVlo, WQKVlo + DMODEL*DMODEL,
                                        WQKVlo + 2*DMODEL*DMODEL, WOlo, W1lo, W2lo};
        int n4s[CVT_SEGS] = {NTOK*DMODEL/4, DMODEL*DMODEL/4, DMODEL*DMODEL/4,
                             DMODEL*DMODEL/4, DMODEL*DMODEL/4, DFFN*DMODEL/4, DMODEL*DFFN/4};
        int cum = 0;
        for (int i = 0; i < CVT_SEGS; i++) {
            a.src[i] = srcs[i]; a.hi[i] = his[i]; a.lo[i] = los[i]; a.n4[i] = n4s[i];
            cum += (n4s[i] + CVT_CHUNK - 1) / CVT_CHUNK;
            a.blk_end[i] = cum;
        }
        cvt_multi_kernel<<<cum, 256>>>(a);
    }

    dim3 gProjK2(DMODEL / 128, NTOK / 64, 2);  // split-K=2: 8 x 128 x 2
    dim3 gQKV(3 * DMODEL / 128, NTOK / 64);    // 24 x 128
    dim3 gFF1(DFFN / 128, NTOK / 64);          // 32 x 128

    // ---- fused QKV projection (Q pre-scaled by 0.125*log2e) ----
    gemm_qkv_kernel<<<gQKV, 256, GEMM_SMEM>>>(dXhi, dXlo, dWQKVhi, dWQKVlo,
        WQb, WKb, WVb, Qhi, Qlo, Khi, Klo, Vhi, Vlo);

    // ---- V transpose for PV operand ----
    transpose_v_kernel<<<dim3(SLEN/32, DMODEL/64, BATCH), 256>>>(Vhi, Vlo, VThi, VTlo);

    // ---- attention (split-S=2) + combine ----
    attn_mma_kernel<<<dim3(SLEN/128, BATCH*NHEAD, 2), 256, ATT_SMEM>>>(
        dQhi, dQlo, dKhi, dKlo, dVThi, dVTlo, ACC, L);
    attn_combine_kernel<<<NTOK*DMODEL/4/256, 256>>>(ACC, L, CTXhi, CTXlo);

    // ---- output projection (split-K=2) + residual LN1 ----
    gemm_mma_kernel<1,0,0><<<gProjK2, 256, GEMM_SMEM>>>(dCTXhi, dCTXlo, dWOhi, dWOlo, WOb, Y, nullptr, nullptr, DMODEL, DMODEL);
    add_ln_kernel<1><<<NTOK, 256>>>(Y, Y + (size_t)NTOK*DMODEL, X, ln1g, ln1b, X1, X1hi, X1lo);

    // ---- MLP: FF1 (no split), W2 (split-K=2) ----
    gemm_mma_kernel<0,1,1><<<gFF1, 256, GEMM_SMEM>>>(dX1hi, dX1lo, dW1hi, dW1lo, b1, nullptr, HIDhi, HIDlo, DFFN, DMODEL);
    gemm_mma_kernel<1,0,0><<<gProjK2, 256, GEMM_SMEM>>>(dHIDhi, dHIDlo, dW2hi, dW2lo, b2, M, nullptr, nullptr, DMODEL, DFFN);
    add_ln_kernel<0><<<NTOK, 256>>>(M, M + (size_t)NTOK*DMODEL, X1, ln2g, ln2b, out, nullptr, nullptr);
}

// round 11
// speedup vs baseline: 1.1121x; 1.1121x over previous
#include <cuda_runtime.h>
#include <cuda.h>
#include <cuda_bf16.h>
#include <cstdint>

#define SLEN 2048
#define BATCH 4
#define DMODEL 1024
#define NHEAD 16
#define DKH 64
#define DFFN 4096
#define NTOK (SLEN*BATCH)   // 8192
#define LN_EPS 1e-5f
#define QSCALE 0.18033688011112042f   // 0.125 * log2(e)

// ---------------- scratch (device globals) ----------------------------------
__device__ __align__(1024) float g_Y[NTOK*DMODEL];
__device__ __align__(1024) float g_X1[NTOK*DMODEL];
__device__ __align__(1024) float g_M[NTOK*DMODEL];

__device__ __align__(1024) __nv_bfloat16 g_Xhi[NTOK*DMODEL],  g_Xlo[NTOK*DMODEL];
__device__ __align__(1024) __nv_bfloat16 g_X1hi[NTOK*DMODEL], g_X1lo[NTOK*DMODEL];
__device__ __align__(1024) __nv_bfloat16 g_CTXhi[NTOK*DMODEL],g_CTXlo[NTOK*DMODEL];
__device__ __align__(1024) __nv_bfloat16 g_Qhi[NTOK*DMODEL],  g_Qlo[NTOK*DMODEL];
__device__ __align__(1024) __nv_bfloat16 g_Khi[NTOK*DMODEL],  g_Klo[NTOK*DMODEL];
__device__ __align__(1024) __nv_bfloat16 g_Vhi[NTOK*DMODEL],  g_Vlo[NTOK*DMODEL];
__device__ __align__(1024) __nv_bfloat16 g_VThi[NTOK*DMODEL], g_VTlo[NTOK*DMODEL];
__device__ __align__(1024) __nv_bfloat16 g_HIDhi[NTOK*DFFN],  g_HIDlo[NTOK*DFFN];
__device__ __align__(1024) __nv_bfloat16 g_WQKVhi[3*DMODEL*DMODEL], g_WQKVlo[3*DMODEL*DMODEL];
__device__ __align__(1024) __nv_bfloat16 g_WOhi[DMODEL*DMODEL], g_WOlo[DMODEL*DMODEL];
__device__ __align__(1024) __nv_bfloat16 g_W1hi[DFFN*DMODEL],   g_W1lo[DFFN*DMODEL];
__device__ __align__(1024) __nv_bfloat16 g_W2hi[DMODEL*DFFN],   g_W2lo[DMODEL*DFFN];

// ---------------- PTX helpers (base-ISA only) --------------------------------
__device__ __forceinline__ uint32_t smem_to_u32(const void* p) {
    uint32_t a;
    asm("{ .reg .u64 t; cvta.to.shared.u64 t, %1; cvt.u32.u64 %0, t; }" : "=r"(a) : "l"(p));
    return a;
}
#define MBARRIER_INIT(mbar, cnt) \
    asm volatile("mbarrier.init.shared.b64 [%0], %1;" :: "r"((uint32_t)(mbar)), "r"((uint32_t)(cnt)) : "memory")
#define MBARRIER_EXPECT_TX(mbar, bytes) \
    asm volatile("mbarrier.arrive.expect_tx.shared.b64 _, [%0], %1;" :: "r"((uint32_t)(mbar)), "r"((uint32_t)(bytes)) : "memory")
#define MBARRIER_ARRIVE(mbar) \
    asm volatile("mbarrier.arrive.shared.b64 _, [%0];" :: "r"((uint32_t)(mbar)) : "memory")
#define FENCE_ASYNC_SHARED() asm volatile("fence.proxy.async.shared::cta;" ::: "memory")

#define MBARRIER_WAIT_PARITY(mbar_smem_addr, phase_parity) do { \
    uint32_t _mbar = (uint32_t)(mbar_smem_addr); \
    uint32_t _parity = (uint32_t)(phase_parity); \
    uint32_t _done; \
    asm volatile("{ .reg .pred p; mbarrier.try_wait.parity.acquire.cta.shared::cta.b64 p, [%1], %2; selp.b32 %0, 1, 0, p; }" \
        : "=r"(_done) : "r"(_mbar), "r"(_parity) : "memory"); \
    if (!_done) { \
        asm volatile("{ .reg .pred P1; WAIT_LOOP_%=: mbarrier.try_wait.parity.acquire.cta.shared::cta.b64 P1, [%0], %1, 0x989680; @P1 bra.uni WAIT_DONE_%=; bra.uni WAIT_LOOP_%=; WAIT_DONE_%=: }" \
            :: "r"(_mbar), "r"(_parity) : "memory"); \
    } \
} while(0)

__device__ __forceinline__ void tma_load_2d(uint32_t dst_smem, const CUtensorMap* m,
                                            int x, int y, uint32_t mbar) {
    asm volatile(
        "cp.async.bulk.tensor.2d.shared::cta.global.tile.mbarrier::complete_tx::bytes "
        "[%0], [%1, {%2, %3}], [%4];"
        :: "r"(dst_smem), "l"(m), "r"(x), "r"(y), "r"(mbar) : "memory");
}

__device__ __forceinline__ void mma_bf16(float* d, const uint32_t* a, const uint32_t* b) {
    asm volatile(
        "mma.sync.aligned.m16n8k16.row.col.f32.bf16.bf16.f32 "
        "{%0,%1,%2,%3},{%4,%5,%6,%7},{%8,%9},{%0,%1,%2,%3};"
        : "+f"(d[0]), "+f"(d[1]), "+f"(d[2]), "+f"(d[3])
        : "r"(a[0]), "r"(a[1]), "r"(a[2]), "r"(a[3]), "r"(b[0]), "r"(b[1]));
}

__device__ __forceinline__ void ldsm_x4(uint32_t* r, uint32_t addr) {
    asm volatile("ldmatrix.sync.aligned.m8n8.x4.shared.b16 {%0,%1,%2,%3}, [%4];"
        : "=r"(r[0]), "=r"(r[1]), "=r"(r[2]), "=r"(r[3]) : "r"(addr));
}

__device__ __forceinline__ float ex2f(float x) {
    float y; asm("ex2.approx.f32 %0, %1;" : "=f"(y) : "f"(x)); return y;
}

// fast hi/lo split: hi = truncated-bf16 pair via PRMT, lo = packed via cvt.bf16x2
__device__ __forceinline__ void split_pack2(float a, float b, uint32_t& hi, uint32_t& lo) {
    uint32_t ua = __float_as_uint(a), ub = __float_as_uint(b);
    uint32_t h;
    asm("prmt.b32 %0, %1, %2, 0x7632;" : "=r"(h) : "r"(ua), "r"(ub));
    float la = a - __uint_as_float(ua & 0xffff0000u);
    float lb = b - __uint_as_float(ub & 0xffff0000u);
    uint32_t l;
    asm("cvt.rn.bf16x2.f32 %0, %1, %2;" : "=r"(l) : "f"(lb), "f"(la));
    hi = h; lo = l;
}
// round-to-nearest bf16x2 pack (unbiased single-term representation)
__device__ __forceinline__ uint32_t rn_pack2(float a, float b) {
    uint32_t r;
    asm("cvt.rn.bf16x2.f32 %0, %1, %2;" : "=r"(r) : "f"(b), "f"(a));
    return r;
}

// ---------------- fused fp32 -> bf16 hi/lo split (multi-segment) -------------
#define CVT_SEGS 7
#define CVT_CHUNK 512
struct CvtArgs {
    const float* src[CVT_SEGS];
    __nv_bfloat16* hi[CVT_SEGS];
    __nv_bfloat16* lo[CVT_SEGS];
    int blk_end[CVT_SEGS];
    int n4[CVT_SEGS];
};

__global__ void __launch_bounds__(256) cvt_multi_kernel(const __grid_constant__ CvtArgs a)
{
    int seg = 0;
#pragma unroll
    for (int k = 0; k < CVT_SEGS - 1; k++)
        if (blockIdx.x >= (unsigned)a.blk_end[k]) seg = k + 1;
    const int local = blockIdx.x - (seg ? a.blk_end[seg - 1] : 0);
    const float* src = a.src[seg];
    __nv_bfloat16* hi = a.hi[seg];
    __nv_bfloat16* lo = a.lo[seg];
    const int n4 = a.n4[seg];
#pragma unroll
    for (int p = 0; p < 2; p++) {
        int i = local * CVT_CHUNK + p * 256 + threadIdx.x;
        if (i < n4) {
            float4 v = ((const float4*)src)[i];
            uint2 uh, ul;
            split_pack2(v.x, v.y, uh.x, ul.x);
            split_pack2(v.z, v.w, uh.y, ul.y);
            ((uint2*)hi)[i] = uh;
            ((uint2*)lo)[i] = ul;
        }
    }
}

// ---------------- split-bf16 GEMM mainloop: 64x128 tile, occ 2 ---------------
#define ST_AHI 0
#define ST_ALO 8192
#define ST_BHI 16384
#define ST_BLO 32768
#define ST_BYTES 49152
#define NPIPE 2
#define GEMM_SMEM (NPIPE*ST_BYTES + 64)

__device__ __forceinline__ void gemm_mainloop(
    const CUtensorMap* mAhi, const CUtensorMap* mAlo,
    const CUtensorMap* mBhi, const CUtensorMap* mBlo,
    int bm, int bn, int nst, char* smem, float acc[][4][4])
{
    const uint32_t sbase = smem_to_u32(smem);
    const uint32_t mbb = sbase + NPIPE * ST_BYTES;
    const int tid = threadIdx.x;
    const int wid = tid >> 5;
    const int lane = tid & 31;
    const int wm = wid & 1;
    const int wn = wid >> 1;

    if (tid == 0) {
#pragma unroll
        for (int i = 0; i < NPIPE; i++) {
            MBARRIER_INIT(mbb + i * 8, 1);        // full
            MBARRIER_INIT(mbb + 16 + i * 8, 8);   // empty (8 warps)
        }
    }
    FENCE_ASYNC_SHARED();
    __syncthreads();

    if (tid == 0) {
#pragma unroll
        for (int s = 0; s < NPIPE; s++) {
            uint32_t mb = mbb + s * 8;
            uint32_t dst = sbase + s * ST_BYTES;
            MBARRIER_EXPECT_TX(mb, ST_BYTES);
            tma_load_2d(dst + ST_AHI, mAhi, s * 64, bm, mb);
            tma_load_2d(dst + ST_ALO, mAlo, s * 64, bm, mb);
            tma_load_2d(dst + ST_BHI, mBhi, s * 64, bn, mb);
            tma_load_2d(dst + ST_BLO, mBlo, s * 64, bn, mb);
        }
    }

    const uint32_t m16 = (lane & 7) * 16;
    const int rA = (lane & 7) + ((lane >> 3) & 1) * 8;
    const uint32_t hA = ((lane >> 4) & 1) * 16;
    const int rB = (lane & 7) + ((lane >> 4) & 1) * 8;
    const uint32_t hB = ((lane >> 3) & 1) * 16;
    uint32_t aoff[2], boff[2];
#pragma unroll
    for (int t = 0; t < 2; t++) aoff[t] = (uint32_t)(wm * 32 + t * 16 + rA) * 128;
#pragma unroll
    for (int jp = 0; jp < 2; jp++) boff[jp] = (uint32_t)(wn * 32 + jp * 16 + rB) * 128;

    int buf = 0, ph = 0;
    for (int s = 0; s < nst; s++) {
        MBARRIER_WAIT_PARITY(mbb + buf * 8, ph);
        const uint32_t sb = sbase + buf * ST_BYTES;

#pragma unroll
        for (int ks = 0; ks < 4; ks++) {
            const uint32_t cA = (ks * 32 + hA) ^ m16;
            const uint32_t cB = (ks * 32 + hB) ^ m16;
            uint32_t ah[2][4], al[2][4];
#pragma unroll
            for (int t = 0; t < 2; t++) {
                ldsm_x4(ah[t], sb + ST_AHI + aoff[t] + cA);
                ldsm_x4(al[t], sb + ST_ALO + aoff[t] + cA);
            }
            uint32_t bh[2][4], bl[2][4];
#pragma unroll
            for (int jp = 0; jp < 2; jp++) {
                ldsm_x4(bh[jp], sb + ST_BHI + boff[jp] + cB);
                ldsm_x4(bl[jp], sb + ST_BLO + boff[jp] + cB);
            }
#pragma unroll
            for (int t = 0; t < 2; t++)
#pragma unroll
                for (int jp = 0; jp < 2; jp++) {
                    mma_bf16(acc[t][2*jp],   ah[t], &bh[jp][0]);
                    mma_bf16(acc[t][2*jp],   ah[t], &bl[jp][0]);
                    mma_bf16(acc[t][2*jp],   al[t], &bh[jp][0]);
                    mma_bf16(acc[t][2*jp+1], ah[t], &bh[jp][2]);
                    mma_bf16(acc[t][2*jp+1], ah[t], &bl[jp][2]);
                    mma_bf16(acc[t][2*jp+1], al[t], &bh[jp][2]);
                }
        }

        if (lane == 0) MBARRIER_ARRIVE(mbb + 16 + buf * 8);
        if (tid == 0 && s + NPIPE < nst) {
            MBARRIER_WAIT_PARITY(mbb + 16 + buf * 8, ph);
            uint32_t mb = mbb + buf * 8;
            uint32_t dst = sbase + buf * ST_BYTES;
            MBARRIER_EXPECT_TX(mb, ST_BYTES);
            tma_load_2d(dst + ST_AHI, mAhi, (s + NPIPE) * 64, bm, mb);
            tma_load_2d(dst + ST_ALO, mAlo, (s + NPIPE) * 64, bm, mb);
            tma_load_2d(dst + ST_BHI, mBhi, (s + NPIPE) * 64, bn, mb);
            tma_load_2d(dst + ST_BLO, mBlo, (s + NPIPE) * 64, bn, mb);
        }
        if (++buf == NPIPE) { buf = 0; ph ^= 1; }
    }
}

// ---------------- generic GEMM kernel (64x128 out per CTA) -------------------
template<int WRITE_F32, int WRITE_HILO, int RELU>
__global__ void __launch_bounds__(256, 2) gemm_mma_kernel(
    const __grid_constant__ CUtensorMap mAhi,
    const __grid_constant__ CUtensorMap mAlo,
    const __grid_constant__ CUtensorMap mBhi,
    const __grid_constant__ CUtensorMap mBlo,
    const float* __restrict__ bias,
    float* __restrict__ C, __nv_bfloat16* __restrict__ Chi, __nv_bfloat16* __restrict__ Clo,
    int N, int K)
{
    extern __shared__ char smem[];
    const int bm = blockIdx.y * 64;
    const int bn = blockIdx.x * 128;
    float acc[2][4][4];
#pragma unroll
    for (int t = 0; t < 2; t++)
#pragma unroll
        for (int j = 0; j < 4; j++)
#pragma unroll
            for (int q = 0; q < 4; q++) acc[t][j][q] = 0.f;

    gemm_mainloop(&mAhi, &mAlo, &mBhi, &mBlo, bm, bn, K >> 6, smem, acc);

    const int lane = threadIdx.x & 31;
    const int wid = threadIdx.x >> 5;
    const int g = lane >> 2, tq = lane & 3;
    const int wm = wid & 1, wn = wid >> 1;
#pragma unroll
    for (int t = 0; t < 2; t++) {
        int row = bm + wm * 32 + t * 16 + g;
#pragma unroll
        for (int j = 0; j < 4; j++) {
            int col = bn + wn * 32 + j * 8 + tq * 2;
            float2 bj = *(const float2*)&bias[col];
            float v0 = acc[t][j][0] + bj.x;
            float v1 = acc[t][j][1] + bj.y;
            float v2 = acc[t][j][2] + bj.x;
            float v3 = acc[t][j][3] + bj.y;
            if (RELU) {
                v0 = fmaxf(v0, 0.f); v1 = fmaxf(v1, 0.f);
                v2 = fmaxf(v2, 0.f); v3 = fmaxf(v3, 0.f);
            }
            if (WRITE_F32) {
                *(float2*)&C[(size_t)row * N + col]       = make_float2(v0, v1);
                *(float2*)&C[(size_t)(row + 8) * N + col] = make_float2(v2, v3);
            }
            if (WRITE_HILO) {
                uint32_t h01, l01, h23, l23;
                split_pack2(v0, v1, h01, l01);
                split_pack2(v2, v3, h23, l23);
                *(uint32_t*)&Chi[(size_t)row * N + col]       = h01;
                *(uint32_t*)&Chi[(size_t)(row + 8) * N + col] = h23;
                *(uint32_t*)&Clo[(size_t)row * N + col]       = l01;
                *(uint32_t*)&Clo[(size_t)(row + 8) * N + col] = l23;
            }
        }
    }
}

// ---------------- fused QKV GEMM (N=3072 packed; scatter epilogue) -----------
// Q part: hi written with round-to-nearest (unbiased single-term operand);
// K/V parts: trunc hi + lo pair (consumed with full 2-term correction).
__global__ void __launch_bounds__(256, 2) gemm_qkv_kernel(
    const __grid_constant__ CUtensorMap mAhi,
    const __grid_constant__ CUtensorMap mAlo,
    const __grid_constant__ CUtensorMap mBhi,
    const __grid_constant__ CUtensorMap mBlo,
    const float* __restrict__ bQ, const float* __restrict__ bK, const float* __restrict__ bV,
    __nv_bfloat16* __restrict__ Qhi, __nv_bfloat16* __restrict__ Qlo,
    __nv_bfloat16* __restrict__ Khi, __nv_bfloat16* __restrict__ Klo,
    __nv_bfloat16* __restrict__ Vhi, __nv_bfloat16* __restrict__ Vlo)
{
    extern __shared__ char smem[];
    const int bm = blockIdx.y * 64;
    const int bn = blockIdx.x * 128;
    float acc[2][4][4];
#pragma unroll
    for (int t = 0; t < 2; t++)
#pragma unroll
        for (int j = 0; j < 4; j++)
#pragma unroll
            for (int q = 0; q < 4; q++) acc[t][j][q] = 0.f;

    gemm_mainloop(&mAhi, &mAlo, &mBhi, &mBlo, bm, bn, DMODEL >> 6, smem, acc);

    const int part = blockIdx.x >> 3;          // 0=Q 1=K 2=V
    const int nb = (blockIdx.x & 7) * 128;
    const float* bias = (part == 0) ? bQ : (part == 1) ? bK : bV;
    __nv_bfloat16* Ohi = (part == 0) ? Qhi : (part == 1) ? Khi : Vhi;
    __nv_bfloat16* Olo = (part == 0) ? Qlo : (part == 1) ? Klo : Vlo;
    const float scl = (part == 0) ? QSCALE : 1.0f;

    const int lane = threadIdx.x & 31;
    const int wid = threadIdx.x >> 5;
    const int g = lane >> 2, tq = lane & 3;
    const int wm = wid & 1, wn = wid >> 1;
#pragma unroll
    for (int t = 0; t < 2; t++) {
        int row = bm + wm * 32 + t * 16 + g;
#pragma unroll
        for (int j = 0; j < 4; j++) {
            int col = nb + wn * 32 + j * 8 + tq * 2;
            float2 bj = *(const float2*)&bias[col];
            float v0 = (acc[t][j][0] + bj.x) * scl;
            float v1 = (acc[t][j][1] + bj.y) * scl;
            float v2 = (acc[t][j][2] + bj.x) * scl;
            float v3 = (acc[t][j][3] + bj.y) * scl;
            uint32_t h01, l01, h23, l23;
            split_pack2(v0, v1, h01, l01);
            split_pack2(v2, v3, h23, l23);
            if (part == 0) {              // Q: unbiased RN hi (lo unused)
                h01 = rn_pack2(v0, v1);
                h23 = rn_pack2(v2, v3);
            }
            *(uint32_t*)&Ohi[(size_t)row * DMODEL + col]       = h01;
            *(uint32_t*)&Ohi[(size_t)(row + 8) * DMODEL + col] = h23;
            *(uint32_t*)&Olo[(size_t)row * DMODEL + col]       = l01;
            *(uint32_t*)&Olo[(size_t)(row + 8) * DMODEL + col] = l23;
        }
    }
}

// ---------------- V transpose: V[s*4+b][d] -> VT[(b*DM+d)][s] -----------------
__global__ void __launch_bounds__(256) transpose_v_kernel(
    const __nv_bfloat16* __restrict__ Vhi, const __nv_bfloat16* __restrict__ Vlo,
    __nv_bfloat16* __restrict__ VThi, __nv_bfloat16* __restrict__ VTlo)
{
    __shared__ __nv_bfloat16 sh[32][64 + 4];
    __shared__ __nv_bfloat16 sl[32][64 + 4];
    const int tid = threadIdx.x;
    const int s0 = blockIdx.x * 32;
    const int d0 = blockIdx.y * 64;
    const int b  = blockIdx.z;

#pragma unroll
    for (int p = 0; p < 2; p++) {
        int idx = tid + p * 256;
        int srow = idx >> 4;
        int dq = idx & 15;
        size_t ga = ((size_t)(s0 + srow) * BATCH + b) * DMODEL + d0 + dq * 4;
        uint2 vh = *(const uint2*)(Vhi + ga);
        uint2 vl = *(const uint2*)(Vlo + ga);
        *(uint2*)&sh[srow][dq * 4] = vh;
        *(uint2*)&sl[srow][dq * 4] = vl;
    }
    __syncthreads();
#pragma unroll
    for (int p = 0; p < 2; p++) {
        int idx = tid + p * 256;
        int drow = idx >> 3;
        int sq = idx & 7;
        __nv_bfloat16 oh[4], ol[4];
#pragma unroll
        for (int k = 0; k < 4; k++) {
            oh[k] = sh[sq * 4 + k][drow];
            ol[k] = sl[sq * 4 + k][drow];
        }
        size_t ga = ((size_t)(b * DMODEL + d0 + drow)) * SLEN + s0 + sq * 4;
        *(uint2*)(VThi + ga) = *(uint2*)oh;
        *(uint2*)(VTlo + ga) = *(uint2*)ol;
    }
}

// ---------------- Flash attention (2-term QK/PV, no-max exp2 softmax) --------
// smem: Qhi 16K | stage{Khi 8K, Klo 8K, Vhi 8K, Vlo 8K} x2 | ctrl
#define ATT_QHI 0
#define ATT_ST0 16384
#define ATT_STSZ 32768
#define ATT_CTRL (ATT_ST0 + 2*ATT_STSZ)
#define ATT_SMEM (ATT_CTRL + 64)
#define NKT (SLEN/64)

__global__ void __launch_bounds__(256, 2) attn_mma_kernel(
    const __grid_constant__ CUtensorMap mQhi,
    const __grid_constant__ CUtensorMap mKhi, const __grid_constant__ CUtensorMap mKlo,
    const __grid_constant__ CUtensorMap mVhi, const __grid_constant__ CUtensorMap mVlo,
    __nv_bfloat16* __restrict__ Ohi, __nv_bfloat16* __restrict__ Olo)
{
    extern __shared__ char smem[];
    const uint32_t sbase = smem_to_u32(smem);
    const uint32_t mbb = sbase + ATT_CTRL;   // full0,full1 @ +0,+8; empty0,empty1 @ +16,+24
    const int tid = threadIdx.x;
    const int w = tid >> 5;
    const int lane = tid & 31;
    const int g = lane >> 2;
    const int t = lane & 3;
    const int q0 = blockIdx.x * 128;
    const int b = blockIdx.y >> 4;
    const int h = blockIdx.y & 15;
    const int xqk = b * DMODEL + h * 64;

    if (tid == 0) {
        MBARRIER_INIT(mbb + 0, 1);
        MBARRIER_INIT(mbb + 8, 1);
        MBARRIER_INIT(mbb + 16, 8);
        MBARRIER_INIT(mbb + 24, 8);
    }
    FENCE_ASYNC_SHARED();
    __syncthreads();

    if (tid == 0) {
        MBARRIER_EXPECT_TX(mbb + 0, ATT_STSZ + 16384);
        tma_load_2d(sbase + ATT_QHI, &mQhi, xqk, q0, mbb + 0);
        tma_load_2d(sbase + ATT_ST0 + 0,     &mKhi, xqk, 0, mbb + 0);
        tma_load_2d(sbase + ATT_ST0 + 8192,  &mKlo, xqk, 0, mbb + 0);
        tma_load_2d(sbase + ATT_ST0 + 16384, &mVhi, 0, xqk, mbb + 0);
        tma_load_2d(sbase + ATT_ST0 + 24576, &mVlo, 0, xqk, mbb + 0);
        MBARRIER_EXPECT_TX(mbb + 8, ATT_STSZ);
        tma_load_2d(sbase + ATT_ST0 + ATT_STSZ + 0,     &mKhi, xqk, 64, mbb + 8);
        tma_load_2d(sbase + ATT_ST0 + ATT_STSZ + 8192,  &mKlo, xqk, 64, mbb + 8);
        tma_load_2d(sbase + ATT_ST0 + ATT_STSZ + 16384, &mVhi, 64, xqk, mbb + 8);
        tma_load_2d(sbase + ATT_ST0 + ATT_STSZ + 24576, &mVlo, 64, xqk, mbb + 8);
    }

    const uint32_t m16 = (lane & 7) * 16;
    const int rA = (lane & 7) + ((lane >> 3) & 1) * 8;
    const uint32_t hA = ((lane >> 4) & 1) * 16;
    const int rB = (lane & 7) + ((lane >> 4) & 1) * 8;
    const uint32_t hB = ((lane >> 3) & 1) * 16;
    const uint32_t qoff = (uint32_t)(w * 16 + rA) * 128;
    uint32_t kvoff[4];
#pragma unroll
    for (int jp = 0; jp < 4; jp++) kvoff[jp] = (uint32_t)(jp * 16 + rB) * 128;

    float l_i[2] = {0.f, 0.f};
    float acc[8][4];
#pragma unroll
    for (int j = 0; j < 8; j++)
#pragma unroll
        for (int q = 0; q < 4; q++) acc[j][q] = 0.f;

    for (int s = 0; s < NKT; s++) {
        const int buf = s & 1;
        const int ph = (s >> 1) & 1;
        MBARRIER_WAIT_PARITY(mbb + buf * 8, ph);
        const uint32_t Kbu = sbase + ATT_ST0 + buf * ATT_STSZ;
        const uint32_t Vbu = Kbu + 16384;

        // ---- scores = Qhi (K_hi + K_lo)  (Q truncated-RN; K full) ----
        float sc[8][4];
#pragma unroll
        for (int j = 0; j < 8; j++)
#pragma unroll
            for (int q = 0; q < 4; q++) sc[j][q] = 0.f;

#pragma unroll
        for (int ks = 0; ks < 4; ks++) {
            const uint32_t cA = (ks * 32 + hA) ^ m16;
            const uint32_t cB = (ks * 32 + hB) ^ m16;
            uint32_t qh[4];
            ldsm_x4(qh, sbase + ATT_QHI + qoff + cA);
#pragma unroll
            for (int jp = 0; jp < 4; jp++) {
                uint32_t kh[4], kl[4];
                ldsm_x4(kh, Kbu + kvoff[jp] + cB);
                ldsm_x4(kl, Kbu + 8192 + kvoff[jp] + cB);
                mma_bf16(sc[2*jp],   qh, &kh[0]);
                mma_bf16(sc[2*jp],   qh, &kl[0]);
                mma_bf16(sc[2*jp+1], qh, &kh[2]);
                mma_bf16(sc[2*jp+1], qh, &kl[2]);
            }
        }

        // p = exp2(score); l accumulated from fp32 p
        float s0 = 0.f, s1 = 0.f;
#pragma unroll
        for (int j = 0; j < 8; j++) {
            sc[j][0] = ex2f(sc[j][0]);
            sc[j][1] = ex2f(sc[j][1]);
            sc[j][2] = ex2f(sc[j][2]);
            sc[j][3] = ex2f(sc[j][3]);
            s0 += sc[j][0] + sc[j][1];
            s1 += sc[j][2] + sc[j][3];
        }
        l_i[0] += s0;
        l_i[1] += s1;

        // ---- ctx += P_rn (V_hi + V_lo)  (P round-to-nearest; V full) ----
#pragma unroll
        for (int ks = 0; ks < 4; ks++) {
            uint32_t pah[4];
            pah[0] = rn_pack2(sc[2*ks][0],   sc[2*ks][1]);
            pah[1] = rn_pack2(sc[2*ks][2],   sc[2*ks][3]);
            pah[2] = rn_pack2(sc[2*ks+1][0], sc[2*ks+1][1]);
            pah[3] = rn_pack2(sc[2*ks+1][2], sc[2*ks+1][3]);
            const uint32_t cB = (ks * 32 + hB) ^ m16;
#pragma unroll
            for (int jp = 0; jp < 4; jp++) {
                uint32_t vh[4], vl[4];
                ldsm_x4(vh, Vbu + kvoff[jp] + cB);
                ldsm_x4(vl, Vbu + 8192 + kvoff[jp] + cB);
                mma_bf16(acc[2*jp],   pah, &vh[0]);
                mma_bf16(acc[2*jp],   pah, &vl[0]);
                mma_bf16(acc[2*jp+1], pah, &vh[2]);
                mma_bf16(acc[2*jp+1], pah, &vl[2]);
            }
        }

        if (lane == 0) MBARRIER_ARRIVE(mbb + 16 + buf * 8);
        if (tid == 0 && s + 2 < NKT) {
            MBARRIER_WAIT_PARITY(mbb + 16 + buf * 8, ph);
            uint32_t mb = mbb + buf * 8;
            uint32_t dst = sbase + ATT_ST0 + buf * ATT_STSZ;
            MBARRIER_EXPECT_TX(mb, ATT_STSZ);
            tma_load_2d(dst + 0,     &mKhi, xqk, (s + 2) * 64, mb);
            tma_load_2d(dst + 8192,  &mKlo, xqk, (s + 2) * 64, mb);
            tma_load_2d(dst + 16384, &mVhi, (s + 2) * 64, xqk, mb);
            tma_load_2d(dst + 24576, &mVlo, (s + 2) * 64, xqk, mb);
        }
    }

    float l0 = l_i[0], l1 = l_i[1];
    l0 += __shfl_xor_sync(0xffffffffu, l0, 1);
    l0 += __shfl_xor_sync(0xffffffffu, l0, 2);
    l1 += __shfl_xor_sync(0xffffffffu, l1, 1);
    l1 += __shfl_xor_sync(0xffffffffu, l1, 2);

    const float inv0 = 1.0f / l0;
    const float inv1 = 1.0f / l1;
    const int row0 = q0 + w * 16 + g;
    const int row1 = row0 + 8;
    const size_t tok0 = (size_t)row0 * BATCH + b;
    const size_t tok1 = (size_t)row1 * BATCH + b;
#pragma unroll
    for (int j = 0; j < 8; j++) {
        const int col = h * 64 + j * 8 + t * 2;
        uint32_t h01, l01, h23, l23;
        split_pack2(acc[j][0] * inv0, acc[j][1] * inv0, h01, l01);
        split_pack2(acc[j][2] * inv1, acc[j][3] * inv1, h23, l23);
        *(uint32_t*)&Ohi[tok0 * DMODEL + col] = h01;
        *(uint32_t*)&Olo[tok0 * DMODEL + col] = l01;
        *(uint32_t*)&Ohi[tok1 * DMODEL + col] = h23;
        *(uint32_t*)&Olo[tok1 * DMODEL + col] = l23;
    }
}

// ---------------- fused residual add + LayerNorm -----------------------------
template<int HILO>
__global__ void __launch_bounds__(256) add_ln_kernel(
    const float* __restrict__ A, const float* __restrict__ R,
    const float* __restrict__ gam, const float* __restrict__ bet,
    float* __restrict__ out, __nv_bfloat16* __restrict__ Ohi,
    __nv_bfloat16* __restrict__ Olo)
{
    __shared__ float red_s[8];
    __shared__ float red_ss[8];
    __shared__ float s_mu, s_rstd;
    const int row = blockIdx.x;
    const int t = threadIdx.x;
    float4 v = ((const float4*)(A + (size_t)row * DMODEL))[t];
    float4 w = ((const float4*)(R + (size_t)row * DMODEL))[t];
    v.x += w.x; v.y += w.y; v.z += w.z; v.w += w.w;
    float s = v.x + v.y + v.z + v.w;
    float ss = v.x * v.x + v.y * v.y + v.z * v.z + v.w * v.w;
#pragma unroll
    for (int off = 16; off >= 1; off >>= 1) {
        s  += __shfl_xor_sync(0xffffffffu, s, off);
        ss += __shfl_xor_sync(0xffffffffu, ss, off);
    }
    if ((t & 31) == 0) { red_s[t >> 5] = s; red_ss[t >> 5] = ss; }
    __syncthreads();
    if (t == 0) {
        float ts = 0.f, tss = 0.f;
#pragma unroll
        for (int i = 0; i < 8; i++) { ts += red_s[i]; tss += red_ss[i]; }
        float mu = ts * (1.0f / DMODEL);
        float var = tss * (1.0f / DMODEL) - mu * mu;
        s_mu = mu;
        s_rstd = rsqrtf(var + LN_EPS);
    }
    __syncthreads();
    float mu = s_mu, rs = s_rstd;
    float4 g = ((const float4*)gam)[t], bb = ((const float4*)bet)[t];
    float4 o;
    o.x = (v.x - mu) * rs * g.x + bb.x;
    o.y = (v.y - mu) * rs * g.y + bb.y;
    o.z = (v.z - mu) * rs * g.z + bb.z;
    o.w = (v.w - mu) * rs * g.w + bb.w;
    ((float4*)(out + (size_t)row * DMODEL))[t] = o;
    if (HILO) {
        uint2 uh, ul;
        split_pack2(o.x, o.y, uh.x, ul.x);
        split_pack2(o.z, o.w, uh.y, ul.y);
        ((uint2*)(Ohi + (size_t)row * DMODEL))[t] = uh;
        ((uint2*)(Olo + (size_t)row * DMODEL))[t] = ul;
    }
}

// ---------------- host: tensormap + launch ------------------------------------
typedef CUresult (*EncodeFn)(
    CUtensorMap*, CUtensorMapDataType, cuuint32_t, void*,
    const cuuint64_t*, const cuuint64_t*, const cuuint32_t*, const cuuint32_t*,
    CUtensorMapInterleave, CUtensorMapSwizzle, CUtensorMapL2promotion,
    CUtensorMapFloatOOBfill);

static void make_desc(EncodeFn enc, CUtensorMap* out, void* ptr,
                      uint64_t rows, uint64_t K, uint32_t box1)
{
    cuuint64_t dims[2]    = {K, rows};
    cuuint64_t strides[1] = {K * 2};
    cuuint32_t box[2]     = {64, box1};
    cuuint32_t estr[2]    = {1, 1};
    enc(out, CU_TENSOR_MAP_DATA_TYPE_BFLOAT16, 2, ptr, dims, strides, box, estr,
        CU_TENSOR_MAP_INTERLEAVE_NONE, CU_TENSOR_MAP_SWIZZLE_128B,
        CU_TENSOR_MAP_L2_PROMOTION_L2_128B, CU_TENSOR_MAP_FLOAT_OOB_FILL_NONE);
}

extern "C" void kernel_launch(void* const* d_in, const int* in_sizes, int n_in,
                              void* d_out, int out_size)
{
    const float* X    = (const float*)d_in[0];
    const float* WQw  = (const float*)d_in[1];
    const float* WQb  = (const float*)d_in[2];
    const float* WKw  = (const float*)d_in[3];
    const float* WKb  = (const float*)d_in[4];
    const float* WVw  = (const float*)d_in[5];
    const float* WVb  = (const float*)d_in[6];
    const float* WOw  = (const float*)d_in[7];
    const float* WOb  = (const float*)d_in[8];
    const float* ln1g = (const float*)d_in[9];
    const float* ln1b = (const float*)d_in[10];
    const float* W1   = (const float*)d_in[11];
    const float* b1   = (const float*)d_in[12];
    const float* W2   = (const float*)d_in[13];
    const float* b2   = (const float*)d_in[14];
    const float* ln2g = (const float*)d_in[15];
    const float* ln2b = (const float*)d_in[16];
    float* out = (float*)d_out;

    float *Y, *X1, *M;
    cudaGetSymbolAddress((void**)&Y,  g_Y);
    cudaGetSymbolAddress((void**)&X1, g_X1);
    cudaGetSymbolAddress((void**)&M,  g_M);

    __nv_bfloat16 *Xhi,*Xlo,*X1hi,*X1lo,*CTXhi,*CTXlo,*HIDhi,*HIDlo;
    __nv_bfloat16 *Qhi,*Qlo,*Khi,*Klo,*Vhi,*Vlo,*VThi,*VTlo;
    __nv_bfloat16 *WQKVhi,*WQKVlo,*WOhi,*WOlo,*W1hi,*W1lo,*W2hi,*W2lo;
    cudaGetSymbolAddress((void**)&Xhi,  g_Xhi);  cudaGetSymbolAddress((void**)&Xlo,  g_Xlo);
    cudaGetSymbolAddress((void**)&X1hi, g_X1hi); cudaGetSymbolAddress((void**)&X1lo, g_X1lo);
    cudaGetSymbolAddress((void**)&CTXhi,g_CTXhi);cudaGetSymbolAddress((void**)&CTXlo,g_CTXlo);
    cudaGetSymbolAddress((void**)&Qhi,  g_Qhi);  cudaGetSymbolAddress((void**)&Qlo,  g_Qlo);
    cudaGetSymbolAddress((void**)&Khi,  g_Khi);  cudaGetSymbolAddress((void**)&Klo,  g_Klo);
    cudaGetSymbolAddress((void**)&Vhi,  g_Vhi);  cudaGetSymbolAddress((void**)&Vlo,  g_Vlo);
    cudaGetSymbolAddress((void**)&VThi, g_VThi); cudaGetSymbolAddress((void**)&VTlo, g_VTlo);
    cudaGetSymbolAddress((void**)&HIDhi,g_HIDhi);cudaGetSymbolAddress((void**)&HIDlo,g_HIDlo);
    cudaGetSymbolAddress((void**)&WQKVhi, g_WQKVhi); cudaGetSymbolAddress((void**)&WQKVlo, g_WQKVlo);
    cudaGetSymbolAddress((void**)&WOhi, g_WOhi); cudaGetSymbolAddress((void**)&WOlo, g_WOlo);
    cudaGetSymbolAddress((void**)&W1hi, g_W1hi); cudaGetSymbolAddress((void**)&W1lo, g_W1lo);
    cudaGetSymbolAddress((void**)&W2hi, g_W2hi); cudaGetSymbolAddress((void**)&W2lo, g_W2lo);

    EncodeFn enc = nullptr;
    {
        void* fp = nullptr;
        cudaDriverEntryPointQueryResult qr;
        cudaGetDriverEntryPoint("cuTensorMapEncodeTiled", &fp, cudaEnableDefault, &qr);
        enc = (EncodeFn)fp;
    }

    CUtensorMap dXhi, dXlo, dWQKVhi, dWQKVlo, dCTXhi, dCTXlo, dWOhi, dWOlo;
    CUtensorMap dX1hi, dX1lo, dW1hi, dW1lo, dHIDhi, dHIDlo, dW2hi, dW2lo;
    make_desc(enc, &dXhi,  Xhi,  NTOK, DMODEL, 64);   make_desc(enc, &dXlo,  Xlo,  NTOK, DMODEL, 64);
    make_desc(enc, &dWQKVhi, WQKVhi, 3*DMODEL, DMODEL, 128);
    make_desc(enc, &dWQKVlo, WQKVlo, 3*DMODEL, DMODEL, 128);
    make_desc(enc, &dCTXhi,CTXhi,NTOK, DMODEL, 64);   make_desc(enc, &dCTXlo,CTXlo,NTOK, DMODEL, 64);
    make_desc(enc, &dWOhi, WOhi, DMODEL, DMODEL, 128);make_desc(enc, &dWOlo, WOlo, DMODEL, DMODEL, 128);
    make_desc(enc, &dX1hi, X1hi, NTOK, DMODEL, 64);   make_desc(enc, &dX1lo, X1lo, NTOK, DMODEL, 64);
    make_desc(enc, &dW1hi, W1hi, DFFN, DMODEL, 128);  make_desc(enc, &dW1lo, W1lo, DFFN, DMODEL, 128);
    make_desc(enc, &dHIDhi,HIDhi,NTOK, DFFN, 64);     make_desc(enc, &dHIDlo,HIDlo,NTOK, DFFN, 64);
    make_desc(enc, &dW2hi, W2hi, DMODEL, DFFN, 128);  make_desc(enc, &dW2lo, W2lo, DMODEL, DFFN, 128);

    CUtensorMap dQhi, dKhi, dKlo, dVThi, dVTlo;
    make_desc(enc, &dQhi, Qhi, SLEN, BATCH*DMODEL, 128);
    make_desc(enc, &dKhi, Khi, SLEN, BATCH*DMODEL, 64);
    make_desc(enc, &dKlo, Klo, SLEN, BATCH*DMODEL, 64);
    make_desc(enc, &dVThi, VThi, BATCH*DMODEL, SLEN, 64);
    make_desc(enc, &dVTlo, VTlo, BATCH*DMODEL, SLEN, 64);

    cudaFuncSetAttribute(gemm_mma_kernel<1,0,0>, cudaFuncAttributeMaxDynamicSharedMemorySize, GEMM_SMEM);
    cudaFuncSetAttribute(gemm_mma_kernel<0,1,1>, cudaFuncAttributeMaxDynamicSharedMemorySize, GEMM_SMEM);
    cudaFuncSetAttribute(gemm_qkv_kernel, cudaFuncAttributeMaxDynamicSharedMemorySize, GEMM_SMEM);
    cudaFuncSetAttribute(attn_mma_kernel, cudaFuncAttributeMaxDynamicSharedMemorySize, ATT_SMEM);

    // ---- fused fp32 -> bf16 hi/lo split: 7 segments, one launch ----
    {
        CvtArgs a;
        const float* srcs[CVT_SEGS] = {X, WQw, WKw, WVw, WOw, W1, W2};
        __nv_bfloat16* his[CVT_SEGS] = {Xhi, WQKVhi, WQKVhi + DMODEL*DMODEL,
                                        WQKVhi + 2*DMODEL*DMODEL, WOhi, W1hi, W2hi};
        __nv_bfloat16* los[CVT_SEGS] = {Xlo, WQKVlo, WQKVlo + DMODEL*DMODEL,
                                        WQKVlo + 2*DMODEL*DMODEL, WOlo, W1lo, W2lo};
        int n4s[CVT_SEGS] = {NTOK*DMODEL/4, DMODEL*DMODEL/4, DMODEL*DMODEL/4,
                             DMODEL*DMODEL/4, DMODEL*DMODEL/4, DFFN*DMODEL/4, DMODEL*DFFN/4};
        int cum = 0;
        for (int i = 0; i < CVT_SEGS; i++) {
            a.src[i] = srcs[i]; a.hi[i] = his[i]; a.lo[i] = los[i]; a.n4[i] = n4s[i];
            cum += (n4s[i] + CVT_CHUNK - 1) / CVT_CHUNK;
            a.blk_end[i] = cum;
        }
        cvt_multi_kernel<<<cum, 256>>>(a);
    }

    dim3 gProj(DMODEL / 128, NTOK / 64);    // 8 x 128
    dim3 gQKV(3 * DMODEL / 128, NTOK / 64); // 24 x 128
    dim3 gFF1(DFFN / 128, NTOK / 64);       // 32 x 128

    // ---- fused QKV projection (Q pre-scaled by 0.125*log2e, RN hi) ----
    gemm_qkv_kernel<<<gQKV, 256, GEMM_SMEM>>>(dXhi, dXlo, dWQKVhi, dWQKVlo,
        WQb, WKb, WVb, Qhi, Qlo, Khi, Klo, Vhi, Vlo);

    // ---- V transpose for PV operand ----
    transpose_v_kernel<<<dim3(SLEN/32, DMODEL/64, BATCH), 256>>>(Vhi, Vlo, VThi, VTlo);

    // ---- attention (2-term QK / 2-term PV) ----
    attn_mma_kernel<<<dim3(SLEN/128, BATCH*NHEAD), 256, ATT_SMEM>>>(
        dQhi, dKhi, dKlo, dVThi, dVTlo, CTXhi, CTXlo);

    // ---- output projection + residual LN1 ----
    gemm_mma_kernel<1,0,0><<<gProj, 256, GEMM_SMEM>>>(dCTXhi, dCTXlo, dWOhi, dWOlo, WOb, Y, nullptr, nullptr, DMODEL, DMODEL);
    add_ln_kernel<1><<<NTOK, 256>>>(Y, X, ln1g, ln1b, X1, X1hi, X1lo);

    // ---- MLP ----
    gemm_mma_kernel<0,1,1><<<gFF1, 256, GEMM_SMEM>>>(dX1hi, dX1lo, dW1hi, dW1lo, b1, nullptr, HIDhi, HIDlo, DFFN, DMODEL);
    gemm_mma_kernel<1,0,0><<<gProj, 256, GEMM_SMEM>>>(dHIDhi, dHIDlo, dW2hi, dW2lo, b2, M, nullptr, nullptr, DMODEL, DFFN);
    add_ln_kernel<0><<<NTOK, 256>>>(M, X1, ln2g, ln2b, out, nullptr, nullptr);
}

// round 12
// speedup vs baseline: 1.2266x; 1.1030x over previous
#include <cuda_runtime.h>
#include <cuda.h>
#include <cuda_bf16.h>
#include <cstdint>

#define SLEN 2048
#define BATCH 4
#define DMODEL 1024
#define NHEAD 16
#define DKH 64
#define DFFN 4096
#define NTOK (SLEN*BATCH)   // 8192
#define LN_EPS 1e-5f
#define QSCALE 0.18033688011112042f   // 0.125 * log2(e)

// ---------------- scratch (device globals) ----------------------------------
__device__ __align__(1024) float g_Y[NTOK*DMODEL];
__device__ __align__(1024) float g_X1[NTOK*DMODEL];
__device__ __align__(1024) float g_M[NTOK*DMODEL];

__device__ __align__(1024) __nv_bfloat16 g_Xhi[NTOK*DMODEL],  g_Xlo[NTOK*DMODEL];
__device__ __align__(1024) __nv_bfloat16 g_X1hi[NTOK*DMODEL], g_X1lo[NTOK*DMODEL];
__device__ __align__(1024) __nv_bfloat16 g_CTXhi[NTOK*DMODEL],g_CTXlo[NTOK*DMODEL];
__device__ __align__(1024) __nv_bfloat16 g_Q[NTOK*DMODEL];
__device__ __align__(1024) __nv_bfloat16 g_K[NTOK*DMODEL];
__device__ __align__(1024) __nv_bfloat16 g_V[NTOK*DMODEL];
__device__ __align__(1024) __nv_bfloat16 g_VT[NTOK*DMODEL];
__device__ __align__(1024) __nv_bfloat16 g_HIDhi[NTOK*DFFN],  g_HIDlo[NTOK*DFFN];
__device__ __align__(1024) __nv_bfloat16 g_WQKVhi[3*DMODEL*DMODEL], g_WQKVlo[3*DMODEL*DMODEL];
__device__ __align__(1024) __nv_bfloat16 g_WOhi[DMODEL*DMODEL], g_WOlo[DMODEL*DMODEL];
__device__ __align__(1024) __nv_bfloat16 g_W1hi[DFFN*DMODEL],   g_W1lo[DFFN*DMODEL];
__device__ __align__(1024) __nv_bfloat16 g_W2hi[DMODEL*DFFN],   g_W2lo[DMODEL*DFFN];

// ---------------- PTX helpers (base-ISA only) --------------------------------
__device__ __forceinline__ uint32_t smem_to_u32(const void* p) {
    uint32_t a;
    asm("{ .reg .u64 t; cvta.to.shared.u64 t, %1; cvt.u32.u64 %0, t; }" : "=r"(a) : "l"(p));
    return a;
}
#define MBARRIER_INIT(mbar, cnt) \
    asm volatile("mbarrier.init.shared.b64 [%0], %1;" :: "r"((uint32_t)(mbar)), "r"((uint32_t)(cnt)) : "memory")
#define MBARRIER_EXPECT_TX(mbar, bytes) \
    asm volatile("mbarrier.arrive.expect_tx.shared.b64 _, [%0], %1;" :: "r"((uint32_t)(mbar)), "r"((uint32_t)(bytes)) : "memory")
#define MBARRIER_ARRIVE(mbar) \
    asm volatile("mbarrier.arrive.shared.b64 _, [%0];" :: "r"((uint32_t)(mbar)) : "memory")
#define FENCE_ASYNC_SHARED() asm volatile("fence.proxy.async.shared::cta;" ::: "memory")

#define MBARRIER_WAIT_PARITY(mbar_smem_addr, phase_parity) do { \
    uint32_t _mbar = (uint32_t)(mbar_smem_addr); \
    uint32_t _parity = (uint32_t)(phase_parity); \
    uint32_t _done; \
    asm volatile("{ .reg .pred p; mbarrier.try_wait.parity.acquire.cta.shared::cta.b64 p, [%1], %2; selp.b32 %0, 1, 0, p; }" \
        : "=r"(_done) : "r"(_mbar), "r"(_parity) : "memory"); \
    if (!_done) { \
        asm volatile("{ .reg .pred P1; WAIT_LOOP_%=: mbarrier.try_wait.parity.acquire.cta.shared::cta.b64 P1, [%0], %1, 0x989680; @P1 bra.uni WAIT_DONE_%=; bra.uni WAIT_LOOP_%=; WAIT_DONE_%=: }" \
            :: "r"(_mbar), "r"(_parity) : "memory"); \
    } \
} while(0)

__device__ __forceinline__ void tma_load_2d(uint32_t dst_smem, const CUtensorMap* m,
                                            int x, int y, uint32_t mbar) {
    asm volatile(
        "cp.async.bulk.tensor.2d.shared::cta.global.tile.mbarrier::complete_tx::bytes "
        "[%0], [%1, {%2, %3}], [%4];"
        :: "r"(dst_smem), "l"(m), "r"(x), "r"(y), "r"(mbar) : "memory");
}

__device__ __forceinline__ void mma_bf16(float* d, const uint32_t* a, const uint32_t* b) {
    asm volatile(
        "mma.sync.aligned.m16n8k16.row.col.f32.bf16.bf16.f32 "
        "{%0,%1,%2,%3},{%4,%5,%6,%7},{%8,%9},{%0,%1,%2,%3};"
        : "+f"(d[0]), "+f"(d[1]), "+f"(d[2]), "+f"(d[3])
        : "r"(a[0]), "r"(a[1]), "r"(a[2]), "r"(a[3]), "r"(b[0]), "r"(b[1]));
}

__device__ __forceinline__ void ldsm_x4(uint32_t* r, uint32_t addr) {
    asm volatile("ldmatrix.sync.aligned.m8n8.x4.shared.b16 {%0,%1,%2,%3}, [%4];"
        : "=r"(r[0]), "=r"(r[1]), "=r"(r[2]), "=r"(r[3]) : "r"(addr));
}

__device__ __forceinline__ float ex2f(float x) {
    float y; asm("ex2.approx.f32 %0, %1;" : "=f"(y) : "f"(x)); return y;
}

// fast hi/lo split: hi = truncated-bf16 pair via PRMT, lo = packed via cvt.bf16x2
__device__ __forceinline__ void split_pack2(float a, float b, uint32_t& hi, uint32_t& lo) {
    uint32_t ua = __float_as_uint(a), ub = __float_as_uint(b);
    uint32_t h;
    asm("prmt.b32 %0, %1, %2, 0x7632;" : "=r"(h) : "r"(ua), "r"(ub));
    float la = a - __uint_as_float(ua & 0xffff0000u);
    float lb = b - __uint_as_float(ub & 0xffff0000u);
    uint32_t l;
    asm("cvt.rn.bf16x2.f32 %0, %1, %2;" : "=r"(l) : "f"(lb), "f"(la));
    hi = h; lo = l;
}
// round-to-nearest bf16x2 pack (unbiased single-term representation)
__device__ __forceinline__ uint32_t rn_pack2(float a, float b) {
    uint32_t r;
    asm("cvt.rn.bf16x2.f32 %0, %1, %2;" : "=r"(r) : "f"(b), "f"(a));
    return r;
}

// ---------------- fused fp32 -> bf16 hi/lo split (multi-segment) -------------
#define CVT_SEGS 7
#define CVT_CHUNK 512
struct CvtArgs {
    const float* src[CVT_SEGS];
    __nv_bfloat16* hi[CVT_SEGS];
    __nv_bfloat16* lo[CVT_SEGS];
    int blk_end[CVT_SEGS];
    int n4[CVT_SEGS];
};

__global__ void __launch_bounds__(256) cvt_multi_kernel(const __grid_constant__ CvtArgs a)
{
    int seg = 0;
#pragma unroll
    for (int k = 0; k < CVT_SEGS - 1; k++)
        if (blockIdx.x >= (unsigned)a.blk_end[k]) seg = k + 1;
    const int local = blockIdx.x - (seg ? a.blk_end[seg - 1] : 0);
    const float* src = a.src[seg];
    __nv_bfloat16* hi = a.hi[seg];
    __nv_bfloat16* lo = a.lo[seg];
    const int n4 = a.n4[seg];
#pragma unroll
    for (int p = 0; p < 2; p++) {
        int i = local * CVT_CHUNK + p * 256 + threadIdx.x;
        if (i < n4) {
            float4 v = ((const float4*)src)[i];
            uint2 uh, ul;
            split_pack2(v.x, v.y, uh.x, ul.x);
            split_pack2(v.z, v.w, uh.y, ul.y);
            ((uint2*)hi)[i] = uh;
            ((uint2*)lo)[i] = ul;
        }
    }
}

// ---------------- split-bf16 GEMM mainloop: 64x128 tile, occ 2 ---------------
#define ST_AHI 0
#define ST_ALO 8192
#define ST_BHI 16384
#define ST_BLO 32768
#define ST_BYTES 49152
#define NPIPE 2
#define GEMM_SMEM (NPIPE*ST_BYTES + 64)

__device__ __forceinline__ void gemm_mainloop(
    const CUtensorMap* mAhi, const CUtensorMap* mAlo,
    const CUtensorMap* mBhi, const CUtensorMap* mBlo,
    int bm, int bn, int nst, char* smem, float acc[][4][4])
{
    const uint32_t sbase = smem_to_u32(smem);
    const uint32_t mbb = sbase + NPIPE * ST_BYTES;
    const int tid = threadIdx.x;
    const int wid = tid >> 5;
    const int lane = tid & 31;
    const int wm = wid & 1;
    const int wn = wid >> 1;

    if (tid == 0) {
#pragma unroll
        for (int i = 0; i < NPIPE; i++) {
            MBARRIER_INIT(mbb + i * 8, 1);        // full
            MBARRIER_INIT(mbb + 16 + i * 8, 8);   // empty (8 warps)
        }
    }
    FENCE_ASYNC_SHARED();
    __syncthreads();

    if (tid == 0) {
#pragma unroll
        for (int s = 0; s < NPIPE; s++) {
            uint32_t mb = mbb + s * 8;
            uint32_t dst = sbase + s * ST_BYTES;
            MBARRIER_EXPECT_TX(mb, ST_BYTES);
            tma_load_2d(dst + ST_AHI, mAhi, s * 64, bm, mb);
            tma_load_2d(dst + ST_ALO, mAlo, s * 64, bm, mb);
            tma_load_2d(dst + ST_BHI, mBhi, s * 64, bn, mb);
            tma_load_2d(dst + ST_BLO, mBlo, s * 64, bn, mb);
        }
    }

    const uint32_t m16 = (lane & 7) * 16;
    const int rA = (lane & 7) + ((lane >> 3) & 1) * 8;
    const uint32_t hA = ((lane >> 4) & 1) * 16;
    const int rB = (lane & 7) + ((lane >> 4) & 1) * 8;
    const uint32_t hB = ((lane >> 3) & 1) * 16;
    uint32_t aoff[2], boff[2];
#pragma unroll
    for (int t = 0; t < 2; t++) aoff[t] = (uint32_t)(wm * 32 + t * 16 + rA) * 128;
#pragma unroll
    for (int jp = 0; jp < 2; jp++) boff[jp] = (uint32_t)(wn * 32 + jp * 16 + rB) * 128;

    int buf = 0, ph = 0;
    for (int s = 0; s < nst; s++) {
        MBARRIER_WAIT_PARITY(mbb + buf * 8, ph);
        const uint32_t sb = sbase + buf * ST_BYTES;

#pragma unroll
        for (int ks = 0; ks < 4; ks++) {
            const uint32_t cA = (ks * 32 + hA) ^ m16;
            const uint32_t cB = (ks * 32 + hB) ^ m16;
            uint32_t ah[2][4], al[2][4];
#pragma unroll
            for (int t = 0; t < 2; t++) {
                ldsm_x4(ah[t], sb + ST_AHI + aoff[t] + cA);
                ldsm_x4(al[t], sb + ST_ALO + aoff[t] + cA);
            }
            uint32_t bh[2][4], bl[2][4];
#pragma unroll
            for (int jp = 0; jp < 2; jp++) {
                ldsm_x4(bh[jp], sb + ST_BHI + boff[jp] + cB);
                ldsm_x4(bl[jp], sb + ST_BLO + boff[jp] + cB);
            }
#pragma unroll
            for (int t = 0; t < 2; t++)
#pragma unroll
                for (int jp = 0; jp < 2; jp++) {
                    mma_bf16(acc[t][2*jp],   ah[t], &bh[jp][0]);
                    mma_bf16(acc[t][2*jp],   ah[t], &bl[jp][0]);
                    mma_bf16(acc[t][2*jp],   al[t], &bh[jp][0]);
                    mma_bf16(acc[t][2*jp+1], ah[t], &bh[jp][2]);
                    mma_bf16(acc[t][2*jp+1], ah[t], &bl[jp][2]);
                    mma_bf16(acc[t][2*jp+1], al[t], &bh[jp][2]);
                }
        }

        if (lane == 0) MBARRIER_ARRIVE(mbb + 16 + buf * 8);
        if (tid == 0 && s + NPIPE < nst) {
            MBARRIER_WAIT_PARITY(mbb + 16 + buf * 8, ph);
            uint32_t mb = mbb + buf * 8;
            uint32_t dst = sbase + buf * ST_BYTES;
            MBARRIER_EXPECT_TX(mb, ST_BYTES);
            tma_load_2d(dst + ST_AHI, mAhi, (s + NPIPE) * 64, bm, mb);
            tma_load_2d(dst + ST_ALO, mAlo, (s + NPIPE) * 64, bm, mb);
            tma_load_2d(dst + ST_BHI, mBhi, (s + NPIPE) * 64, bn, mb);
            tma_load_2d(dst + ST_BLO, mBlo, (s + NPIPE) * 64, bn, mb);
        }
        if (++buf == NPIPE) { buf = 0; ph ^= 1; }
    }
}

// ---------------- generic GEMM kernel (64x128 out per CTA) -------------------
template<int WRITE_F32, int WRITE_HILO, int RELU>
__global__ void __launch_bounds__(256, 2) gemm_mma_kernel(
    const __grid_constant__ CUtensorMap mAhi,
    const __grid_constant__ CUtensorMap mAlo,
    const __grid_constant__ CUtensorMap mBhi,
    const __grid_constant__ CUtensorMap mBlo,
    const float* __restrict__ bias,
    float* __restrict__ C, __nv_bfloat16* __restrict__ Chi, __nv_bfloat16* __restrict__ Clo,
    int N, int K)
{
    extern __shared__ char smem[];
    const int bm = blockIdx.y * 64;
    const int bn = blockIdx.x * 128;
    float acc[2][4][4];
#pragma unroll
    for (int t = 0; t < 2; t++)
#pragma unroll
        for (int j = 0; j < 4; j++)
#pragma unroll
            for (int q = 0; q < 4; q++) acc[t][j][q] = 0.f;

    gemm_mainloop(&mAhi, &mAlo, &mBhi, &mBlo, bm, bn, K >> 6, smem, acc);

    const int lane = threadIdx.x & 31;
    const int wid = threadIdx.x >> 5;
    const int g = lane >> 2, tq = lane & 3;
    const int wm = wid & 1, wn = wid >> 1;
#pragma unroll
    for (int t = 0; t < 2; t++) {
        int row = bm + wm * 32 + t * 16 + g;
#pragma unroll
        for (int j = 0; j < 4; j++) {
            int col = bn + wn * 32 + j * 8 + tq * 2;
            float2 bj = *(const float2*)&bias[col];
            float v0 = acc[t][j][0] + bj.x;
            float v1 = acc[t][j][1] + bj.y;
            float v2 = acc[t][j][2] + bj.x;
            float v3 = acc[t][j][3] + bj.y;
            if (RELU) {
                v0 = fmaxf(v0, 0.f); v1 = fmaxf(v1, 0.f);
                v2 = fmaxf(v2, 0.f); v3 = fmaxf(v3, 0.f);
            }
            if (WRITE_F32) {
                *(float2*)&C[(size_t)row * N + col]       = make_float2(v0, v1);
                *(float2*)&C[(size_t)(row + 8) * N + col] = make_float2(v2, v3);
            }
            if (WRITE_HILO) {
                uint32_t h01, l01, h23, l23;
                split_pack2(v0, v1, h01, l01);
                split_pack2(v2, v3, h23, l23);
                *(uint32_t*)&Chi[(size_t)row * N + col]       = h01;
                *(uint32_t*)&Chi[(size_t)(row + 8) * N + col] = h23;
                *(uint32_t*)&Clo[(size_t)row * N + col]       = l01;
                *(uint32_t*)&Clo[(size_t)(row + 8) * N + col] = l23;
            }
        }
    }
}

// ---------------- fused QKV GEMM: all outputs single RN bf16 -----------------
__global__ void __launch_bounds__(256, 2) gemm_qkv_kernel(
    const __grid_constant__ CUtensorMap mAhi,
    const __grid_constant__ CUtensorMap mAlo,
    const __grid_constant__ CUtensorMap mBhi,
    const __grid_constant__ CUtensorMap mBlo,
    const float* __restrict__ bQ, const float* __restrict__ bK, const float* __restrict__ bV,
    __nv_bfloat16* __restrict__ Q, __nv_bfloat16* __restrict__ K,
    __nv_bfloat16* __restrict__ V)
{
    extern __shared__ char smem[];
    const int bm = blockIdx.y * 64;
    const int bn = blockIdx.x * 128;
    float acc[2][4][4];
#pragma unroll
    for (int t = 0; t < 2; t++)
#pragma unroll
        for (int j = 0; j < 4; j++)
#pragma unroll
            for (int q = 0; q < 4; q++) acc[t][j][q] = 0.f;

    gemm_mainloop(&mAhi, &mAlo, &mBhi, &mBlo, bm, bn, DMODEL >> 6, smem, acc);

    const int part = blockIdx.x >> 3;          // 0=Q 1=K 2=V
    const int nb = (blockIdx.x & 7) * 128;
    const float* bias = (part == 0) ? bQ : (part == 1) ? bK : bV;
    __nv_bfloat16* O = (part == 0) ? Q : (part == 1) ? K : V;
    const float scl = (part == 0) ? QSCALE : 1.0f;

    const int lane = threadIdx.x & 31;
    const int wid = threadIdx.x >> 5;
    const int g = lane >> 2, tq = lane & 3;
    const int wm = wid & 1, wn = wid >> 1;
#pragma unroll
    for (int t = 0; t < 2; t++) {
        int row = bm + wm * 32 + t * 16 + g;
#pragma unroll
        for (int j = 0; j < 4; j++) {
            int col = nb + wn * 32 + j * 8 + tq * 2;
            float2 bj = *(const float2*)&bias[col];
            float v0 = (acc[t][j][0] + bj.x) * scl;
            float v1 = (acc[t][j][1] + bj.y) * scl;
            float v2 = (acc[t][j][2] + bj.x) * scl;
            float v3 = (acc[t][j][3] + bj.y) * scl;
            *(uint32_t*)&O[(size_t)row * DMODEL + col]       = rn_pack2(v0, v1);
            *(uint32_t*)&O[(size_t)(row + 8) * DMODEL + col] = rn_pack2(v2, v3);
        }
    }
}

// ---------------- V transpose: V[s*4+b][d] -> VT[(b*DM+d)][s] -----------------
__global__ void __launch_bounds__(256) transpose_v_kernel(
    const __nv_bfloat16* __restrict__ V, __nv_bfloat16* __restrict__ VT)
{
    __shared__ __nv_bfloat16 sh[32][64 + 4];
    const int tid = threadIdx.x;
    const int s0 = blockIdx.x * 32;
    const int d0 = blockIdx.y * 64;
    const int b  = blockIdx.z;

#pragma unroll
    for (int p = 0; p < 2; p++) {
        int idx = tid + p * 256;
        int srow = idx >> 4;
        int dq = idx & 15;
        size_t ga = ((size_t)(s0 + srow) * BATCH + b) * DMODEL + d0 + dq * 4;
        *(uint2*)&sh[srow][dq * 4] = *(const uint2*)(V + ga);
    }
    __syncthreads();
#pragma unroll
    for (int p = 0; p < 2; p++) {
        int idx = tid + p * 256;
        int drow = idx >> 3;
        int sq = idx & 7;
        __nv_bfloat16 oh[4];
#pragma unroll
        for (int k = 0; k < 4; k++) oh[k] = sh[sq * 4 + k][drow];
        size_t ga = ((size_t)(b * DMODEL + d0 + drow)) * SLEN + s0 + sq * 4;
        *(uint2*)(VT + ga) = *(uint2*)oh;
    }
}

// ---------------- Flash attention (fully 1-term RN bf16) ---------------------
// smem: Q 16K | stage{K 8K, V 8K} x2 | ctrl
#define ATT_Q 0
#define ATT_ST0 16384
#define ATT_STSZ 16384
#define ATT_CTRL (ATT_ST0 + 2*ATT_STSZ)
#define ATT_SMEM (ATT_CTRL + 64)
#define NKT (SLEN/64)

__global__ void __launch_bounds__(256, 2) attn_mma_kernel(
    const __grid_constant__ CUtensorMap mQ,
    const __grid_constant__ CUtensorMap mK,
    const __grid_constant__ CUtensorMap mV,
    __nv_bfloat16* __restrict__ Ohi, __nv_bfloat16* __restrict__ Olo)
{
    extern __shared__ char smem[];
    const uint32_t sbase = smem_to_u32(smem);
    const uint32_t mbb = sbase + ATT_CTRL;   // full0,full1 @ +0,+8; empty0,empty1 @ +16,+24
    const int tid = threadIdx.x;
    const int w = tid >> 5;
    const int lane = tid & 31;
    const int g = lane >> 2;
    const int t = lane & 3;
    const int q0 = blockIdx.x * 128;
    const int b = blockIdx.y >> 4;
    const int h = blockIdx.y & 15;
    const int xqk = b * DMODEL + h * 64;

    if (tid == 0) {
        MBARRIER_INIT(mbb + 0, 1);
        MBARRIER_INIT(mbb + 8, 1);
        MBARRIER_INIT(mbb + 16, 8);
        MBARRIER_INIT(mbb + 24, 8);
    }
    FENCE_ASYNC_SHARED();
    __syncthreads();

    if (tid == 0) {
        MBARRIER_EXPECT_TX(mbb + 0, ATT_STSZ + 16384);
        tma_load_2d(sbase + ATT_Q, &mQ, xqk, q0, mbb + 0);
        tma_load_2d(sbase + ATT_ST0 + 0,    &mK, xqk, 0, mbb + 0);
        tma_load_2d(sbase + ATT_ST0 + 8192, &mV, 0, xqk, mbb + 0);
        MBARRIER_EXPECT_TX(mbb + 8, ATT_STSZ);
        tma_load_2d(sbase + ATT_ST0 + ATT_STSZ + 0,    &mK, xqk, 64, mbb + 8);
        tma_load_2d(sbase + ATT_ST0 + ATT_STSZ + 8192, &mV, 64, xqk, mbb + 8);
    }

    const uint32_t m16 = (lane & 7) * 16;
    const int rA = (lane & 7) + ((lane >> 3) & 1) * 8;
    const uint32_t hA = ((lane >> 4) & 1) * 16;
    const int rB = (lane & 7) + ((lane >> 4) & 1) * 8;
    const uint32_t hB = ((lane >> 3) & 1) * 16;
    const uint32_t qoff = (uint32_t)(w * 16 + rA) * 128;
    uint32_t kvoff[4];
#pragma unroll
    for (int jp = 0; jp < 4; jp++) kvoff[jp] = (uint32_t)(jp * 16 + rB) * 128;

    float l_i[2] = {0.f, 0.f};
    float acc[8][4];
#pragma unroll
    for (int j = 0; j < 8; j++)
#pragma unroll
        for (int q = 0; q < 4; q++) acc[j][q] = 0.f;

    for (int s = 0; s < NKT; s++) {
        const int buf = s & 1;
        const int ph = (s >> 1) & 1;
        MBARRIER_WAIT_PARITY(mbb + buf * 8, ph);
        const uint32_t Kbu = sbase + ATT_ST0 + buf * ATT_STSZ;
        const uint32_t Vbu = Kbu + 8192;

        // ---- scores = Q K^T (both RN bf16, fp32 accum) ----
        float sc[8][4];
#pragma unroll
        for (int j = 0; j < 8; j++)
#pragma unroll
            for (int q = 0; q < 4; q++) sc[j][q] = 0.f;

#pragma unroll
        for (int ks = 0; ks < 4; ks++) {
            const uint32_t cA = (ks * 32 + hA) ^ m16;
            const uint32_t cB = (ks * 32 + hB) ^ m16;
            uint32_t qh[4];
            ldsm_x4(qh, sbase + ATT_Q + qoff + cA);
#pragma unroll
            for (int jp = 0; jp < 4; jp++) {
                uint32_t kh[4];
                ldsm_x4(kh, Kbu + kvoff[jp] + cB);
                mma_bf16(sc[2*jp],   qh, &kh[0]);
                mma_bf16(sc[2*jp+1], qh, &kh[2]);
            }
        }

        // p = exp2(score); l accumulated from fp32 p
        float s0 = 0.f, s1 = 0.f;
#pragma unroll
        for (int j = 0; j < 8; j++) {
            sc[j][0] = ex2f(sc[j][0]);
            sc[j][1] = ex2f(sc[j][1]);
            sc[j][2] = ex2f(sc[j][2]);
            sc[j][3] = ex2f(sc[j][3]);
            s0 += sc[j][0] + sc[j][1];
            s1 += sc[j][2] + sc[j][3];
        }
        l_i[0] += s0;
        l_i[1] += s1;

        // ---- ctx += P_rn V ----
#pragma unroll
        for (int ks = 0; ks < 4; ks++) {
            uint32_t pah[4];
            pah[0] = rn_pack2(sc[2*ks][0],   sc[2*ks][1]);
            pah[1] = rn_pack2(sc[2*ks][2],   sc[2*ks][3]);
            pah[2] = rn_pack2(sc[2*ks+1][0], sc[2*ks+1][1]);
            pah[3] = rn_pack2(sc[2*ks+1][2], sc[2*ks+1][3]);
            const uint32_t cB = (ks * 32 + hB) ^ m16;
#pragma unroll
            for (int jp = 0; jp < 4; jp++) {
                uint32_t vh[4];
                ldsm_x4(vh, Vbu + kvoff[jp] + cB);
                mma_bf16(acc[2*jp],   pah, &vh[0]);
                mma_bf16(acc[2*jp+1], pah, &vh[2]);
            }
        }

        if (lane == 0) MBARRIER_ARRIVE(mbb + 16 + buf * 8);
        if (tid == 0 && s + 2 < NKT) {
            MBARRIER_WAIT_PARITY(mbb + 16 + buf * 8, ph);
            uint32_t mb = mbb + buf * 8;
            uint32_t dst = sbase + ATT_ST0 + buf * ATT_STSZ;
            MBARRIER_EXPECT_TX(mb, ATT_STSZ);
            tma_load_2d(dst + 0,    &mK, xqk, (s + 2) * 64, mb);
            tma_load_2d(dst + 8192, &mV, (s + 2) * 64, xqk, mb);
        }
    }

    float l0 = l_i[0], l1 = l_i[1];
    l0 += __shfl_xor_sync(0xffffffffu, l0, 1);
    l0 += __shfl_xor_sync(0xffffffffu, l0, 2);
    l1 += __shfl_xor_sync(0xffffffffu, l1, 1);
    l1 += __shfl_xor_sync(0xffffffffu, l1, 2);

    const float inv0 = 1.0f / l0;
    const float inv1 = 1.0f / l1;
    const int row0 = q0 + w * 16 + g;
    const int row1 = row0 + 8;
    const size_t tok0 = (size_t)row0 * BATCH + b;
    const size_t tok1 = (size_t)row1 * BATCH + b;
#pragma unroll
    for (int j = 0; j < 8; j++) {
        const int col = h * 64 + j * 8 + t * 2;
        uint32_t h01, l01, h23, l23;
        split_pack2(acc[j][0] * inv0, acc[j][1] * inv0, h01, l01);
        split_pack2(acc[j][2] * inv1, acc[j][3] * inv1, h23, l23);
        *(uint32_t*)&Ohi[tok0 * DMODEL + col] = h01;
        *(uint32_t*)&Olo[tok0 * DMODEL + col] = l01;
        *(uint32_t*)&Ohi[tok1 * DMODEL + col] = h23;
        *(uint32_t*)&Olo[tok1 * DMODEL + col] = l23;
    }
}

// ---------------- fused residual add + LayerNorm -----------------------------
template<int HILO>
__global__ void __launch_bounds__(256) add_ln_kernel(
    const float* __restrict__ A, const float* __restrict__ R,
    const float* __restrict__ gam, const float* __restrict__ bet,
    float* __restrict__ out, __nv_bfloat16* __restrict__ Ohi,
    __nv_bfloat16* __restrict__ Olo)
{
    __shared__ float red_s[8];
    __shared__ float red_ss[8];
    __shared__ float s_mu, s_rstd;
    const int row = blockIdx.x;
    const int t = threadIdx.x;
    float4 v = ((const float4*)(A + (size_t)row * DMODEL))[t];
    float4 w = ((const float4*)(R + (size_t)row * DMODEL))[t];
    v.x += w.x; v.y += w.y; v.z += w.z; v.w += w.w;
    float s = v.x + v.y + v.z + v.w;
    float ss = v.x * v.x + v.y * v.y + v.z * v.z + v.w * v.w;
#pragma unroll
    for (int off = 16; off >= 1; off >>= 1) {
        s  += __shfl_xor_sync(0xffffffffu, s, off);
        ss += __shfl_xor_sync(0xffffffffu, ss, off);
    }
    if ((t & 31) == 0) { red_s[t >> 5] = s; red_ss[t >> 5] = ss; }
    __syncthreads();
    if (t == 0) {
        float ts = 0.f, tss = 0.f;
#pragma unroll
        for (int i = 0; i < 8; i++) { ts += red_s[i]; tss += red_ss[i]; }
        float mu = ts * (1.0f / DMODEL);
        float var = tss * (1.0f / DMODEL) - mu * mu;
        s_mu = mu;
        s_rstd = rsqrtf(var + LN_EPS);
    }
    __syncthreads();
    float mu = s_mu, rs = s_rstd;
    float4 g = ((const float4*)gam)[t], bb = ((const float4*)bet)[t];
    float4 o;
    o.x = (v.x - mu) * rs * g.x + bb.x;
    o.y = (v.y - mu) * rs * g.y + bb.y;
    o.z = (v.z - mu) * rs * g.z + bb.z;
    o.w = (v.w - mu) * rs * g.w + bb.w;
    ((float4*)(out + (size_t)row * DMODEL))[t] = o;
    if (HILO) {
        uint2 uh, ul;
        split_pack2(o.x, o.y, uh.x, ul.x);
        split_pack2(o.z, o.w, uh.y, ul.y);
        ((uint2*)(Ohi + (size_t)row * DMODEL))[t] = uh;
        ((uint2*)(Olo + (size_t)row * DMODEL))[t] = ul;
    }
}

// ---------------- host: tensormap + launch ------------------------------------
typedef CUresult (*EncodeFn)(
    CUtensorMap*, CUtensorMapDataType, cuuint32_t, void*,
    const cuuint64_t*, const cuuint64_t*, const cuuint32_t*, const cuuint32_t*,
    CUtensorMapInterleave, CUtensorMapSwizzle, CUtensorMapL2promotion,
    CUtensorMapFloatOOBfill);

static void make_desc(EncodeFn enc, CUtensorMap* out, void* ptr,
                      uint64_t rows, uint64_t K, uint32_t box1)
{
    cuuint64_t dims[2]    = {K, rows};
    cuuint64_t strides[1] = {K * 2};
    cuuint32_t box[2]     = {64, box1};
    cuuint32_t estr[2]    = {1, 1};
    enc(out, CU_TENSOR_MAP_DATA_TYPE_BFLOAT16, 2, ptr, dims, strides, box, estr,
        CU_TENSOR_MAP_INTERLEAVE_NONE, CU_TENSOR_MAP_SWIZZLE_128B,
        CU_TENSOR_MAP_L2_PROMOTION_L2_128B, CU_TENSOR_MAP_FLOAT_OOB_FILL_NONE);
}

extern "C" void kernel_launch(void* const* d_in, const int* in_sizes, int n_in,
                              void* d_out, int out_size)
{
    const float* X    = (const float*)d_in[0];
    const float* WQw  = (const float*)d_in[1];
    const float* WQb  = (const float*)d_in[2];
    const float* WKw  = (const float*)d_in[3];
    const float* WKb  = (const float*)d_in[4];
    const float* WVw  = (const float*)d_in[5];
    const float* WVb  = (const float*)d_in[6];
    const float* WOw  = (const float*)d_in[7];
    const float* WOb  = (const float*)d_in[8];
    const float* ln1g = (const float*)d_in[9];
    const float* ln1b = (const float*)d_in[10];
    const float* W1   = (const float*)d_in[11];
    const float* b1   = (const float*)d_in[12];
    const float* W2   = (const float*)d_in[13];
    const float* b2   = (const float*)d_in[14];
    const float* ln2g = (const float*)d_in[15];
    const float* ln2b = (const float*)d_in[16];
    float* out = (float*)d_out;

    float *Y, *X1, *M;
    cudaGetSymbolAddress((void**)&Y,  g_Y);
    cudaGetSymbolAddress((void**)&X1, g_X1);
    cudaGetSymbolAddress((void**)&M,  g_M);

    __nv_bfloat16 *Xhi,*Xlo,*X1hi,*X1lo,*CTXhi,*CTXlo,*HIDhi,*HIDlo;
    __nv_bfloat16 *Q,*K,*V,*VT;
    __nv_bfloat16 *WQKVhi,*WQKVlo,*WOhi,*WOlo,*W1hi,*W1lo,*W2hi,*W2lo;
    cudaGetSymbolAddress((void**)&Xhi,  g_Xhi);  cudaGetSymbolAddress((void**)&Xlo,  g_Xlo);
    cudaGetSymbolAddress((void**)&X1hi, g_X1hi); cudaGetSymbolAddress((void**)&X1lo, g_X1lo);
    cudaGetSymbolAddress((void**)&CTXhi,g_CTXhi);cudaGetSymbolAddress((void**)&CTXlo,g_CTXlo);
    cudaGetSymbolAddress((void**)&Q,  g_Q);
    cudaGetSymbolAddress((void**)&K,  g_K);
    cudaGetSymbolAddress((void**)&V,  g_V);
    cudaGetSymbolAddress((void**)&VT, g_VT);
    cudaGetSymbolAddress((void**)&HIDhi,g_HIDhi);cudaGetSymbolAddress((void**)&HIDlo,g_HIDlo);
    cudaGetSymbolAddress((void**)&WQKVhi, g_WQKVhi); cudaGetSymbolAddress((void**)&WQKVlo, g_WQKVlo);
    cudaGetSymbolAddress((void**)&WOhi, g_WOhi); cudaGetSymbolAddress((void**)&WOlo, g_WOlo);
    cudaGetSymbolAddress((void**)&W1hi, g_W1hi); cudaGetSymbolAddress((void**)&W1lo, g_W1lo);
    cudaGetSymbolAddress((void**)&W2hi, g_W2hi); cudaGetSymbolAddress((void**)&W2lo, g_W2lo);

    EncodeFn enc = nullptr;
    {
        void* fp = nullptr;
        cudaDriverEntryPointQueryResult qr;
        cudaGetDriverEntryPoint("cuTensorMapEncodeTiled", &fp, cudaEnableDefault, &qr);
        enc = (EncodeFn)fp;
    }

    CUtensorMap dXhi, dXlo, dWQKVhi, dWQKVlo, dCTXhi, dCTXlo, dWOhi, dWOlo;
    CUtensorMap dX1hi, dX1lo, dW1hi, dW1lo, dHIDhi, dHIDlo, dW2hi, dW2lo;
    make_desc(enc, &dXhi,  Xhi,  NTOK, DMODEL, 64);   make_desc(enc, &dXlo,  Xlo,  NTOK, DMODEL, 64);
    make_desc(enc, &dWQKVhi, WQKVhi, 3*DMODEL, DMODEL, 128);
    make_desc(enc, &dWQKVlo, WQKVlo, 3*DMODEL, DMODEL, 128);
    make_desc(enc, &dCTXhi,CTXhi,NTOK, DMODEL, 64);   make_desc(enc, &dCTXlo,CTXlo,NTOK, DMODEL, 64);
    make_desc(enc, &dWOhi, WOhi, DMODEL, DMODEL, 128);make_desc(enc, &dWOlo, WOlo, DMODEL, DMODEL, 128);
    make_desc(enc, &dX1hi, X1hi, NTOK, DMODEL, 64);   make_desc(enc, &dX1lo, X1lo, NTOK, DMODEL, 64);
    make_desc(enc, &dW1hi, W1hi, DFFN, DMODEL, 128);  make_desc(enc, &dW1lo, W1lo, DFFN, DMODEL, 128);
    make_desc(enc, &dHIDhi,HIDhi,NTOK, DFFN, 64);     make_desc(enc, &dHIDlo,HIDlo,NTOK, DFFN, 64);
    make_desc(enc, &dW2hi, W2hi, DMODEL, DFFN, 128);  make_desc(enc, &dW2lo, W2lo, DMODEL, DFFN, 128);

    CUtensorMap dQ, dK, dVT;
    make_desc(enc, &dQ, Q, SLEN, BATCH*DMODEL, 128);
    make_desc(enc, &dK, K, SLEN, BATCH*DMODEL, 64);
    make_desc(enc, &dVT, VT, BATCH*DMODEL, SLEN, 64);

    cudaFuncSetAttribute(gemm_mma_kernel<1,0,0>, cudaFuncAttributeMaxDynamicSharedMemorySize, GEMM_SMEM);
    cudaFuncSetAttribute(gemm_mma_kernel<0,1,1>, cudaFuncAttributeMaxDynamicSharedMemorySize, GEMM_SMEM);
    cudaFuncSetAttribute(gemm_qkv_kernel, cudaFuncAttributeMaxDynamicSharedMemorySize, GEMM_SMEM);
    cudaFuncSetAttribute(attn_mma_kernel, cudaFuncAttributeMaxDynamicSharedMemorySize, ATT_SMEM);

    // ---- fused fp32 -> bf16 hi/lo split: 7 segments, one launch ----
    {
        CvtArgs a;
        const float* srcs[CVT_SEGS] = {X, WQw, WKw, WVw, WOw, W1, W2};
        __nv_bfloat16* his[CVT_SEGS] = {Xhi, WQKVhi, WQKVhi + DMODEL*DMODEL,
                                        WQKVhi + 2*DMODEL*DMODEL, WOhi, W1hi, W2hi};
        __nv_bfloat16* los[CVT_SEGS] = {Xlo, WQKVlo, WQKVlo + DMODEL*DMODEL,
                                        WQKVlo + 2*DMODEL*DMODEL, WOlo, W1lo, W2lo};
        int n4s[CVT_SEGS] = {NTOK*DMODEL/4, DMODEL*DMODEL/4, DMODEL*DMODEL/4,
                             DMODEL*DMODEL/4, DMODEL*DMODEL/4, DFFN*DMODEL/4, DMODEL*DFFN/4};
        int cum = 0;
        for (int i = 0; i < CVT_SEGS; i++) {
            a.src[i] = srcs[i]; a.hi[i] = his[i]; a.lo[i] = los[i]; a.n4[i] = n4s[i];
            cum += (n4s[i] + CVT_CHUNK - 1) / CVT_CHUNK;
            a.blk_end[i] = cum;
        }
        cvt_multi_kernel<<<cum, 256>>>(a);
    }

    dim3 gProj(DMODEL / 128, NTOK / 64);    // 8 x 128
    dim3 gQKV(3 * DMODEL / 128, NTOK / 64); // 24 x 128
    dim3 gFF1(DFFN / 128, NTOK / 64);       // 32 x 128

    // ---- fused QKV projection (Q pre-scaled by 0.125*log2e; RN bf16 out) ----
    gemm_qkv_kernel<<<gQKV, 256, GEMM_SMEM>>>(dXhi, dXlo, dWQKVhi, dWQKVlo,
        WQb, WKb, WVb, Q, K, V);

    // ---- V transpose for PV operand ----
    transpose_v_kernel<<<dim3(SLEN/32, DMODEL/64, BATCH), 256>>>(V, VT);

    // ---- attention (1-term RN bf16 Q/K/P/V, fp32 accum) ----
    attn_mma_kernel<<<dim3(SLEN/128, BATCH*NHEAD), 256, ATT_SMEM>>>(
        dQ, dK, dVT, CTXhi, CTXlo);

    // ---- output projection + residual LN1 ----
    gemm_mma_kernel<1,0,0><<<gProj, 256, GEMM_SMEM>>>(dCTXhi, dCTXlo, dWOhi, dWOlo, WOb, Y, nullptr, nullptr, DMODEL, DMODEL);
    add_ln_kernel<1><<<NTOK, 256>>>(Y, X, ln1g, ln1b, X1, X1hi, X1lo);

    // ---- MLP ----
    gemm_mma_kernel<0,1,1><<<gFF1, 256, GEMM_SMEM>>>(dX1hi, dX1lo, dW1hi, dW1lo, b1, nullptr, HIDhi, HIDlo, DFFN, DMODEL);
    gemm_mma_kernel<1,0,0><<<gProj, 256, GEMM_SMEM>>>(dHIDhi, dHIDlo, dW2hi, dW2lo, b2, M, nullptr, nullptr, DMODEL, DFFN);
    add_ln_kernel<0><<<NTOK, 256>>>(M, X1, ln2g, ln2b, out, nullptr, nullptr);
}

// round 13
// speedup vs baseline: 1.6693x; 1.3609x over previous
#include <cuda_runtime.h>
#include <cuda.h>
#include <cuda_bf16.h>
#include <cuda_fp16.h>
#include <cstdint>

#define SLEN 2048
#define BATCH 4
#define DMODEL 1024
#define NHEAD 16
#define DKH 64
#define DFFN 4096
#define NTOK (SLEN*BATCH)   // 8192
#define LN_EPS 1e-5f
#define QSCALE 0.18033688011112042f   // 0.125 * log2(e)

// ---------------- scratch (device globals) ----------------------------------
__device__ __align__(1024) float g_Y[NTOK*DMODEL];
__device__ __align__(1024) float g_X1[NTOK*DMODEL];
__device__ __align__(1024) float g_M[NTOK*DMODEL];

// fp16 GEMM operands
__device__ __align__(1024) __half g_Xf[NTOK*DMODEL];
__device__ __align__(1024) __half g_X1f[NTOK*DMODEL];
__device__ __align__(1024) __half g_CTXf[NTOK*DMODEL];
__device__ __align__(1024) __half g_HIDf[NTOK*DFFN];
__device__ __align__(1024) __half g_WQKVh[3*DMODEL*DMODEL], g_WQKVl[3*DMODEL*DMODEL];
__device__ __align__(1024) __half g_WOh[DMODEL*DMODEL], g_WOl[DMODEL*DMODEL];
__device__ __align__(1024) __half g_W1h[DFFN*DMODEL],   g_W1l[DFFN*DMODEL];
__device__ __align__(1024) __half g_W2h[DMODEL*DFFN],   g_W2l[DMODEL*DFFN];

// bf16 attention operands
__device__ __align__(1024) __nv_bfloat16 g_Q[NTOK*DMODEL];
__device__ __align__(1024) __nv_bfloat16 g_K[NTOK*DMODEL];
__device__ __align__(1024) __nv_bfloat16 g_V[NTOK*DMODEL];
__device__ __align__(1024) __nv_bfloat16 g_VT[NTOK*DMODEL];

// ---------------- PTX helpers (base-ISA only) --------------------------------
__device__ __forceinline__ uint32_t smem_to_u32(const void* p) {
    uint32_t a;
    asm("{ .reg .u64 t; cvta.to.shared.u64 t, %1; cvt.u32.u64 %0, t; }" : "=r"(a) : "l"(p));
    return a;
}
#define MBARRIER_INIT(mbar, cnt) \
    asm volatile("mbarrier.init.shared.b64 [%0], %1;" :: "r"((uint32_t)(mbar)), "r"((uint32_t)(cnt)) : "memory")
#define MBARRIER_EXPECT_TX(mbar, bytes) \
    asm volatile("mbarrier.arrive.expect_tx.shared.b64 _, [%0], %1;" :: "r"((uint32_t)(mbar)), "r"((uint32_t)(bytes)) : "memory")
#define MBARRIER_ARRIVE(mbar) \
    asm volatile("mbarrier.arrive.shared.b64 _, [%0];" :: "r"((uint32_t)(mbar)) : "memory")
#define FENCE_ASYNC_SHARED() asm volatile("fence.proxy.async.shared::cta;" ::: "memory")

#define MBARRIER_WAIT_PARITY(mbar_smem_addr, phase_parity) do { \
    uint32_t _mbar = (uint32_t)(mbar_smem_addr); \
    uint32_t _parity = (uint32_t)(phase_parity); \
    uint32_t _done; \
    asm volatile("{ .reg .pred p; mbarrier.try_wait.parity.acquire.cta.shared::cta.b64 p, [%1], %2; selp.b32 %0, 1, 0, p; }" \
        : "=r"(_done) : "r"(_mbar), "r"(_parity) : "memory"); \
    if (!_done) { \
        asm volatile("{ .reg .pred P1; WAIT_LOOP_%=: mbarrier.try_wait.parity.acquire.cta.shared::cta.b64 P1, [%0], %1, 0x989680; @P1 bra.uni WAIT_DONE_%=; bra.uni WAIT_LOOP_%=; WAIT_DONE_%=: }" \
            :: "r"(_mbar), "r"(_parity) : "memory"); \
    } \
} while(0)

__device__ __forceinline__ void tma_load_2d(uint32_t dst_smem, const CUtensorMap* m,
                                            int x, int y, uint32_t mbar) {
    asm volatile(
        "cp.async.bulk.tensor.2d.shared::cta.global.tile.mbarrier::complete_tx::bytes "
        "[%0], [%1, {%2, %3}], [%4];"
        :: "r"(dst_smem), "l"(m), "r"(x), "r"(y), "r"(mbar) : "memory");
}

__device__ __forceinline__ void mma_bf16(float* d, const uint32_t* a, const uint32_t* b) {
    asm volatile(
        "mma.sync.aligned.m16n8k16.row.col.f32.bf16.bf16.f32 "
        "{%0,%1,%2,%3},{%4,%5,%6,%7},{%8,%9},{%0,%1,%2,%3};"
        : "+f"(d[0]), "+f"(d[1]), "+f"(d[2]), "+f"(d[3])
        : "r"(a[0]), "r"(a[1]), "r"(a[2]), "r"(a[3]), "r"(b[0]), "r"(b[1]));
}
__device__ __forceinline__ void mma_f16(float* d, const uint32_t* a, const uint32_t* b) {
    asm volatile(
        "mma.sync.aligned.m16n8k16.row.col.f32.f16.f16.f32 "
        "{%0,%1,%2,%3},{%4,%5,%6,%7},{%8,%9},{%0,%1,%2,%3};"
        : "+f"(d[0]), "+f"(d[1]), "+f"(d[2]), "+f"(d[3])
        : "r"(a[0]), "r"(a[1]), "r"(a[2]), "r"(a[3]), "r"(b[0]), "r"(b[1]));
}

__device__ __forceinline__ void ldsm_x4(uint32_t* r, uint32_t addr) {
    asm volatile("ldmatrix.sync.aligned.m8n8.x4.shared.b16 {%0,%1,%2,%3}, [%4];"
        : "=r"(r[0]), "=r"(r[1]), "=r"(r[2]), "=r"(r[3]) : "r"(addr));
}

__device__ __forceinline__ float ex2f(float x) {
    float y; asm("ex2.approx.f32 %0, %1;" : "=f"(y) : "f"(x)); return y;
}

// bf16 pair packers (attention path)
__device__ __forceinline__ uint32_t rn_pack2_bf16(float a, float b) {
    uint32_t r;
    asm("cvt.rn.bf16x2.f32 %0, %1, %2;" : "=r"(r) : "f"(b), "f"(a));
    return r;
}
// fp16 pair packers (GEMM path)
__device__ __forceinline__ uint32_t rn_pack2_f16(float a, float b) {
    __half2 h = __floats2half2_rn(a, b);
    return *(uint32_t*)&h;
}
__device__ __forceinline__ void f16_split2(float a, float b, uint32_t& hi, uint32_t& lo) {
    __half ha = __float2half_rn(a), hb = __float2half_rn(b);
    __half la = __float2half_rn(a - __half2float(ha));
    __half lb = __float2half_rn(b - __half2float(hb));
    __half2 ph = {ha, hb}, pl = {la, lb};
    hi = *(uint32_t*)&ph; lo = *(uint32_t*)&pl;
}

// ---------------- fused fp32 -> fp16 hi(/lo) convert (multi-segment) ---------
#define CVT_SEGS 7
#define CVT_CHUNK 512
struct CvtArgs {
    const float* src[CVT_SEGS];
    __half* hi[CVT_SEGS];
    __half* lo[CVT_SEGS];        // null -> 1-term RN only
    int blk_end[CVT_SEGS];
    int n4[CVT_SEGS];
};

__global__ void __launch_bounds__(256) cvt_multi_kernel(const __grid_constant__ CvtArgs a)
{
    int seg = 0;
#pragma unroll
    for (int k = 0; k < CVT_SEGS - 1; k++)
        if (blockIdx.x >= (unsigned)a.blk_end[k]) seg = k + 1;
    const int local = blockIdx.x - (seg ? a.blk_end[seg - 1] : 0);
    const float* src = a.src[seg];
    __half* hi = a.hi[seg];
    __half* lo = a.lo[seg];
    const int n4 = a.n4[seg];
#pragma unroll
    for (int p = 0; p < 2; p++) {
        int i = local * CVT_CHUNK + p * 256 + threadIdx.x;
        if (i < n4) {
            float4 v = ((const float4*)src)[i];
            uint2 uh, ul;
            f16_split2(v.x, v.y, uh.x, ul.x);
            f16_split2(v.z, v.w, uh.y, ul.y);
            ((uint2*)hi)[i] = uh;
            if (lo) ((uint2*)lo)[i] = ul;
        }
    }
}

// ---------------- fp16 2-MMA GEMM mainloop: 64x128 tile, occ 2 ---------------
// stage (40KB): A 8K | Bh 16K | Bl 16K. NPIPE=2 -> 80KB/CTA.
#define ST_A   0
#define ST_BHI 8192
#define ST_BLO 24576
#define ST_BYTES 40960
#define NPIPE 2
#define GEMM_SMEM (NPIPE*ST_BYTES + 64)

__device__ __forceinline__ void gemm_mainloop(
    const CUtensorMap* mA,
    const CUtensorMap* mBhi, const CUtensorMap* mBlo,
    int bm, int bn, int nst, char* smem, float acc[][4][4])
{
    const uint32_t sbase = smem_to_u32(smem);
    const uint32_t mbb = sbase + NPIPE * ST_BYTES;
    const int tid = threadIdx.x;
    const int wid = tid >> 5;
    const int lane = tid & 31;
    const int wm = wid & 1;
    const int wn = wid >> 1;

    if (tid == 0) {
#pragma unroll
        for (int i = 0; i < NPIPE; i++) {
            MBARRIER_INIT(mbb + i * 8, 1);        // full
            MBARRIER_INIT(mbb + 16 + i * 8, 8);   // empty (8 warps)
        }
    }
    FENCE_ASYNC_SHARED();
    __syncthreads();

    if (tid == 0) {
#pragma unroll
        for (int s = 0; s < NPIPE; s++) {
            uint32_t mb = mbb + s * 8;
            uint32_t dst = sbase + s * ST_BYTES;
            MBARRIER_EXPECT_TX(mb, ST_BYTES);
            tma_load_2d(dst + ST_A,   mA,   s * 64, bm, mb);
            tma_load_2d(dst + ST_BHI, mBhi, s * 64, bn, mb);
            tma_load_2d(dst + ST_BLO, mBlo, s * 64, bn, mb);
        }
    }

    const uint32_t m16 = (lane & 7) * 16;
    const int rA = (lane & 7) + ((lane >> 3) & 1) * 8;
    const uint32_t hA = ((lane >> 4) & 1) * 16;
    const int rB = (lane & 7) + ((lane >> 4) & 1) * 8;
    const uint32_t hB = ((lane >> 3) & 1) * 16;
    uint32_t aoff[2], boff[2];
#pragma unroll
    for (int t = 0; t < 2; t++) aoff[t] = (uint32_t)(wm * 32 + t * 16 + rA) * 128;
#pragma unroll
    for (int jp = 0; jp < 2; jp++) boff[jp] = (uint32_t)(wn * 32 + jp * 16 + rB) * 128;

    int buf = 0, ph = 0;
    for (int s = 0; s < nst; s++) {
        MBARRIER_WAIT_PARITY(mbb + buf * 8, ph);
        const uint32_t sb = sbase + buf * ST_BYTES;

#pragma unroll
        for (int ks = 0; ks < 4; ks++) {
            const uint32_t cA = (ks * 32 + hA) ^ m16;
            const uint32_t cB = (ks * 32 + hB) ^ m16;
            uint32_t av[2][4];
#pragma unroll
            for (int t = 0; t < 2; t++)
                ldsm_x4(av[t], sb + ST_A + aoff[t] + cA);
            uint32_t bh[2][4], bl[2][4];
#pragma unroll
            for (int jp = 0; jp < 2; jp++) {
                ldsm_x4(bh[jp], sb + ST_BHI + boff[jp] + cB);
                ldsm_x4(bl[jp], sb + ST_BLO + boff[jp] + cB);
            }
#pragma unroll
            for (int t = 0; t < 2; t++)
#pragma unroll
                for (int jp = 0; jp < 2; jp++) {
                    mma_f16(acc[t][2*jp],   av[t], &bh[jp][0]);
                    mma_f16(acc[t][2*jp],   av[t], &bl[jp][0]);
                    mma_f16(acc[t][2*jp+1], av[t], &bh[jp][2]);
                    mma_f16(acc[t][2*jp+1], av[t], &bl[jp][2]);
                }
        }

        if (lane == 0) MBARRIER_ARRIVE(mbb + 16 + buf * 8);
        if (tid == 0 && s + NPIPE < nst) {
            MBARRIER_WAIT_PARITY(mbb + 16 + buf * 8, ph);
            uint32_t mb = mbb + buf * 8;
            uint32_t dst = sbase + buf * ST_BYTES;
            MBARRIER_EXPECT_TX(mb, ST_BYTES);
            tma_load_2d(dst + ST_A,   mA,   (s + NPIPE) * 64, bm, mb);
            tma_load_2d(dst + ST_BHI, mBhi, (s + NPIPE) * 64, bn, mb);
            tma_load_2d(dst + ST_BLO, mBlo, (s + NPIPE) * 64, bn, mb);
        }
        if (++buf == NPIPE) { buf = 0; ph ^= 1; }
    }
}

// ---------------- generic GEMM kernel (64x128 out per CTA) -------------------
template<int WRITE_F32, int WRITE_F16, int RELU>
__global__ void __launch_bounds__(256, 2) gemm_mma_kernel(
    const __grid_constant__ CUtensorMap mA,
    const __grid_constant__ CUtensorMap mBhi,
    const __grid_constant__ CUtensorMap mBlo,
    const float* __restrict__ bias,
    float* __restrict__ C, __half* __restrict__ Cf,
    int N, int K)
{
    extern __shared__ char smem[];
    const int bm = blockIdx.y * 64;
    const int bn = blockIdx.x * 128;
    float acc[2][4][4];
#pragma unroll
    for (int t = 0; t < 2; t++)
#pragma unroll
        for (int j = 0; j < 4; j++)
#pragma unroll
            for (int q = 0; q < 4; q++) acc[t][j][q] = 0.f;

    gemm_mainloop(&mA, &mBhi, &mBlo, bm, bn, K >> 6, smem, acc);

    const int lane = threadIdx.x & 31;
    const int wid = threadIdx.x >> 5;
    const int g = lane >> 2, tq = lane & 3;
    const int wm = wid & 1, wn = wid >> 1;
#pragma unroll
    for (int t = 0; t < 2; t++) {
        int row = bm + wm * 32 + t * 16 + g;
#pragma unroll
        for (int j = 0; j < 4; j++) {
            int col = bn + wn * 32 + j * 8 + tq * 2;
            float2 bj = *(const float2*)&bias[col];
            float v0 = acc[t][j][0] + bj.x;
            float v1 = acc[t][j][1] + bj.y;
            float v2 = acc[t][j][2] + bj.x;
            float v3 = acc[t][j][3] + bj.y;
            if (RELU) {
                v0 = fmaxf(v0, 0.f); v1 = fmaxf(v1, 0.f);
                v2 = fmaxf(v2, 0.f); v3 = fmaxf(v3, 0.f);
            }
            if (WRITE_F32) {
                *(float2*)&C[(size_t)row * N + col]       = make_float2(v0, v1);
                *(float2*)&C[(size_t)(row + 8) * N + col] = make_float2(v2, v3);
            }
            if (WRITE_F16) {
                *(uint32_t*)&Cf[(size_t)row * N + col]       = rn_pack2_f16(v0, v1);
                *(uint32_t*)&Cf[(size_t)(row + 8) * N + col] = rn_pack2_f16(v2, v3);
            }
        }
    }
}

// ---------------- fused QKV GEMM: outputs RN bf16 (attention operands) -------
__global__ void __launch_bounds__(256, 2) gemm_qkv_kernel(
    const __grid_constant__ CUtensorMap mA,
    const __grid_constant__ CUtensorMap mBhi,
    const __grid_constant__ CUtensorMap mBlo,
    const float* __restrict__ bQ, const float* __restrict__ bK, const float* __restrict__ bV,
    __nv_bfloat16* __restrict__ Q, __nv_bfloat16* __restrict__ K,
    __nv_bfloat16* __restrict__ V)
{
    extern __shared__ char smem[];
    const int bm = blockIdx.y * 64;
    const int bn = blockIdx.x * 128;
    float acc[2][4][4];
#pragma unroll
    for (int t = 0; t < 2; t++)
#pragma unroll
        for (int j = 0; j < 4; j++)
#pragma unroll
            for (int q = 0; q < 4; q++) acc[t][j][q] = 0.f;

    gemm_mainloop(&mA, &mBhi, &mBlo, bm, bn, DMODEL >> 6, smem, acc);

    const int part = blockIdx.x >> 3;          // 0=Q 1=K 2=V
    const int nb = (blockIdx.x & 7) * 128;
    const float* bias = (part == 0) ? bQ : (part == 1) ? bK : bV;
    __nv_bfloat16* O = (part == 0) ? Q : (part == 1) ? K : V;
    const float scl = (part == 0) ? QSCALE : 1.0f;

    const int lane = threadIdx.x & 31;
    const int wid = threadIdx.x >> 5;
    const int g = lane >> 2, tq = lane & 3;
    const int wm = wid & 1, wn = wid >> 1;
#pragma unroll
    for (int t = 0; t < 2; t++) {
        int row = bm + wm * 32 + t * 16 + g;
#pragma unroll
        for (int j = 0; j < 4; j++) {
            int col = nb + wn * 32 + j * 8 + tq * 2;
            float2 bj = *(const float2*)&bias[col];
            float v0 = (acc[t][j][0] + bj.x) * scl;
            float v1 = (acc[t][j][1] + bj.y) * scl;
            float v2 = (acc[t][j][2] + bj.x) * scl;
            float v3 = (acc[t][j][3] + bj.y) * scl;
            *(uint32_t*)&O[(size_t)row * DMODEL + col]       = rn_pack2_bf16(v0, v1);
            *(uint32_t*)&O[(size_t)(row + 8) * DMODEL + col] = rn_pack2_bf16(v2, v3);
        }
    }
}

// ---------------- V transpose: V[s*4+b][d] -> VT[(b*DM+d)][s] -----------------
__global__ void __launch_bounds__(256) transpose_v_kernel(
    const __nv_bfloat16* __restrict__ V, __nv_bfloat16* __restrict__ VT)
{
    __shared__ __nv_bfloat16 sh[32][64 + 4];
    const int tid = threadIdx.x;
    const int s0 = blockIdx.x * 32;
    const int d0 = blockIdx.y * 64;
    const int b  = blockIdx.z;

#pragma unroll
    for (int p = 0; p < 2; p++) {
        int idx = tid + p * 256;
        int srow = idx >> 4;
        int dq = idx & 15;
        size_t ga = ((size_t)(s0 + srow) * BATCH + b) * DMODEL + d0 + dq * 4;
        *(uint2*)&sh[srow][dq * 4] = *(const uint2*)(V + ga);
    }
    __syncthreads();
#pragma unroll
    for (int p = 0; p < 2; p++) {
        int idx = tid + p * 256;
        int drow = idx >> 3;
        int sq = idx & 7;
        __nv_bfloat16 oh[4];
#pragma unroll
        for (int k = 0; k < 4; k++) oh[k] = sh[sq * 4 + k][drow];
        size_t ga = ((size_t)(b * DMODEL + d0 + drow)) * SLEN + s0 + sq * 4;
        *(uint2*)(VT + ga) = *(uint2*)oh;
    }
}

// ---------------- Flash attention (1-term RN bf16; ctx out = fp16) -----------
#define ATT_Q 0
#define ATT_ST0 16384
#define ATT_STSZ 16384
#define ATT_CTRL (ATT_ST0 + 2*ATT_STSZ)
#define ATT_SMEM (ATT_CTRL + 64)
#define NKT (SLEN/64)

__global__ void __launch_bounds__(256, 2) attn_mma_kernel(
    const __grid_constant__ CUtensorMap mQ,
    const __grid_constant__ CUtensorMap mK,
    const __grid_constant__ CUtensorMap mV,
    __half* __restrict__ Of)
{
    extern __shared__ char smem[];
    const uint32_t sbase = smem_to_u32(smem);
    const uint32_t mbb = sbase + ATT_CTRL;
    const int tid = threadIdx.x;
    const int w = tid >> 5;
    const int lane = tid & 31;
    const int g = lane >> 2;
    const int t = lane & 3;
    const int q0 = blockIdx.x * 128;
    const int b = blockIdx.y >> 4;
    const int h = blockIdx.y & 15;
    const int xqk = b * DMODEL + h * 64;

    if (tid == 0) {
        MBARRIER_INIT(mbb + 0, 1);
        MBARRIER_INIT(mbb + 8, 1);
        MBARRIER_INIT(mbb + 16, 8);
        MBARRIER_INIT(mbb + 24, 8);
    }
    FENCE_ASYNC_SHARED();
    __syncthreads();

    if (tid == 0) {
        MBARRIER_EXPECT_TX(mbb + 0, ATT_STSZ + 16384);
        tma_load_2d(sbase + ATT_Q, &mQ, xqk, q0, mbb + 0);
        tma_load_2d(sbase + ATT_ST0 + 0,    &mK, xqk, 0, mbb + 0);
        tma_load_2d(sbase + ATT_ST0 + 8192, &mV, 0, xqk, mbb + 0);
        MBARRIER_EXPECT_TX(mbb + 8, ATT_STSZ);
        tma_load_2d(sbase + ATT_ST0 + ATT_STSZ + 0,    &mK, xqk, 64, mbb + 8);
        tma_load_2d(sbase + ATT_ST0 + ATT_STSZ + 8192, &mV, 64, xqk, mbb + 8);
    }

    const uint32_t m16 = (lane & 7) * 16;
    const int rA = (lane & 7) + ((lane >> 3) & 1) * 8;
    const uint32_t hA = ((lane >> 4) & 1) * 16;
    const int rB = (lane & 7) + ((lane >> 4) & 1) * 8;
    const uint32_t hB = ((lane >> 3) & 1) * 16;
    const uint32_t qoff = (uint32_t)(w * 16 + rA) * 128;
    uint32_t kvoff[4];
#pragma unroll
    for (int jp = 0; jp < 4; jp++) kvoff[jp] = (uint32_t)(jp * 16 + rB) * 128;

    float l_i[2] = {0.f, 0.f};
    float acc[8][4];
#pragma unroll
    for (int j = 0; j < 8; j++)
#pragma unroll
        for (int q = 0; q < 4; q++) acc[j][q] = 0.f;

    for (int s = 0; s < NKT; s++) {
        const int buf = s & 1;
        const int ph = (s >> 1) & 1;
        MBARRIER_WAIT_PARITY(mbb + buf * 8, ph);
        const uint32_t Kbu = sbase + ATT_ST0 + buf * ATT_STSZ;
        const uint32_t Vbu = Kbu + 8192;

        float sc[8][4];
#pragma unroll
        for (int j = 0; j < 8; j++)
#pragma unroll
            for (int q = 0; q < 4; q++) sc[j][q] = 0.f;

#pragma unroll
        for (int ks = 0; ks < 4; ks++) {
            const uint32_t cA = (ks * 32 + hA) ^ m16;
            const uint32_t cB = (ks * 32 + hB) ^ m16;
            uint32_t qh[4];
            ldsm_x4(qh, sbase + ATT_Q + qoff + cA);
#pragma unroll
            for (int jp = 0; jp < 4; jp++) {
                uint32_t kh[4];
                ldsm_x4(kh, Kbu + kvoff[jp] + cB);
                mma_bf16(sc[2*jp],   qh, &kh[0]);
                mma_bf16(sc[2*jp+1], qh, &kh[2]);
            }
        }

        float s0 = 0.f, s1 = 0.f;
#pragma unroll
        for (int j = 0; j < 8; j++) {
            sc[j][0] = ex2f(sc[j][0]);
            sc[j][1] = ex2f(sc[j][1]);
            sc[j][2] = ex2f(sc[j][2]);
            sc[j][3] = ex2f(sc[j][3]);
            s0 += sc[j][0] + sc[j][1];
            s1 += sc[j][2] + sc[j][3];
        }
        l_i[0] += s0;
        l_i[1] += s1;

#pragma unroll
        for (int ks = 0; ks < 4; ks++) {
            uint32_t pah[4];
            pah[0] = rn_pack2_bf16(sc[2*ks][0],   sc[2*ks][1]);
            pah[1] = rn_pack2_bf16(sc[2*ks][2],   sc[2*ks][3]);
            pah[2] = rn_pack2_bf16(sc[2*ks+1][0], sc[2*ks+1][1]);
            pah[3] = rn_pack2_bf16(sc[2*ks+1][2], sc[2*ks+1][3]);
            const uint32_t cB = (ks * 32 + hB) ^ m16;
#pragma unroll
            for (int jp = 0; jp < 4; jp++) {
                uint32_t vh[4];
                ldsm_x4(vh, Vbu + kvoff[jp] + cB);
                mma_bf16(acc[2*jp],   pah, &vh[0]);
                mma_bf16(acc[2*jp+1], pah, &vh[2]);
            }
        }

        if (lane == 0) MBARRIER_ARRIVE(mbb + 16 + buf * 8);
        if (tid == 0 && s + 2 < NKT) {
            MBARRIER_WAIT_PARITY(mbb + 16 + buf * 8, ph);
            uint32_t mb = mbb + buf * 8;
            uint32_t dst = sbase + ATT_ST0 + buf * ATT_STSZ;
            MBARRIER_EXPECT_TX(mb, ATT_STSZ);
            tma_load_2d(dst + 0,    &mK, xqk, (s + 2) * 64, mb);
            tma_load_2d(dst + 8192, &mV, (s + 2) * 64, xqk, mb);
        }
    }

    float l0 = l_i[0], l1 = l_i[1];
    l0 += __shfl_xor_sync(0xffffffffu, l0, 1);
    l0 += __shfl_xor_sync(0xffffffffu, l0, 2);
    l1 += __shfl_xor_sync(0xffffffffu, l1, 1);
    l1 += __shfl_xor_sync(0xffffffffu, l1, 2);

    const float inv0 = 1.0f / l0;
    const float inv1 = 1.0f / l1;
    const int row0 = q0 + w * 16 + g;
    const int row1 = row0 + 8;
    const size_t tok0 = (size_t)row0 * BATCH + b;
    const size_t tok1 = (size_t)row1 * BATCH + b;
#pragma unroll
    for (int j = 0; j < 8; j++) {
        const int col = h * 64 + j * 8 + t * 2;
        *(uint32_t*)&Of[tok0 * DMODEL + col] = rn_pack2_f16(acc[j][0] * inv0, acc[j][1] * inv0);
        *(uint32_t*)&Of[tok1 * DMODEL + col] = rn_pack2_f16(acc[j][2] * inv1, acc[j][3] * inv1);
    }
}

// ---------------- fused residual add + LayerNorm -----------------------------
template<int F16OUT>
__global__ void __launch_bounds__(256) add_ln_kernel(
    const float* __restrict__ A, const float* __restrict__ R,
    const float* __restrict__ gam, const float* __restrict__ bet,
    float* __restrict__ out, __half* __restrict__ Of)
{
    __shared__ float red_s[8];
    __shared__ float red_ss[8];
    __shared__ float s_mu, s_rstd;
    const int row = blockIdx.x;
    const int t = threadIdx.x;
    float4 v = ((const float4*)(A + (size_t)row * DMODEL))[t];
    float4 w = ((const float4*)(R + (size_t)row * DMODEL))[t];
    v.x += w.x; v.y += w.y; v.z += w.z; v.w += w.w;
    float s = v.x + v.y + v.z + v.w;
    float ss = v.x * v.x + v.y * v.y + v.z * v.z + v.w * v.w;
#pragma unroll
    for (int off = 16; off >= 1; off >>= 1) {
        s  += __shfl_xor_sync(0xffffffffu, s, off);
        ss += __shfl_xor_sync(0xffffffffu, ss, off);
    }
    if ((t & 31) == 0) { red_s[t >> 5] = s; red_ss[t >> 5] = ss; }
    __syncthreads();
    if (t == 0) {
        float ts = 0.f, tss = 0.f;
#pragma unroll
        for (int i = 0; i < 8; i++) { ts += red_s[i]; tss += red_ss[i]; }
        float mu = ts * (1.0f / DMODEL);
        float var = tss * (1.0f / DMODEL) - mu * mu;
        s_mu = mu;
        s_rstd = rsqrtf(var + LN_EPS);
    }
    __syncthreads();
    float mu = s_mu, rs = s_rstd;
    float4 g = ((const float4*)gam)[t], bb = ((const float4*)bet)[t];
    float4 o;
    o.x = (v.x - mu) * rs * g.x + bb.x;
    o.y = (v.y - mu) * rs * g.y + bb.y;
    o.z = (v.z - mu) * rs * g.z + bb.z;
    o.w = (v.w - mu) * rs * g.w + bb.w;
    ((float4*)(out + (size_t)row * DMODEL))[t] = o;
    if (F16OUT) {
        uint2 u;
        u.x = rn_pack2_f16(o.x, o.y);
        u.y = rn_pack2_f16(o.z, o.w);
        ((uint2*)(Of + (size_t)row * DMODEL))[t] = u;
    }
}

// ---------------- host: tensormap + launch ------------------------------------
typedef CUresult (*EncodeFn)(
    CUtensorMap*, CUtensorMapDataType, cuuint32_t, void*,
    const cuuint64_t*, const cuuint64_t*, const cuuint32_t*, const cuuint32_t*,
    CUtensorMapInterleave, CUtensorMapSwizzle, CUtensorMapL2promotion,
    CUtensorMapFloatOOBfill);

static void make_desc(EncodeFn enc, CUtensorMap* out, void* ptr,
                      uint64_t rows, uint64_t K, uint32_t box1,
                      CUtensorMapDataType dt)
{
    cuuint64_t dims[2]    = {K, rows};
    cuuint64_t strides[1] = {K * 2};
    cuuint32_t box[2]     = {64, box1};
    cuuint32_t estr[2]    = {1, 1};
    enc(out, dt, 2, ptr, dims, strides, box, estr,
        CU_TENSOR_MAP_INTERLEAVE_NONE, CU_TENSOR_MAP_SWIZZLE_128B,
        CU_TENSOR_MAP_L2_PROMOTION_L2_128B, CU_TENSOR_MAP_FLOAT_OOB_FILL_NONE);
}

extern "C" void kernel_launch(void* const* d_in, const int* in_sizes, int n_in,
                              void* d_out, int out_size)
{
    const float* X    = (const float*)d_in[0];
    const float* WQw  = (const float*)d_in[1];
    const float* WQb  = (const float*)d_in[2];
    const float* WKw  = (const float*)d_in[3];
    const float* WKb  = (const float*)d_in[4];
    const float* WVw  = (const float*)d_in[5];
    const float* WVb  = (const float*)d_in[6];
    const float* WOw  = (const float*)d_in[7];
    const float* WOb  = (const float*)d_in[8];
    const float* ln1g = (const float*)d_in[9];
    const float* ln1b = (const float*)d_in[10];
    const float* W1   = (const float*)d_in[11];
    const float* b1   = (const float*)d_in[12];
    const float* W2   = (const float*)d_in[13];
    const float* b2   = (const float*)d_in[14];
    const float* ln2g = (const float*)d_in[15];
    const float* ln2b = (const float*)d_in[16];
    float* out = (float*)d_out;

    float *Y, *X1, *M;
    cudaGetSymbolAddress((void**)&Y,  g_Y);
    cudaGetSymbolAddress((void**)&X1, g_X1);
    cudaGetSymbolAddress((void**)&M,  g_M);

    __half *Xf,*X1f,*CTXf,*HIDf;
    __half *WQKVh,*WQKVl,*WOh,*WOl,*W1h,*W1l,*W2h,*W2l;
    __nv_bfloat16 *Q,*K,*V,*VT;
    cudaGetSymbolAddress((void**)&Xf,   g_Xf);
    cudaGetSymbolAddress((void**)&X1f,  g_X1f);
    cudaGetSymbolAddress((void**)&CTXf, g_CTXf);
    cudaGetSymbolAddress((void**)&HIDf, g_HIDf);
    cudaGetSymbolAddress((void**)&WQKVh, g_WQKVh); cudaGetSymbolAddress((void**)&WQKVl, g_WQKVl);
    cudaGetSymbolAddress((void**)&WOh, g_WOh); cudaGetSymbolAddress((void**)&WOl, g_WOl);
    cudaGetSymbolAddress((void**)&W1h, g_W1h); cudaGetSymbolAddress((void**)&W1l, g_W1l);
    cudaGetSymbolAddress((void**)&W2h, g_W2h); cudaGetSymbolAddress((void**)&W2l, g_W2l);
    cudaGetSymbolAddress((void**)&Q,  g_Q);
    cudaGetSymbolAddress((void**)&K,  g_K);
    cudaGetSymbolAddress((void**)&V,  g_V);
    cudaGetSymbolAddress((void**)&VT, g_VT);

    EncodeFn enc = nullptr;
    {
        void* fp = nullptr;
        cudaDriverEntryPointQueryResult qr;
        cudaGetDriverEntryPoint("cuTensorMapEncodeTiled", &fp, cudaEnableDefault, &qr);
        enc = (EncodeFn)fp;
    }

    const CUtensorMapDataType F16 = CU_TENSOR_MAP_DATA_TYPE_FLOAT16;
    const CUtensorMapDataType BF16 = CU_TENSOR_MAP_DATA_TYPE_BFLOAT16;

    CUtensorMap dXf, dWQKVh, dWQKVl, dCTXf, dWOh, dWOl;
    CUtensorMap dX1f, dW1h, dW1l, dHIDf, dW2h, dW2l;
    make_desc(enc, &dXf,  Xf,  NTOK, DMODEL, 64, F16);
    make_desc(enc, &dWQKVh, WQKVh, 3*DMODEL, DMODEL, 128, F16);
    make_desc(enc, &dWQKVl, WQKVl, 3*DMODEL, DMODEL, 128, F16);
    make_desc(enc, &dCTXf, CTXf, NTOK, DMODEL, 64, F16);
    make_desc(enc, &dWOh, WOh, DMODEL, DMODEL, 128, F16);
    make_desc(enc, &dWOl, WOl, DMODEL, DMODEL, 128, F16);
    make_desc(enc, &dX1f, X1f, NTOK, DMODEL, 64, F16);
    make_desc(enc, &dW1h, W1h, DFFN, DMODEL, 128, F16);
    make_desc(enc, &dW1l, W1l, DFFN, DMODEL, 128, F16);
    make_desc(enc, &dHIDf, HIDf, NTOK, DFFN, 64, F16);
    make_desc(enc, &dW2h, W2h, DMODEL, DFFN, 128, F16);
    make_desc(enc, &dW2l, W2l, DMODEL, DFFN, 128, F16);

    CUtensorMap dQ, dK, dVT;
    make_desc(enc, &dQ, Q, SLEN, BATCH*DMODEL, 128, BF16);
    make_desc(enc, &dK, K, SLEN, BATCH*DMODEL, 64, BF16);
    make_desc(enc, &dVT, VT, BATCH*DMODEL, SLEN, 64, BF16);

    cudaFuncSetAttribute(gemm_mma_kernel<1,0,0>, cudaFuncAttributeMaxDynamicSharedMemorySize, GEMM_SMEM);
    cudaFuncSetAttribute(gemm_mma_kernel<0,1,1>, cudaFuncAttributeMaxDynamicSharedMemorySize, GEMM_SMEM);
    cudaFuncSetAttribute(gemm_qkv_kernel, cudaFuncAttributeMaxDynamicSharedMemorySize, GEMM_SMEM);
    cudaFuncSetAttribute(attn_mma_kernel, cudaFuncAttributeMaxDynamicSharedMemorySize, ATT_SMEM);

    // ---- fused fp32 -> fp16 converts: X 1-term RN, weights 2-term ----
    {
        CvtArgs a;
        const float* srcs[CVT_SEGS] = {X, WQw, WKw, WVw, WOw, W1, W2};
        __half* his[CVT_SEGS] = {Xf, WQKVh, WQKVh + DMODEL*DMODEL,
                                 WQKVh + 2*DMODEL*DMODEL, WOh, W1h, W2h};
        __half* los[CVT_SEGS] = {nullptr, WQKVl, WQKVl + DMODEL*DMODEL,
                                 WQKVl + 2*DMODEL*DMODEL, WOl, W1l, W2l};
        int n4s[CVT_SEGS] = {NTOK*DMODEL/4, DMODEL*DMODEL/4, DMODEL*DMODEL/4,
                             DMODEL*DMODEL/4, DMODEL*DMODEL/4, DFFN*DMODEL/4, DMODEL*DFFN/4};
        int cum = 0;
        for (int i = 0; i < CVT_SEGS; i++) {
            a.src[i] = srcs[i]; a.hi[i] = his[i]; a.lo[i] = los[i]; a.n4[i] = n4s[i];
            cum += (n4s[i] + CVT_CHUNK - 1) / CVT_CHUNK;
            a.blk_end[i] = cum;
        }
        cvt_multi_kernel<<<cum, 256>>>(a);
    }

    dim3 gProj(DMODEL / 128, NTOK / 64);    // 8 x 128
    dim3 gQKV(3 * DMODEL / 128, NTOK / 64); // 24 x 128
    dim3 gFF1(DFFN / 128, NTOK / 64);       // 32 x 128

    // ---- fused QKV projection (Q pre-scaled; RN bf16 out) ----
    gemm_qkv_kernel<<<gQKV, 256, GEMM_SMEM>>>(dXf, dWQKVh, dWQKVl,
        WQb, WKb, WVb, Q, K, V);

    // ---- V transpose for PV operand ----
    transpose_v_kernel<<<dim3(SLEN/32, DMODEL/64, BATCH), 256>>>(V, VT);

    // ---- attention (bf16 1-term, ctx out fp16) ----
    attn_mma_kernel<<<dim3(SLEN/128, BATCH*NHEAD), 256, ATT_SMEM>>>(
        dQ, dK, dVT, CTXf);

    // ---- output projection + residual LN1 ----
    gemm_mma_kernel<1,0,0><<<gProj, 256, GEMM_SMEM>>>(dCTXf, dWOh, dWOl, WOb, Y, nullptr, DMODEL, DMODEL);
    add_ln_kernel<1><<<NTOK, 256>>>(Y, X, ln1g, ln1b, X1, X1f);

    // ---- MLP ----
    gemm_mma_kernel<0,1,1><<<gFF1, 256, GEMM_SMEM>>>(dX1f, dW1h, dW1l, b1, nullptr, HIDf, DFFN, DMODEL);
    gemm_mma_kernel<1,0,0><<<gProj, 256, GEMM_SMEM>>>(dHIDf, dW2h, dW2l, b2, M, nullptr, DMODEL, DFFN);
    add_ln_kernel<0><<<NTOK, 256>>>(M, X1, ln2g, ln2b, out, nullptr);
}

// round 14
// speedup vs baseline: 2.4392x; 1.4612x over previous
#include <cuda_runtime.h>
#include <cuda.h>
#include <cuda_bf16.h>
#include <cuda_fp16.h>
#include <cstdint>

#define SLEN 2048
#define BATCH 4
#define DMODEL 1024
#define NHEAD 16
#define DKH 64
#define DFFN 4096
#define NTOK (SLEN*BATCH)   // 8192
#define LN_EPS 1e-5f
#define QSCALE 0.18033688011112042f   // 0.125 * log2(e)

// ---------------- scratch (device globals) ----------------------------------
__device__ __align__(1024) float g_Y[NTOK*DMODEL];
__device__ __align__(1024) float g_X1[NTOK*DMODEL];
__device__ __align__(1024) float g_M[NTOK*DMODEL];

// fp16 GEMM operands (all 1-term RN)
__device__ __align__(1024) __half g_Xf[NTOK*DMODEL];
__device__ __align__(1024) __half g_X1f[NTOK*DMODEL];
__device__ __align__(1024) __half g_CTXf[NTOK*DMODEL];
__device__ __align__(1024) __half g_HIDf[NTOK*DFFN];
__device__ __align__(1024) __half g_WQKVf[3*DMODEL*DMODEL];
__device__ __align__(1024) __half g_WOf[DMODEL*DMODEL];
__device__ __align__(1024) __half g_W1f[DFFN*DMODEL];
__device__ __align__(1024) __half g_W2f[DMODEL*DFFN];

// bf16 attention operands
__device__ __align__(1024) __nv_bfloat16 g_Q[NTOK*DMODEL];
__device__ __align__(1024) __nv_bfloat16 g_K[NTOK*DMODEL];
__device__ __align__(1024) __nv_bfloat16 g_V[NTOK*DMODEL];
__device__ __align__(1024) __nv_bfloat16 g_VT[NTOK*DMODEL];

// ---------------- PTX helpers (base-ISA only) --------------------------------
__device__ __forceinline__ uint32_t smem_to_u32(const void* p) {
    uint32_t a;
    asm("{ .reg .u64 t; cvta.to.shared.u64 t, %1; cvt.u32.u64 %0, t; }" : "=r"(a) : "l"(p));
    return a;
}
#define MBARRIER_INIT(mbar, cnt) \
    asm volatile("mbarrier.init.shared.b64 [%0], %1;" :: "r"((uint32_t)(mbar)), "r"((uint32_t)(cnt)) : "memory")
#define MBARRIER_EXPECT_TX(mbar, bytes) \
    asm volatile("mbarrier.arrive.expect_tx.shared.b64 _, [%0], %1;" :: "r"((uint32_t)(mbar)), "r"((uint32_t)(bytes)) : "memory")
#define MBARRIER_ARRIVE(mbar) \
    asm volatile("mbarrier.arrive.shared.b64 _, [%0];" :: "r"((uint32_t)(mbar)) : "memory")
#define FENCE_ASYNC_SHARED() asm volatile("fence.proxy.async.shared::cta;" ::: "memory")

#define MBARRIER_WAIT_PARITY(mbar_smem_addr, phase_parity) do { \
    uint32_t _mbar = (uint32_t)(mbar_smem_addr); \
    uint32_t _parity = (uint32_t)(phase_parity); \
    uint32_t _done; \
    asm volatile("{ .reg .pred p; mbarrier.try_wait.parity.acquire.cta.shared::cta.b64 p, [%1], %2; selp.b32 %0, 1, 0, p; }" \
        : "=r"(_done) : "r"(_mbar), "r"(_parity) : "memory"); \
    if (!_done) { \
        asm volatile("{ .reg .pred P1; WAIT_LOOP_%=: mbarrier.try_wait.parity.acquire.cta.shared::cta.b64 P1, [%0], %1, 0x989680; @P1 bra.uni WAIT_DONE_%=; bra.uni WAIT_LOOP_%=; WAIT_DONE_%=: }" \
            :: "r"(_mbar), "r"(_parity) : "memory"); \
    } \
} while(0)

__device__ __forceinline__ void tma_load_2d(uint32_t dst_smem, const CUtensorMap* m,
                                            int x, int y, uint32_t mbar) {
    asm volatile(
        "cp.async.bulk.tensor.2d.shared::cta.global.tile.mbarrier::complete_tx::bytes "
        "[%0], [%1, {%2, %3}], [%4];"
        :: "r"(dst_smem), "l"(m), "r"(x), "r"(y), "r"(mbar) : "memory");
}

__device__ __forceinline__ void mma_bf16(float* d, const uint32_t* a, const uint32_t* b) {
    asm volatile(
        "mma.sync.aligned.m16n8k16.row.col.f32.bf16.bf16.f32 "
        "{%0,%1,%2,%3},{%4,%5,%6,%7},{%8,%9},{%0,%1,%2,%3};"
        : "+f"(d[0]), "+f"(d[1]), "+f"(d[2]), "+f"(d[3])
        : "r"(a[0]), "r"(a[1]), "r"(a[2]), "r"(a[3]), "r"(b[0]), "r"(b[1]));
}
__device__ __forceinline__ void mma_f16(float* d, const uint32_t* a, const uint32_t* b) {
    asm volatile(
        "mma.sync.aligned.m16n8k16.row.col.f32.f16.f16.f32 "
        "{%0,%1,%2,%3},{%4,%5,%6,%7},{%8,%9},{%0,%1,%2,%3};"
        : "+f"(d[0]), "+f"(d[1]), "+f"(d[2]), "+f"(d[3])
        : "r"(a[0]), "r"(a[1]), "r"(a[2]), "r"(a[3]), "r"(b[0]), "r"(b[1]));
}

__device__ __forceinline__ void ldsm_x4(uint32_t* r, uint32_t addr) {
    asm volatile("ldmatrix.sync.aligned.m8n8.x4.shared.b16 {%0,%1,%2,%3}, [%4];"
        : "=r"(r[0]), "=r"(r[1]), "=r"(r[2]), "=r"(r[3]) : "r"(addr));
}

__device__ __forceinline__ float ex2f(float x) {
    float y; asm("ex2.approx.f32 %0, %1;" : "=f"(y) : "f"(x)); return y;
}

__device__ __forceinline__ uint32_t rn_pack2_bf16(float a, float b) {
    uint32_t r;
    asm("cvt.rn.bf16x2.f32 %0, %1, %2;" : "=r"(r) : "f"(b), "f"(a));
    return r;
}
__device__ __forceinline__ uint32_t rn_pack2_f16(float a, float b) {
    __half2 h = __floats2half2_rn(a, b);
    return *(uint32_t*)&h;
}

// ---------------- fused fp32 -> fp16 RN convert (multi-segment) --------------
#define CVT_SEGS 7
#define CVT_CHUNK 512
struct CvtArgs {
    const float* src[CVT_SEGS];
    __half* dst[CVT_SEGS];
    int blk_end[CVT_SEGS];
    int n4[CVT_SEGS];
};

__global__ void __launch_bounds__(256) cvt_multi_kernel(const __grid_constant__ CvtArgs a)
{
    int seg = 0;
#pragma unroll
    for (int k = 0; k < CVT_SEGS - 1; k++)
        if (blockIdx.x >= (unsigned)a.blk_end[k]) seg = k + 1;
    const int local = blockIdx.x - (seg ? a.blk_end[seg - 1] : 0);
    const float* src = a.src[seg];
    __half* dst = a.dst[seg];
    const int n4 = a.n4[seg];
#pragma unroll
    for (int p = 0; p < 2; p++) {
        int i = local * CVT_CHUNK + p * 256 + threadIdx.x;
        if (i < n4) {
            float4 v = ((const float4*)src)[i];
            uint2 u;
            u.x = rn_pack2_f16(v.x, v.y);
            u.y = rn_pack2_f16(v.z, v.w);
            ((uint2*)dst)[i] = u;
        }
    }
}

// ---------------- fp16 1-MMA GEMM mainloop: 64x128 tile, occ 2 ---------------
// stage (24KB): A 8K | B 16K. NPIPE=2 -> 48KB/CTA.
#define ST_A 0
#define ST_B 8192
#define ST_BYTES 24576
#define NPIPE 2
#define GEMM_SMEM (NPIPE*ST_BYTES + 64)

__device__ __forceinline__ void gemm_mainloop(
    const CUtensorMap* mA, const CUtensorMap* mB,
    int bm, int bn, int nst, char* smem, float acc[][4][4])
{
    const uint32_t sbase = smem_to_u32(smem);
    const uint32_t mbb = sbase + NPIPE * ST_BYTES;
    const int tid = threadIdx.x;
    const int wid = tid >> 5;
    const int lane = tid & 31;
    const int wm = wid & 1;
    const int wn = wid >> 1;

    if (tid == 0) {
#pragma unroll
        for (int i = 0; i < NPIPE; i++) {
            MBARRIER_INIT(mbb + i * 8, 1);        // full
            MBARRIER_INIT(mbb + 16 + i * 8, 8);   // empty (8 warps)
        }
    }
    FENCE_ASYNC_SHARED();
    __syncthreads();

    if (tid == 0) {
#pragma unroll
        for (int s = 0; s < NPIPE; s++) {
            uint32_t mb = mbb + s * 8;
            uint32_t dst = sbase + s * ST_BYTES;
            MBARRIER_EXPECT_TX(mb, ST_BYTES);
            tma_load_2d(dst + ST_A, mA, s * 64, bm, mb);
            tma_load_2d(dst + ST_B, mB, s * 64, bn, mb);
        }
    }

    const uint32_t m16 = (lane & 7) * 16;
    const int rA = (lane & 7) + ((lane >> 3) & 1) * 8;
    const uint32_t hA = ((lane >> 4) & 1) * 16;
    const int rB = (lane & 7) + ((lane >> 4) & 1) * 8;
    const uint32_t hB = ((lane >> 3) & 1) * 16;
    uint32_t aoff[2], boff[2];
#pragma unroll
    for (int t = 0; t < 2; t++) aoff[t] = (uint32_t)(wm * 32 + t * 16 + rA) * 128;
#pragma unroll
    for (int jp = 0; jp < 2; jp++) boff[jp] = (uint32_t)(wn * 32 + jp * 16 + rB) * 128;

    int buf = 0, ph = 0;
    for (int s = 0; s < nst; s++) {
        MBARRIER_WAIT_PARITY(mbb + buf * 8, ph);
        const uint32_t sb = sbase + buf * ST_BYTES;

#pragma unroll
        for (int ks = 0; ks < 4; ks++) {
            const uint32_t cA = (ks * 32 + hA) ^ m16;
            const uint32_t cB = (ks * 32 + hB) ^ m16;
            uint32_t av[2][4];
#pragma unroll
            for (int t = 0; t < 2; t++)
                ldsm_x4(av[t], sb + ST_A + aoff[t] + cA);
            uint32_t bv[2][4];
#pragma unroll
            for (int jp = 0; jp < 2; jp++)
                ldsm_x4(bv[jp], sb + ST_B + boff[jp] + cB);
#pragma unroll
            for (int t = 0; t < 2; t++)
#pragma unroll
                for (int jp = 0; jp < 2; jp++) {
                    mma_f16(acc[t][2*jp],   av[t], &bv[jp][0]);
                    mma_f16(acc[t][2*jp+1], av[t], &bv[jp][2]);
                }
        }

        if (lane == 0) MBARRIER_ARRIVE(mbb + 16 + buf * 8);
        if (tid == 0 && s + NPIPE < nst) {
            MBARRIER_WAIT_PARITY(mbb + 16 + buf * 8, ph);
            uint32_t mb = mbb + buf * 8;
            uint32_t dst = sbase + buf * ST_BYTES;
            MBARRIER_EXPECT_TX(mb, ST_BYTES);
            tma_load_2d(dst + ST_A, mA, (s + NPIPE) * 64, bm, mb);
            tma_load_2d(dst + ST_B, mB, (s + NPIPE) * 64, bn, mb);
        }
        if (++buf == NPIPE) { buf = 0; ph ^= 1; }
    }
}

// ---------------- generic GEMM kernel (64x128 out per CTA) -------------------
template<int WRITE_F32, int WRITE_F16, int RELU>
__global__ void __launch_bounds__(256, 2) gemm_mma_kernel(
    const __grid_constant__ CUtensorMap mA,
    const __grid_constant__ CUtensorMap mB,
    const float* __restrict__ bias,
    float* __restrict__ C, __half* __restrict__ Cf,
    int N, int K)
{
    extern __shared__ char smem[];
    const int bm = blockIdx.y * 64;
    const int bn = blockIdx.x * 128;
    float acc[2][4][4];
#pragma unroll
    for (int t = 0; t < 2; t++)
#pragma unroll
        for (int j = 0; j < 4; j++)
#pragma unroll
            for (int q = 0; q < 4; q++) acc[t][j][q] = 0.f;

    gemm_mainloop(&mA, &mB, bm, bn, K >> 6, smem, acc);

    const int lane = threadIdx.x & 31;
    const int wid = threadIdx.x >> 5;
    const int g = lane >> 2, tq = lane & 3;
    const int wm = wid & 1, wn = wid >> 1;
#pragma unroll
    for (int t = 0; t < 2; t++) {
        int row = bm + wm * 32 + t * 16 + g;
#pragma unroll
        for (int j = 0; j < 4; j++) {
            int col = bn + wn * 32 + j * 8 + tq * 2;
            float2 bj = *(const float2*)&bias[col];
            float v0 = acc[t][j][0] + bj.x;
            float v1 = acc[t][j][1] + bj.y;
            float v2 = acc[t][j][2] + bj.x;
            float v3 = acc[t][j][3] + bj.y;
            if (RELU) {
                v0 = fmaxf(v0, 0.f); v1 = fmaxf(v1, 0.f);
                v2 = fmaxf(v2, 0.f); v3 = fmaxf(v3, 0.f);
            }
            if (WRITE_F32) {
                *(float2*)&C[(size_t)row * N + col]       = make_float2(v0, v1);
                *(float2*)&C[(size_t)(row + 8) * N + col] = make_float2(v2, v3);
            }
            if (WRITE_F16) {
                *(uint32_t*)&Cf[(size_t)row * N + col]       = rn_pack2_f16(v0, v1);
                *(uint32_t*)&Cf[(size_t)(row + 8) * N + col] = rn_pack2_f16(v2, v3);
            }
        }
    }
}

// ---------------- fused QKV GEMM: outputs RN bf16 (attention operands) -------
__global__ void __launch_bounds__(256, 2) gemm_qkv_kernel(
    const __grid_constant__ CUtensorMap mA,
    const __grid_constant__ CUtensorMap mB,
    const float* __restrict__ bQ, const float* __restrict__ bK, const float* __restrict__ bV,
    __nv_bfloat16* __restrict__ Q, __nv_bfloat16* __restrict__ K,
    __nv_bfloat16* __restrict__ V)
{
    extern __shared__ char smem[];
    const int bm = blockIdx.y * 64;
    const int bn = blockIdx.x * 128;
    float acc[2][4][4];
#pragma unroll
    for (int t = 0; t < 2; t++)
#pragma unroll
        for (int j = 0; j < 4; j++)
#pragma unroll
            for (int q = 0; q < 4; q++) acc[t][j][q] = 0.f;

    gemm_mainloop(&mA, &mB, bm, bn, DMODEL >> 6, smem, acc);

    const int part = blockIdx.x >> 3;          // 0=Q 1=K 2=V
    const int nb = (blockIdx.x & 7) * 128;
    const float* bias = (part == 0) ? bQ : (part == 1) ? bK : bV;
    __nv_bfloat16* O = (part == 0) ? Q : (part == 1) ? K : V;
    const float scl = (part == 0) ? QSCALE : 1.0f;

    const int lane = threadIdx.x & 31;
    const int wid = threadIdx.x >> 5;
    const int g = lane >> 2, tq = lane & 3;
    const int wm = wid & 1, wn = wid >> 1;
#pragma unroll
    for (int t = 0; t < 2; t++) {
        int row = bm + wm * 32 + t * 16 + g;
#pragma unroll
        for (int j = 0; j < 4; j++) {
            int col = nb + wn * 32 + j * 8 + tq * 2;
            float2 bj = *(const float2*)&bias[col];
            float v0 = (acc[t][j][0] + bj.x) * scl;
            float v1 = (acc[t][j][1] + bj.y) * scl;
            float v2 = (acc[t][j][2] + bj.x) * scl;
            float v3 = (acc[t][j][3] + bj.y) * scl;
            *(uint32_t*)&O[(size_t)row * DMODEL + col]       = rn_pack2_bf16(v0, v1);
            *(uint32_t*)&O[(size_t)(row + 8) * DMODEL + col] = rn_pack2_bf16(v2, v3);
        }
    }
}

// ---------------- V transpose: V[s*4+b][d] -> VT[(b*DM+d)][s] -----------------
__global__ void __launch_bounds__(256) transpose_v_kernel(
    const __nv_bfloat16* __restrict__ V, __nv_bfloat16* __restrict__ VT)
{
    __shared__ __nv_bfloat16 sh[32][64 + 4];
    const int tid = threadIdx.x;
    const int s0 = blockIdx.x * 32;
    const int d0 = blockIdx.y * 64;
    const int b  = blockIdx.z;

#pragma unroll
    for (int p = 0; p < 2; p++) {
        int idx = tid + p * 256;
        int srow = idx >> 4;
        int dq = idx & 15;
        size_t ga = ((size_t)(s0 + srow) * BATCH + b) * DMODEL + d0 + dq * 4;
        *(uint2*)&sh[srow][dq * 4] = *(const uint2*)(V + ga);
    }
    __syncthreads();
#pragma unroll
    for (int p = 0; p < 2; p++) {
        int idx = tid + p * 256;
        int drow = idx >> 3;
        int sq = idx & 7;
        __nv_bfloat16 oh[4];
#pragma unroll
        for (int k = 0; k < 4; k++) oh[k] = sh[sq * 4 + k][drow];
        size_t ga = ((size_t)(b * DMODEL + d0 + drow)) * SLEN + s0 + sq * 4;
        *(uint2*)(VT + ga) = *(uint2*)oh;
    }
}

// ---------------- Flash attention (1-term RN bf16; ctx out = fp16) -----------
#define ATT_Q 0
#define ATT_ST0 16384
#define ATT_STSZ 16384
#define ATT_CTRL (ATT_ST0 + 2*ATT_STSZ)
#define ATT_SMEM (ATT_CTRL + 64)
#define NKT (SLEN/64)

__global__ void __launch_bounds__(256, 2) attn_mma_kernel(
    const __grid_constant__ CUtensorMap mQ,
    const __grid_constant__ CUtensorMap mK,
    const __grid_constant__ CUtensorMap mV,
    __half* __restrict__ Of)
{
    extern __shared__ char smem[];
    const uint32_t sbase = smem_to_u32(smem);
    const uint32_t mbb = sbase + ATT_CTRL;
    const int tid = threadIdx.x;
    const int w = tid >> 5;
    const int lane = tid & 31;
    const int g = lane >> 2;
    const int t = lane & 3;
    const int q0 = blockIdx.x * 128;
    const int b = blockIdx.y >> 4;
    const int h = blockIdx.y & 15;
    const int xqk = b * DMODEL + h * 64;

    if (tid == 0) {
        MBARRIER_INIT(mbb + 0, 1);
        MBARRIER_INIT(mbb + 8, 1);
        MBARRIER_INIT(mbb + 16, 8);
        MBARRIER_INIT(mbb + 24, 8);
    }
    FENCE_ASYNC_SHARED();
    __syncthreads();

    if (tid == 0) {
        MBARRIER_EXPECT_TX(mbb + 0, ATT_STSZ + 16384);
        tma_load_2d(sbase + ATT_Q, &mQ, xqk, q0, mbb + 0);
        tma_load_2d(sbase + ATT_ST0 + 0,    &mK, xqk, 0, mbb + 0);
        tma_load_2d(sbase + ATT_ST0 + 8192, &mV, 0, xqk, mbb + 0);
        MBARRIER_EXPECT_TX(mbb + 8, ATT_STSZ);
        tma_load_2d(sbase + ATT_ST0 + ATT_STSZ + 0,    &mK, xqk, 64, mbb + 8);
        tma_load_2d(sbase + ATT_ST0 + ATT_STSZ + 8192, &mV, 64, xqk, mbb + 8);
    }

    const uint32_t m16 = (lane & 7) * 16;
    const int rA = (lane & 7) + ((lane >> 3) & 1) * 8;
    const uint32_t hA = ((lane >> 4) & 1) * 16;
    const int rB = (lane & 7) + ((lane >> 4) & 1) * 8;
    const uint32_t hB = ((lane >> 3) & 1) * 16;
    const uint32_t qoff = (uint32_t)(w * 16 + rA) * 128;
    uint32_t kvoff[4];
#pragma unroll
    for (int jp = 0; jp < 4; jp++) kvoff[jp] = (uint32_t)(jp * 16 + rB) * 128;

    float l_i[2] = {0.f, 0.f};
    float acc[8][4];
#pragma unroll
    for (int j = 0; j < 8; j++)
#pragma unroll
        for (int q = 0; q < 4; q++) acc[j][q] = 0.f;

    for (int s = 0; s < NKT; s++) {
        const int buf = s & 1;
        const int ph = (s >> 1) & 1;
        MBARRIER_WAIT_PARITY(mbb + buf * 8, ph);
        const uint32_t Kbu = sbase + ATT_ST0 + buf * ATT_STSZ;
        const uint32_t Vbu = Kbu + 8192;

        float sc[8][4];
#pragma unroll
        for (int j = 0; j < 8; j++)
#pragma unroll
            for (int q = 0; q < 4; q++) sc[j][q] = 0.f;

#pragma unroll
        for (int ks = 0; ks < 4; ks++) {
            const uint32_t cA = (ks * 32 + hA) ^ m16;
            const uint32_t cB = (ks * 32 + hB) ^ m16;
            uint32_t qh[4];
            ldsm_x4(qh, sbase + ATT_Q + qoff + cA);
#pragma unroll
            for (int jp = 0; jp < 4; jp++) {
                uint32_t kh[4];
                ldsm_x4(kh, Kbu + kvoff[jp] + cB);
                mma_bf16(sc[2*jp],   qh, &kh[0]);
                mma_bf16(sc[2*jp+1], qh, &kh[2]);
            }
        }

        float s0 = 0.f, s1 = 0.f;
#pragma unroll
        for (int j = 0; j < 8; j++) {
            sc[j][0] = ex2f(sc[j][0]);
            sc[j][1] = ex2f(sc[j][1]);
            sc[j][2] = ex2f(sc[j][2]);
            sc[j][3] = ex2f(sc[j][3]);
            s0 += sc[j][0] + sc[j][1];
            s1 += sc[j][2] + sc[j][3];
        }
        l_i[0] += s0;
        l_i[1] += s1;

#pragma unroll
        for (int ks = 0; ks < 4; ks++) {
            uint32_t pah[4];
            pah[0] = rn_pack2_bf16(sc[2*ks][0],   sc[2*ks][1]);
            pah[1] = rn_pack2_bf16(sc[2*ks][2],   sc[2*ks][3]);
            pah[2] = rn_pack2_bf16(sc[2*ks+1][0], sc[2*ks+1][1]);
            pah[3] = rn_pack2_bf16(sc[2*ks+1][2], sc[2*ks+1][3]);
            const uint32_t cB = (ks * 32 + hB) ^ m16;
#pragma unroll
            for (int jp = 0; jp < 4; jp++) {
                uint32_t vh[4];
                ldsm_x4(vh, Vbu + kvoff[jp] + cB);
                mma_bf16(acc[2*jp],   pah, &vh[0]);
                mma_bf16(acc[2*jp+1], pah, &vh[2]);
            }
        }

        if (lane == 0) MBARRIER_ARRIVE(mbb + 16 + buf * 8);
        if (tid == 0 && s + 2 < NKT) {
            MBARRIER_WAIT_PARITY(mbb + 16 + buf * 8, ph);
            uint32_t mb = mbb + buf * 8;
            uint32_t dst = sbase + ATT_ST0 + buf * ATT_STSZ;
            MBARRIER_EXPECT_TX(mb, ATT_STSZ);
            tma_load_2d(dst + 0,    &mK, xqk, (s + 2) * 64, mb);
            tma_load_2d(dst + 8192, &mV, (s + 2) * 64, xqk, mb);
        }
    }

    float l0 = l_i[0], l1 = l_i[1];
    l0 += __shfl_xor_sync(0xffffffffu, l0, 1);
    l0 += __shfl_xor_sync(0xffffffffu, l0, 2);
    l1 += __shfl_xor_sync(0xffffffffu, l1, 1);
    l1 += __shfl_xor_sync(0xffffffffu, l1, 2);

    const float inv0 = 1.0f / l0;
    const float inv1 = 1.0f / l1;
    const int row0 = q0 + w * 16 + g;
    const int row1 = row0 + 8;
    const size_t tok0 = (size_t)row0 * BATCH + b;
    const size_t tok1 = (size_t)row1 * BATCH + b;
#pragma unroll
    for (int j = 0; j < 8; j++) {
        const int col = h * 64 + j * 8 + t * 2;
        *(uint32_t*)&Of[tok0 * DMODEL + col] = rn_pack2_f16(acc[j][0] * inv0, acc[j][1] * inv0);
        *(uint32_t*)&Of[tok1 * DMODEL + col] = rn_pack2_f16(acc[j][2] * inv1, acc[j][3] * inv1);
    }
}

// ---------------- fused residual add + LayerNorm -----------------------------
template<int F16OUT>
__global__ void __launch_bounds__(256) add_ln_kernel(
    const float* __restrict__ A, const float* __restrict__ R,
    const float* __restrict__ gam, const float* __restrict__ bet,
    float* __restrict__ out, __half* __restrict__ Of)
{
    __shared__ float red_s[8];
    __shared__ float red_ss[8];
    __shared__ float s_mu, s_rstd;
    const int row = blockIdx.x;
    const int t = threadIdx.x;
    float4 v = ((const float4*)(A + (size_t)row * DMODEL))[t];
    float4 w = ((const float4*)(R + (size_t)row * DMODEL))[t];
    v.x += w.x; v.y += w.y; v.z += w.z; v.w += w.w;
    float s = v.x + v.y + v.z + v.w;
    float ss = v.x * v.x + v.y * v.y + v.z * v.z + v.w * v.w;
#pragma unroll
    for (int off = 16; off >= 1; off >>= 1) {
        s  += __shfl_xor_sync(0xffffffffu, s, off);
        ss += __shfl_xor_sync(0xffffffffu, ss, off);
    }
    if ((t & 31) == 0) { red_s[t >> 5] = s; red_ss[t >> 5] = ss; }
    __syncthreads();
    if (t == 0) {
        float ts = 0.f, tss = 0.f;
#pragma unroll
        for (int i = 0; i < 8; i++) { ts += red_s[i]; tss += red_ss[i]; }
        float mu = ts * (1.0f / DMODEL);
        float var = tss * (1.0f / DMODEL) - mu * mu;
        s_mu = mu;
        s_rstd = rsqrtf(var + LN_EPS);
    }
    __syncthreads();
    float mu = s_mu, rs = s_rstd;
    float4 g = ((const float4*)gam)[t], bb = ((const float4*)bet)[t];
    float4 o;
    o.x = (v.x - mu) * rs * g.x + bb.x;
    o.y = (v.y - mu) * rs * g.y + bb.y;
    o.z = (v.z - mu) * rs * g.z + bb.z;
    o.w = (v.w - mu) * rs * g.w + bb.w;
    ((float4*)(out + (size_t)row * DMODEL))[t] = o;
    if (F16OUT) {
        uint2 u;
        u.x = rn_pack2_f16(o.x, o.y);
        u.y = rn_pack2_f16(o.z, o.w);
        ((uint2*)(Of + (size_t)row * DMODEL))[t] = u;
    }
}

// ---------------- host: tensormap + launch ------------------------------------
typedef CUresult (*EncodeFn)(
    CUtensorMap*, CUtensorMapDataType, cuuint32_t, void*,
    const cuuint64_t*, const cuuint64_t*, const cuuint32_t*, const cuuint32_t*,
    CUtensorMapInterleave, CUtensorMapSwizzle, CUtensorMapL2promotion,
    CUtensorMapFloatOOBfill);

static void make_desc(EncodeFn enc, CUtensorMap* out, void* ptr,
                      uint64_t rows, uint64_t K, uint32_t box1,
                      CUtensorMapDataType dt)
{
    cuuint64_t dims[2]    = {K, rows};
    cuuint64_t strides[1] = {K * 2};
    cuuint32_t box[2]     = {64, box1};
    cuuint32_t estr[2]    = {1, 1};
    enc(out, dt, 2, ptr, dims, strides, box, estr,
        CU_TENSOR_MAP_INTERLEAVE_NONE, CU_TENSOR_MAP_SWIZZLE_128B,
        CU_TENSOR_MAP_L2_PROMOTION_L2_128B, CU_TENSOR_MAP_FLOAT_OOB_FILL_NONE);
}

extern "C" void kernel_launch(void* const* d_in, const int* in_sizes, int n_in,
                              void* d_out, int out_size)
{
    const float* X    = (const float*)d_in[0];
    const float* WQw  = (const float*)d_in[1];
    const float* WQb  = (const float*)d_in[2];
    const float* WKw  = (const float*)d_in[3];
    const float* WKb  = (const float*)d_in[4];
    const float* WVw  = (const float*)d_in[5];
    const float* WVb  = (const float*)d_in[6];
    const float* WOw  = (const float*)d_in[7];
    const float* WOb  = (const float*)d_in[8];
    const float* ln1g = (const float*)d_in[9];
    const float* ln1b = (const float*)d_in[10];
    const float* W1   = (const float*)d_in[11];
    const float* b1   = (const float*)d_in[12];
    const float* W2   = (const float*)d_in[13];
    const float* b2   = (const float*)d_in[14];
    const float* ln2g = (const float*)d_in[15];
    const float* ln2b = (const float*)d_in[16];
    float* out = (float*)d_out;

    float *Y, *X1, *M;
    cudaGetSymbolAddress((void**)&Y,  g_Y);
    cudaGetSymbolAddress((void**)&X1, g_X1);
    cudaGetSymbolAddress((void**)&M,  g_M);

    __half *Xf,*X1f,*CTXf,*HIDf,*WQKVf,*WOf,*W1f,*W2f;
    __nv_bfloat16 *Q,*K,*V,*VT;
    cudaGetSymbolAddress((void**)&Xf,   g_Xf);
    cudaGetSymbolAddress((void**)&X1f,  g_X1f);
    cudaGetSymbolAddress((void**)&CTXf, g_CTXf);
    cudaGetSymbolAddress((void**)&HIDf, g_HIDf);
    cudaGetSymbolAddress((void**)&WQKVf, g_WQKVf);
    cudaGetSymbolAddress((void**)&WOf, g_WOf);
    cudaGetSymbolAddress((void**)&W1f, g_W1f);
    cudaGetSymbolAddress((void**)&W2f, g_W2f);
    cudaGetSymbolAddress((void**)&Q,  g_Q);
    cudaGetSymbolAddress((void**)&K,  g_K);
    cudaGetSymbolAddress((void**)&V,  g_V);
    cudaGetSymbolAddress((void**)&VT, g_VT);

    EncodeFn enc = nullptr;
    {
        void* fp = nullptr;
        cudaDriverEntryPointQueryResult qr;
        cudaGetDriverEntryPoint("cuTensorMapEncodeTiled", &fp, cudaEnableDefault, &qr);
        enc = (EncodeFn)fp;
    }

    const CUtensorMapDataType F16 = CU_TENSOR_MAP_DATA_TYPE_FLOAT16;
    const CUtensorMapDataType BF16 = CU_TENSOR_MAP_DATA_TYPE_BFLOAT16;

    CUtensorMap dXf, dWQKVf, dCTXf, dWOf, dX1f, dW1f, dHIDf, dW2f;
    make_desc(enc, &dXf,  Xf,  NTOK, DMODEL, 64, F16);
    make_desc(enc, &dWQKVf, WQKVf, 3*DMODEL, DMODEL, 128, F16);
    make_desc(enc, &dCTXf, CTXf, NTOK, DMODEL, 64, F16);
    make_desc(enc, &dWOf, WOf, DMODEL, DMODEL, 128, F16);
    make_desc(enc, &dX1f, X1f, NTOK, DMODEL, 64, F16);
    make_desc(enc, &dW1f, W1f, DFFN, DMODEL, 128, F16);
    make_desc(enc, &dHIDf, HIDf, NTOK, DFFN, 64, F16);
    make_desc(enc, &dW2f, W2f, DMODEL, DFFN, 128, F16);

    CUtensorMap dQ, dK, dVT;
    make_desc(enc, &dQ, Q, SLEN, BATCH*DMODEL, 128, BF16);
    make_desc(enc, &dK, K, SLEN, BATCH*DMODEL, 64, BF16);
    make_desc(enc, &dVT, VT, BATCH*DMODEL, SLEN, 64, BF16);

    cudaFuncSetAttribute(gemm_mma_kernel<1,0,0>, cudaFuncAttributeMaxDynamicSharedMemorySize, GEMM_SMEM);
    cudaFuncSetAttribute(gemm_mma_kernel<0,1,1>, cudaFuncAttributeMaxDynamicSharedMemorySize, GEMM_SMEM);
    cudaFuncSetAttribute(gemm_qkv_kernel, cudaFuncAttributeMaxDynamicSharedMemorySize, GEMM_SMEM);
    cudaFuncSetAttribute(attn_mma_kernel, cudaFuncAttributeMaxDynamicSharedMemorySize, ATT_SMEM);

    // ---- fused fp32 -> fp16 RN converts (all 1-term) ----
    {
        CvtArgs a;
        const float* srcs[CVT_SEGS] = {X, WQw, WKw, WVw, WOw, W1, W2};
        __half* dsts[CVT_SEGS] = {Xf, WQKVf, WQKVf + DMODEL*DMODEL,
                                  WQKVf + 2*DMODEL*DMODEL, WOf, W1f, W2f};
        int n4s[CVT_SEGS] = {NTOK*DMODEL/4, DMODEL*DMODEL/4, DMODEL*DMODEL/4,
                             DMODEL*DMODEL/4, DMODEL*DMODEL/4, DFFN*DMODEL/4, DMODEL*DFFN/4};
        int cum = 0;
        for (int i = 0; i < CVT_SEGS; i++) {
            a.src[i] = srcs[i]; a.dst[i] = dsts[i]; a.n4[i] = n4s[i];
            cum += (n4s[i] + CVT_CHUNK - 1) / CVT_CHUNK;
            a.blk_end[i] = cum;
        }
        cvt_multi_kernel<<<cum, 256>>>(a);
    }

    dim3 gProj(DMODEL / 128, NTOK / 64);    // 8 x 128
    dim3 gQKV(3 * DMODEL / 128, NTOK / 64); // 24 x 128
    dim3 gFF1(DFFN / 128, NTOK / 64);       // 32 x 128

    // ---- fused QKV projection (Q pre-scaled; RN bf16 out) ----
    gemm_qkv_kernel<<<gQKV, 256, GEMM_SMEM>>>(dXf, dWQKVf,
        WQb, WKb, WVb, Q, K, V);

    // ---- V transpose for PV operand ----
    transpose_v_kernel<<<dim3(SLEN/32, DMODEL/64, BATCH), 256>>>(V, VT);

    // ---- attention (bf16 1-term, ctx out fp16) ----
    attn_mma_kernel<<<dim3(SLEN/128, BATCH*NHEAD), 256, ATT_SMEM>>>(
        dQ, dK, dVT, CTXf);

    // ---- output projection + residual LN1 ----
    gemm_mma_kernel<1,0,0><<<gProj, 256, GEMM_SMEM>>>(dCTXf, dWOf, WOb, Y, nullptr, DMODEL, DMODEL);
    add_ln_kernel<1><<<NTOK, 256>>>(Y, X, ln1g, ln1b, X1, X1f);

    // ---- MLP ----
    gemm_mma_kernel<0,1,1><<<gFF1, 256, GEMM_SMEM>>>(dX1f, dW1f, b1, nullptr, HIDf, DFFN, DMODEL);
    gemm_mma_kernel<1,0,0><<<gProj, 256, GEMM_SMEM>>>(dHIDf, dW2f, b2, M, nullptr, DMODEL, DFFN);
    add_ln_kernel<0><<<NTOK, 256>>>(M, X1, ln2g, ln2b, out, nullptr);
}

// round 15
// speedup vs baseline: 2.4992x; 1.0246x over previous
#include <cuda_runtime.h>
#include <cuda.h>
#include <cuda_bf16.h>
#include <cuda_fp16.h>
#include <cstdint>

#define SLEN 2048
#define BATCH 4
#define DMODEL 1024
#define NHEAD 16
#define DKH 64
#define DFFN 4096
#define NTOK (SLEN*BATCH)   // 8192
#define LN_EPS 1e-5f
#define QSCALE 0.18033688011112042f   // 0.125 * log2(e)

// ---------------- scratch (device globals) ----------------------------------
__device__ __align__(1024) float g_Y[NTOK*DMODEL];
__device__ __align__(1024) float g_X1[NTOK*DMODEL];
__device__ __align__(1024) float g_M[NTOK*DMODEL];

// fp16 GEMM operands (all 1-term RN)
__device__ __align__(1024) __half g_Xf[NTOK*DMODEL];
__device__ __align__(1024) __half g_X1f[NTOK*DMODEL];
__device__ __align__(1024) __half g_CTXf[NTOK*DMODEL];
__device__ __align__(1024) __half g_HIDf[NTOK*DFFN];
__device__ __align__(1024) __half g_WQKVf[3*DMODEL*DMODEL];
__device__ __align__(1024) __half g_WOf[DMODEL*DMODEL];
__device__ __align__(1024) __half g_W1f[DFFN*DMODEL];
__device__ __align__(1024) __half g_W2f[DMODEL*DFFN];

// bf16 attention operands
__device__ __align__(1024) __nv_bfloat16 g_Q[NTOK*DMODEL];
__device__ __align__(1024) __nv_bfloat16 g_K[NTOK*DMODEL];
__device__ __align__(1024) __nv_bfloat16 g_V[NTOK*DMODEL];
__device__ __align__(1024) __nv_bfloat16 g_VT[NTOK*DMODEL];

// ---------------- PTX helpers (base-ISA only) --------------------------------
__device__ __forceinline__ uint32_t smem_to_u32(const void* p) {
    uint32_t a;
    asm("{ .reg .u64 t; cvta.to.shared.u64 t, %1; cvt.u32.u64 %0, t; }" : "=r"(a) : "l"(p));
    return a;
}
#define MBARRIER_INIT(mbar, cnt) \
    asm volatile("mbarrier.init.shared.b64 [%0], %1;" :: "r"((uint32_t)(mbar)), "r"((uint32_t)(cnt)) : "memory")
#define MBARRIER_EXPECT_TX(mbar, bytes) \
    asm volatile("mbarrier.arrive.expect_tx.shared.b64 _, [%0], %1;" :: "r"((uint32_t)(mbar)), "r"((uint32_t)(bytes)) : "memory")
#define MBARRIER_ARRIVE(mbar) \
    asm volatile("mbarrier.arrive.shared.b64 _, [%0];" :: "r"((uint32_t)(mbar)) : "memory")
#define FENCE_ASYNC_SHARED() asm volatile("fence.proxy.async.shared::cta;" ::: "memory")

#define MBARRIER_WAIT_PARITY(mbar_smem_addr, phase_parity) do { \
    uint32_t _mbar = (uint32_t)(mbar_smem_addr); \
    uint32_t _parity = (uint32_t)(phase_parity); \
    uint32_t _done; \
    asm volatile("{ .reg .pred p; mbarrier.try_wait.parity.acquire.cta.shared::cta.b64 p, [%1], %2; selp.b32 %0, 1, 0, p; }" \
        : "=r"(_done) : "r"(_mbar), "r"(_parity) : "memory"); \
    if (!_done) { \
        asm volatile("{ .reg .pred P1; WAIT_LOOP_%=: mbarrier.try_wait.parity.acquire.cta.shared::cta.b64 P1, [%0], %1, 0x989680; @P1 bra.uni WAIT_DONE_%=; bra.uni WAIT_LOOP_%=; WAIT_DONE_%=: }" \
            :: "r"(_mbar), "r"(_parity) : "memory"); \
    } \
} while(0)

__device__ __forceinline__ void tma_load_2d(uint32_t dst_smem, const CUtensorMap* m,
                                            int x, int y, uint32_t mbar) {
    asm volatile(
        "cp.async.bulk.tensor.2d.shared::cta.global.tile.mbarrier::complete_tx::bytes "
        "[%0], [%1, {%2, %3}], [%4];"
        :: "r"(dst_smem), "l"(m), "r"(x), "r"(y), "r"(mbar) : "memory");
}

__device__ __forceinline__ void mma_bf16(float* d, const uint32_t* a, const uint32_t* b) {
    asm volatile(
        "mma.sync.aligned.m16n8k16.row.col.f32.bf16.bf16.f32 "
        "{%0,%1,%2,%3},{%4,%5,%6,%7},{%8,%9},{%0,%1,%2,%3};"
        : "+f"(d[0]), "+f"(d[1]), "+f"(d[2]), "+f"(d[3])
        : "r"(a[0]), "r"(a[1]), "r"(a[2]), "r"(a[3]), "r"(b[0]), "r"(b[1]));
}
__device__ __forceinline__ void mma_f16(float* d, const uint32_t* a, const uint32_t* b) {
    asm volatile(
        "mma.sync.aligned.m16n8k16.row.col.f32.f16.f16.f32 "
        "{%0,%1,%2,%3},{%4,%5,%6,%7},{%8,%9},{%0,%1,%2,%3};"
        : "+f"(d[0]), "+f"(d[1]), "+f"(d[2]), "+f"(d[3])
        : "r"(a[0]), "r"(a[1]), "r"(a[2]), "r"(a[3]), "r"(b[0]), "r"(b[1]));
}

__device__ __forceinline__ void ldsm_x4(uint32_t* r, uint32_t addr) {
    asm volatile("ldmatrix.sync.aligned.m8n8.x4.shared.b16 {%0,%1,%2,%3}, [%4];"
        : "=r"(r[0]), "=r"(r[1]), "=r"(r[2]), "=r"(r[3]) : "r"(addr));
}

__device__ __forceinline__ float ex2f(float x) {
    float y; asm("ex2.approx.f32 %0, %1;" : "=f"(y) : "f"(x)); return y;
}

__device__ __forceinline__ uint32_t rn_pack2_bf16(float a, float b) {
    uint32_t r;
    asm("cvt.rn.bf16x2.f32 %0, %1, %2;" : "=r"(r) : "f"(b), "f"(a));
    return r;
}
__device__ __forceinline__ uint32_t rn_pack2_f16(float a, float b) {
    __half2 h = __floats2half2_rn(a, b);
    return *(uint32_t*)&h;
}

// ---------------- fused fp32 -> fp16 RN convert (multi-segment) --------------
#define CVT_SEGS 7
#define CVT_CHUNK 512
struct CvtArgs {
    const float* src[CVT_SEGS];
    __half* dst[CVT_SEGS];
    int blk_end[CVT_SEGS];
    int n4[CVT_SEGS];
};

__global__ void __launch_bounds__(256) cvt_multi_kernel(const __grid_constant__ CvtArgs a)
{
    int seg = 0;
#pragma unroll
    for (int k = 0; k < CVT_SEGS - 1; k++)
        if (blockIdx.x >= (unsigned)a.blk_end[k]) seg = k + 1;
    const int local = blockIdx.x - (seg ? a.blk_end[seg - 1] : 0);
    const float* src = a.src[seg];
    __half* dst = a.dst[seg];
    const int n4 = a.n4[seg];
#pragma unroll
    for (int p = 0; p < 2; p++) {
        int i = local * CVT_CHUNK + p * 256 + threadIdx.x;
        if (i < n4) {
            float4 v = ((const float4*)src)[i];
            uint2 u;
            u.x = rn_pack2_f16(v.x, v.y);
            u.y = rn_pack2_f16(v.z, v.w);
            ((uint2*)dst)[i] = u;
        }
    }
}

// ---------------- fp16 1-MMA GEMM mainloop: 128x128 tile, occ 2 --------------
// stage (32KB): A 16K | B 16K. NPIPE=2 -> 64KB/CTA.
// warp grid 2(wm: 64 rows) x 4(wn: 32 cols); per warp 4 m16 x 4 n8 accumulators.
#define ST_A 0
#define ST_B 16384
#define ST_BYTES 32768
#define NPIPE 2
#define GEMM_SMEM (NPIPE*ST_BYTES + 64)

__device__ __forceinline__ void gemm_mainloop(
    const CUtensorMap* mA, const CUtensorMap* mB,
    int bm, int bn, int nst, char* smem, float acc[][4][4])
{
    const uint32_t sbase = smem_to_u32(smem);
    const uint32_t mbb = sbase + NPIPE * ST_BYTES;
    const int tid = threadIdx.x;
    const int wid = tid >> 5;
    const int lane = tid & 31;
    const int wm = wid & 1;        // 2 M-groups of 64 rows
    const int wn = wid >> 1;       // 4 N-groups of 32 cols

    if (tid == 0) {
#pragma unroll
        for (int i = 0; i < NPIPE; i++) {
            MBARRIER_INIT(mbb + i * 8, 1);        // full
            MBARRIER_INIT(mbb + 16 + i * 8, 8);   // empty (8 warps)
        }
    }
    FENCE_ASYNC_SHARED();
    __syncthreads();

    if (tid == 0) {
#pragma unroll
        for (int s = 0; s < NPIPE; s++) {
            uint32_t mb = mbb + s * 8;
            uint32_t dst = sbase + s * ST_BYTES;
            MBARRIER_EXPECT_TX(mb, ST_BYTES);
            tma_load_2d(dst + ST_A, mA, s * 64, bm, mb);
            tma_load_2d(dst + ST_B, mB, s * 64, bn, mb);
        }
    }

    const uint32_t m16 = (lane & 7) * 16;
    const int rA = (lane & 7) + ((lane >> 3) & 1) * 8;
    const uint32_t hA = ((lane >> 4) & 1) * 16;
    const int rB = (lane & 7) + ((lane >> 4) & 1) * 8;
    const uint32_t hB = ((lane >> 3) & 1) * 16;
    uint32_t aoff[4], boff[2];
#pragma unroll
    for (int t = 0; t < 4; t++) aoff[t] = (uint32_t)(wm * 64 + t * 16 + rA) * 128;
#pragma unroll
    for (int jp = 0; jp < 2; jp++) boff[jp] = (uint32_t)(wn * 32 + jp * 16 + rB) * 128;

    int buf = 0, ph = 0;
    for (int s = 0; s < nst; s++) {
        MBARRIER_WAIT_PARITY(mbb + buf * 8, ph);
        const uint32_t sb = sbase + buf * ST_BYTES;

#pragma unroll
        for (int ks = 0; ks < 4; ks++) {
            const uint32_t cA = (ks * 32 + hA) ^ m16;
            const uint32_t cB = (ks * 32 + hB) ^ m16;
            uint32_t av[4][4];
#pragma unroll
            for (int t = 0; t < 4; t++)
                ldsm_x4(av[t], sb + ST_A + aoff[t] + cA);
            uint32_t bv[2][4];
#pragma unroll
            for (int jp = 0; jp < 2; jp++)
                ldsm_x4(bv[jp], sb + ST_B + boff[jp] + cB);
#pragma unroll
            for (int t = 0; t < 4; t++)
#pragma unroll
                for (int jp = 0; jp < 2; jp++) {
                    mma_f16(acc[t][2*jp],   av[t], &bv[jp][0]);
                    mma_f16(acc[t][2*jp+1], av[t], &bv[jp][2]);
                }
        }

        if (lane == 0) MBARRIER_ARRIVE(mbb + 16 + buf * 8);
        if (tid == 0 && s + NPIPE < nst) {
            MBARRIER_WAIT_PARITY(mbb + 16 + buf * 8, ph);
            uint32_t mb = mbb + buf * 8;
            uint32_t dst = sbase + buf * ST_BYTES;
            MBARRIER_EXPECT_TX(mb, ST_BYTES);
            tma_load_2d(dst + ST_A, mA, (s + NPIPE) * 64, bm, mb);
            tma_load_2d(dst + ST_B, mB, (s + NPIPE) * 64, bn, mb);
        }
        if (++buf == NPIPE) { buf = 0; ph ^= 1; }
    }
}

// ---------------- generic GEMM kernel (128x128 out per CTA) ------------------
template<int WRITE_F32, int WRITE_F16, int RELU>
__global__ void __launch_bounds__(256, 2) gemm_mma_kernel(
    const __grid_constant__ CUtensorMap mA,
    const __grid_constant__ CUtensorMap mB,
    const float* __restrict__ bias,
    float* __restrict__ C, __half* __restrict__ Cf,
    int N, int K)
{
    extern __shared__ char smem[];
    const int bm = blockIdx.y * 128;
    const int bn = blockIdx.x * 128;
    float acc[4][4][4];
#pragma unroll
    for (int t = 0; t < 4; t++)
#pragma unroll
        for (int j = 0; j < 4; j++)
#pragma unroll
            for (int q = 0; q < 4; q++) acc[t][j][q] = 0.f;

    gemm_mainloop(&mA, &mB, bm, bn, K >> 6, smem, acc);

    const int lane = threadIdx.x & 31;
    const int wid = threadIdx.x >> 5;
    const int g = lane >> 2, tq = lane & 3;
    const int wm = wid & 1, wn = wid >> 1;
#pragma unroll
    for (int t = 0; t < 4; t++) {
        int row = bm + wm * 64 + t * 16 + g;
#pragma unroll
        for (int j = 0; j < 4; j++) {
            int col = bn + wn * 32 + j * 8 + tq * 2;
            float2 bj = *(const float2*)&bias[col];
            float v0 = acc[t][j][0] + bj.x;
            float v1 = acc[t][j][1] + bj.y;
            float v2 = acc[t][j][2] + bj.x;
            float v3 = acc[t][j][3] + bj.y;
            if (RELU) {
                v0 = fmaxf(v0, 0.f); v1 = fmaxf(v1, 0.f);
                v2 = fmaxf(v2, 0.f); v3 = fmaxf(v3, 0.f);
            }
            if (WRITE_F32) {
                *(float2*)&C[(size_t)row * N + col]       = make_float2(v0, v1);
                *(float2*)&C[(size_t)(row + 8) * N + col] = make_float2(v2, v3);
            }
            if (WRITE_F16) {
                *(uint32_t*)&Cf[(size_t)row * N + col]       = rn_pack2_f16(v0, v1);
                *(uint32_t*)&Cf[(size_t)(row + 8) * N + col] = rn_pack2_f16(v2, v3);
            }
        }
    }
}

// ---------------- fused QKV GEMM: outputs RN bf16 (attention operands) -------
__global__ void __launch_bounds__(256, 2) gemm_qkv_kernel(
    const __grid_constant__ CUtensorMap mA,
    const __grid_constant__ CUtensorMap mB,
    const float* __restrict__ bQ, const float* __restrict__ bK, const float* __restrict__ bV,
    __nv_bfloat16* __restrict__ Q, __nv_bfloat16* __restrict__ K,
    __nv_bfloat16* __restrict__ V)
{
    extern __shared__ char smem[];
    const int bm = blockIdx.y * 128;
    const int bn = blockIdx.x * 128;
    float acc[4][4][4];
#pragma unroll
    for (int t = 0; t < 4; t++)
#pragma unroll
        for (int j = 0; j < 4; j++)
#pragma unroll
            for (int q = 0; q < 4; q++) acc[t][j][q] = 0.f;

    gemm_mainloop(&mA, &mB, bm, bn, DMODEL >> 6, smem, acc);

    const int part = blockIdx.x >> 3;          // 0=Q 1=K 2=V
    const int nb = (blockIdx.x & 7) * 128;
    const float* bias = (part == 0) ? bQ : (part == 1) ? bK : bV;
    __nv_bfloat16* O = (part == 0) ? Q : (part == 1) ? K : V;
    const float scl = (part == 0) ? QSCALE : 1.0f;

    const int lane = threadIdx.x & 31;
    const int wid = threadIdx.x >> 5;
    const int g = lane >> 2, tq = lane & 3;
    const int wm = wid & 1, wn = wid >> 1;
#pragma unroll
    for (int t = 0; t < 4; t++) {
        int row = bm + wm * 64 + t * 16 + g;
#pragma unroll
        for (int j = 0; j < 4; j++) {
            int col = nb + wn * 32 + j * 8 + tq * 2;
            float2 bj = *(const float2*)&bias[col];
            float v0 = (acc[t][j][0] + bj.x) * scl;
            float v1 = (acc[t][j][1] + bj.y) * scl;
            float v2 = (acc[t][j][2] + bj.x) * scl;
            float v3 = (acc[t][j][3] + bj.y) * scl;
            *(uint32_t*)&O[(size_t)row * DMODEL + col]       = rn_pack2_bf16(v0, v1);
            *(uint32_t*)&O[(size_t)(row + 8) * DMODEL + col] = rn_pack2_bf16(v2, v3);
        }
    }
}

// ---------------- V transpose: V[s*4+b][d] -> VT[(b*DM+d)][s] -----------------
__global__ void __launch_bounds__(256) transpose_v_kernel(
    const __nv_bfloat16* __restrict__ V, __nv_bfloat16* __restrict__ VT)
{
    __shared__ __nv_bfloat16 sh[32][64 + 4];
    const int tid = threadIdx.x;
    const int s0 = blockIdx.x * 32;
    const int d0 = blockIdx.y * 64;
    const int b  = blockIdx.z;

#pragma unroll
    for (int p = 0; p < 2; p++) {
        int idx = tid + p * 256;
        int srow = idx >> 4;
        int dq = idx & 15;
        size_t ga = ((size_t)(s0 + srow) * BATCH + b) * DMODEL + d0 + dq * 4;
        *(uint2*)&sh[srow][dq * 4] = *(const uint2*)(V + ga);
    }
    __syncthreads();
#pragma unroll
    for (int p = 0; p < 2; p++) {
        int idx = tid + p * 256;
        int drow = idx >> 3;
        int sq = idx & 7;
        __nv_bfloat16 oh[4];
#pragma unroll
        for (int k = 0; k < 4; k++) oh[k] = sh[sq * 4 + k][drow];
        size_t ga = ((size_t)(b * DMODEL + d0 + drow)) * SLEN + s0 + sq * 4;
        *(uint2*)(VT + ga) = *(uint2*)oh;
    }
}

// ---------------- Flash attention (1-term RN bf16; ctx out = fp16) -----------
#define ATT_Q 0
#define ATT_ST0 16384
#define ATT_STSZ 16384
#define ATT_CTRL (ATT_ST0 + 2*ATT_STSZ)
#define ATT_SMEM (ATT_CTRL + 64)
#define NKT (SLEN/64)

__global__ void __launch_bounds__(256, 2) attn_mma_kernel(
    const __grid_constant__ CUtensorMap mQ,
    const __grid_constant__ CUtensorMap mK,
    const __grid_constant__ CUtensorMap mV,
    __half* __restrict__ Of)
{
    extern __shared__ char smem[];
    const uint32_t sbase = smem_to_u32(smem);
    const uint32_t mbb = sbase + ATT_CTRL;
    const int tid = threadIdx.x;
    const int w = tid >> 5;
    const int lane = tid & 31;
    const int g = lane >> 2;
    const int t = lane & 3;
    const int q0 = blockIdx.x * 128;
    const int b = blockIdx.y >> 4;
    const int h = blockIdx.y & 15;
    const int xqk = b * DMODEL + h * 64;

    if (tid == 0) {
        MBARRIER_INIT(mbb + 0, 1);
        MBARRIER_INIT(mbb + 8, 1);
        MBARRIER_INIT(mbb + 16, 8);
        MBARRIER_INIT(mbb + 24, 8);
    }
    FENCE_ASYNC_SHARED();
    __syncthreads();

    if (tid == 0) {
        MBARRIER_EXPECT_TX(mbb + 0, ATT_STSZ + 16384);
        tma_load_2d(sbase + ATT_Q, &mQ, xqk, q0, mbb + 0);
        tma_load_2d(sbase + ATT_ST0 + 0,    &mK, xqk, 0, mbb + 0);
        tma_load_2d(sbase + ATT_ST0 + 8192, &mV, 0, xqk, mbb + 0);
        MBARRIER_EXPECT_TX(mbb + 8, ATT_STSZ);
        tma_load_2d(sbase + ATT_ST0 + ATT_STSZ + 0,    &mK, xqk, 64, mbb + 8);
        tma_load_2d(sbase + ATT_ST0 + ATT_STSZ + 8192, &mV, 64, xqk, mbb + 8);
    }

    const uint32_t m16 = (lane & 7) * 16;
    const int rA = (lane & 7) + ((lane >> 3) & 1) * 8;
    const uint32_t hA = ((lane >> 4) & 1) * 16;
    const int rB = (lane & 7) + ((lane >> 4) & 1) * 8;
    const uint32_t hB = ((lane >> 3) & 1) * 16;
    const uint32_t qoff = (uint32_t)(w * 16 + rA) * 128;
    uint32_t kvoff[4];
#pragma unroll
    for (int jp = 0; jp < 4; jp++) kvoff[jp] = (uint32_t)(jp * 16 + rB) * 128;

    float l_i[2] = {0.f, 0.f};
    float acc[8][4];
#pragma unroll
    for (int j = 0; j < 8; j++)
#pragma unroll
        for (int q = 0; q < 4; q++) acc[j][q] = 0.f;

    for (int s = 0; s < NKT; s++) {
        const int buf = s & 1;
        const int ph = (s >> 1) & 1;
        MBARRIER_WAIT_PARITY(mbb + buf * 8, ph);
        const uint32_t Kbu = sbase + ATT_ST0 + buf * ATT_STSZ;
        const uint32_t Vbu = Kbu + 8192;

        float sc[8][4];
#pragma unroll
        for (int j = 0; j < 8; j++)
#pragma unroll
            for (int q = 0; q < 4; q++) sc[j][q] = 0.f;

#pragma unroll
        for (int ks = 0; ks < 4; ks++) {
            const uint32_t cA = (ks * 32 + hA) ^ m16;
            const uint32_t cB = (ks * 32 + hB) ^ m16;
            uint32_t qh[4];
            ldsm_x4(qh, sbase + ATT_Q + qoff + cA);
#pragma unroll
            for (int jp = 0; jp < 4; jp++) {
                uint32_t kh[4];
                ldsm_x4(kh, Kbu + kvoff[jp] + cB);
                mma_bf16(sc[2*jp],   qh, &kh[0]);
                mma_bf16(sc[2*jp+1], qh, &kh[2]);
            }
        }

        float s0 = 0.f, s1 = 0.f;
#pragma unroll
        for (int j = 0; j < 8; j++) {
            sc[j][0] = ex2f(sc[j][0]);
            sc[j][1] = ex2f(sc[j][1]);
            sc[j][2] = ex2f(sc[j][2]);
            sc[j][3] = ex2f(sc[j][3]);
            s0 += sc[j][0] + sc[j][1];
            s1 += sc[j][2] + sc[j][3];
        }
        l_i[0] += s0;
        l_i[1] += s1;

#pragma unroll
        for (int ks = 0; ks < 4; ks++) {
            uint32_t pah[4];
            pah[0] = rn_pack2_bf16(sc[2*ks][0],   sc[2*ks][1]);
            pah[1] = rn_pack2_bf16(sc[2*ks][2],   sc[2*ks][3]);
            pah[2] = rn_pack2_bf16(sc[2*ks+1][0], sc[2*ks+1][1]);
            pah[3] = rn_pack2_bf16(sc[2*ks+1][2], sc[2*ks+1][3]);
            const uint32_t cB = (ks * 32 + hB) ^ m16;
#pragma unroll
            for (int jp = 0; jp < 4; jp++) {
                uint32_t vh[4];
                ldsm_x4(vh, Vbu + kvoff[jp] + cB);
                mma_bf16(acc[2*jp],   pah, &vh[0]);
                mma_bf16(acc[2*jp+1], pah, &vh[2]);
            }
        }

        if (lane == 0) MBARRIER_ARRIVE(mbb + 16 + buf * 8);
        if (tid == 0 && s + 2 < NKT) {
            MBARRIER_WAIT_PARITY(mbb + 16 + buf * 8, ph);
            uint32_t mb = mbb + buf * 8;
            uint32_t dst = sbase + ATT_ST0 + buf * ATT_STSZ;
            MBARRIER_EXPECT_TX(mb, ATT_STSZ);
            tma_load_2d(dst + 0,    &mK, xqk, (s + 2) * 64, mb);
            tma_load_2d(dst + 8192, &mV, (s + 2) * 64, xqk, mb);
        }
    }

    float l0 = l_i[0], l1 = l_i[1];
    l0 += __shfl_xor_sync(0xffffffffu, l0, 1);
    l0 += __shfl_xor_sync(0xffffffffu, l0, 2);
    l1 += __shfl_xor_sync(0xffffffffu, l1, 1);
    l1 += __shfl_xor_sync(0xffffffffu, l1, 2);

    const float inv0 = 1.0f / l0;
    const float inv1 = 1.0f / l1;
    const int row0 = q0 + w * 16 + g;
    const int row1 = row0 + 8;
    const size_t tok0 = (size_t)row0 * BATCH + b;
    const size_t tok1 = (size_t)row1 * BATCH + b;
#pragma unroll
    for (int j = 0; j < 8; j++) {
        const int col = h * 64 + j * 8 + t * 2;
        *(uint32_t*)&Of[tok0 * DMODEL + col] = rn_pack2_f16(acc[j][0] * inv0, acc[j][1] * inv0);
        *(uint32_t*)&Of[tok1 * DMODEL + col] = rn_pack2_f16(acc[j][2] * inv1, acc[j][3] * inv1);
    }
}

// ---------------- fused residual add + LayerNorm -----------------------------
template<int F16OUT>
__global__ void __launch_bounds__(256) add_ln_kernel(
    const float* __restrict__ A, const float* __restrict__ R,
    const float* __restrict__ gam, const float* __restrict__ bet,
    float* __restrict__ out, __half* __restrict__ Of)
{
    __shared__ float red_s[8];
    __shared__ float red_ss[8];
    __shared__ float s_mu, s_rstd;
    const int row = blockIdx.x;
    const int t = threadIdx.x;
    float4 v = ((const float4*)(A + (size_t)row * DMODEL))[t];
    float4 w = ((const float4*)(R + (size_t)row * DMODEL))[t];
    v.x += w.x; v.y += w.y; v.z += w.z; v.w += w.w;
    float s = v.x + v.y + v.z + v.w;
    float ss = v.x * v.x + v.y * v.y + v.z * v.z + v.w * v.w;
#pragma unroll
    for (int off = 16; off >= 1; off >>= 1) {
        s  += __shfl_xor_sync(0xffffffffu, s, off);
        ss += __shfl_xor_sync(0xffffffffu, ss, off);
    }
    if ((t & 31) == 0) { red_s[t >> 5] = s; red_ss[t >> 5] = ss; }
    __syncthreads();
    if (t == 0) {
        float ts = 0.f, tss = 0.f;
#pragma unroll
        for (int i = 0; i < 8; i++) { ts += red_s[i]; tss += red_ss[i]; }
        float mu = ts * (1.0f / DMODEL);
        float var = tss * (1.0f / DMODEL) - mu * mu;
        s_mu = mu;
        s_rstd = rsqrtf(var + LN_EPS);
    }
    __syncthreads();
    float mu = s_mu, rs = s_rstd;
    float4 g = ((const float4*)gam)[t], bb = ((const float4*)bet)[t];
    float4 o;
    o.x = (v.x - mu) * rs * g.x + bb.x;
    o.y = (v.y - mu) * rs * g.y + bb.y;
    o.z = (v.z - mu) * rs * g.z + bb.z;
    o.w = (v.w - mu) * rs * g.w + bb.w;
    ((float4*)(out + (size_t)row * DMODEL))[t] = o;
    if (F16OUT) {
        uint2 u;
        u.x = rn_pack2_f16(o.x, o.y);
        u.y = rn_pack2_f16(o.z, o.w);
        ((uint2*)(Of + (size_t)row * DMODEL))[t] = u;
    }
}

// ---------------- host: tensormap + launch ------------------------------------
typedef CUresult (*EncodeFn)(
    CUtensorMap*, CUtensorMapDataType, cuuint32_t, void*,
    const cuuint64_t*, const cuuint64_t*, const cuuint32_t*, const cuuint32_t*,
    CUtensorMapInterleave, CUtensorMapSwizzle, CUtensorMapL2promotion,
    CUtensorMapFloatOOBfill);

static void make_desc(EncodeFn enc, CUtensorMap* out, void* ptr,
                      uint64_t rows, uint64_t K, uint32_t box1,
                      CUtensorMapDataType dt)
{
    cuuint64_t dims[2]    = {K, rows};
    cuuint64_t strides[1] = {K * 2};
    cuuint32_t box[2]     = {64, box1};
    cuuint32_t estr[2]    = {1, 1};
    enc(out, dt, 2, ptr, dims, strides, box, estr,
        CU_TENSOR_MAP_INTERLEAVE_NONE, CU_TENSOR_MAP_SWIZZLE_128B,
        CU_TENSOR_MAP_L2_PROMOTION_L2_128B, CU_TENSOR_MAP_FLOAT_OOB_FILL_NONE);
}

extern "C" void kernel_launch(void* const* d_in, const int* in_sizes, int n_in,
                              void* d_out, int out_size)
{
    const float* X    = (const float*)d_in[0];
    const float* WQw  = (const float*)d_in[1];
    const float* WQb  = (const float*)d_in[2];
    const float* WKw  = (const float*)d_in[3];
    const float* WKb  = (const float*)d_in[4];
    const float* WVw  = (const float*)d_in[5];
    const float* WVb  = (const float*)d_in[6];
    const float* WOw  = (const float*)d_in[7];
    const float* WOb  = (const float*)d_in[8];
    const float* ln1g = (const float*)d_in[9];
    const float* ln1b = (const float*)d_in[10];
    const float* W1   = (const float*)d_in[11];
    const float* b1   = (const float*)d_in[12];
    const float* W2   = (const float*)d_in[13];
    const float* b2   = (const float*)d_in[14];
    const float* ln2g = (const float*)d_in[15];
    const float* ln2b = (const float*)d_in[16];
    float* out = (float*)d_out;

    float *Y, *X1, *M;
    cudaGetSymbolAddress((void**)&Y,  g_Y);
    cudaGetSymbolAddress((void**)&X1, g_X1);
    cudaGetSymbolAddress((void**)&M,  g_M);

    __half *Xf,*X1f,*CTXf,*HIDf,*WQKVf,*WOf,*W1f,*W2f;
    __nv_bfloat16 *Q,*K,*V,*VT;
    cudaGetSymbolAddress((void**)&Xf,   g_Xf);
    cudaGetSymbolAddress((void**)&X1f,  g_X1f);
    cudaGetSymbolAddress((void**)&CTXf, g_CTXf);
    cudaGetSymbolAddress((void**)&HIDf, g_HIDf);
    cudaGetSymbolAddress((void**)&WQKVf, g_WQKVf);
    cudaGetSymbolAddress((void**)&WOf, g_WOf);
    cudaGetSymbolAddress((void**)&W1f, g_W1f);
    cudaGetSymbolAddress((void**)&W2f, g_W2f);
    cudaGetSymbolAddress((void**)&Q,  g_Q);
    cudaGetSymbolAddress((void**)&K,  g_K);
    cudaGetSymbolAddress((void**)&V,  g_V);
    cudaGetSymbolAddress((void**)&VT, g_VT);

    EncodeFn enc = nullptr;
    {
        void* fp = nullptr;
        cudaDriverEntryPointQueryResult qr;
        cudaGetDriverEntryPoint("cuTensorMapEncodeTiled", &fp, cudaEnableDefault, &qr);
        enc = (EncodeFn)fp;
    }

    const CUtensorMapDataType F16 = CU_TENSOR_MAP_DATA_TYPE_FLOAT16;
    const CUtensorMapDataType BF16 = CU_TENSOR_MAP_DATA_TYPE_BFLOAT16;

    CUtensorMap dXf, dWQKVf, dCTXf, dWOf, dX1f, dW1f, dHIDf, dW2f;
    make_desc(enc, &dXf,  Xf,  NTOK, DMODEL, 128, F16);
    make_desc(enc, &dWQKVf, WQKVf, 3*DMODEL, DMODEL, 128, F16);
    make_desc(enc, &dCTXf, CTXf, NTOK, DMODEL, 128, F16);
    make_desc(enc, &dWOf, WOf, DMODEL, DMODEL, 128, F16);
    make_desc(enc, &dX1f, X1f, NTOK, DMODEL, 128, F16);
    make_desc(enc, &dW1f, W1f, DFFN, DMODEL, 128, F16);
    make_desc(enc, &dHIDf, HIDf, NTOK, DFFN, 128, F16);
    make_desc(enc, &dW2f, W2f, DMODEL, DFFN, 128, F16);

    CUtensorMap dQ, dK, dVT;
    make_desc(enc, &dQ, Q, SLEN, BATCH*DMODEL, 128, BF16);
    make_desc(enc, &dK, K, SLEN, BATCH*DMODEL, 64, BF16);
    make_desc(enc, &dVT, VT, BATCH*DMODEL, SLEN, 64, BF16);

    cudaFuncSetAttribute(gemm_mma_kernel<1,0,0>, cudaFuncAttributeMaxDynamicSharedMemorySize, GEMM_SMEM);
    cudaFuncSetAttribute(gemm_mma_kernel<0,1,1>, cudaFuncAttributeMaxDynamicSharedMemorySize, GEMM_SMEM);
    cudaFuncSetAttribute(gemm_qkv_kernel, cudaFuncAttributeMaxDynamicSharedMemorySize, GEMM_SMEM);
    cudaFuncSetAttribute(attn_mma_kernel, cudaFuncAttributeMaxDynamicSharedMemorySize, ATT_SMEM);

    // ---- fused fp32 -> fp16 RN converts (all 1-term) ----
    {
        CvtArgs a;
        const float* srcs[CVT_SEGS] = {X, WQw, WKw, WVw, WOw, W1, W2};
        __half* dsts[CVT_SEGS] = {Xf, WQKVf, WQKVf + DMODEL*DMODEL,
                                  WQKVf + 2*DMODEL*DMODEL, WOf, W1f, W2f};
        int n4s[CVT_SEGS] = {NTOK*DMODEL/4, DMODEL*DMODEL/4, DMODEL*DMODEL/4,
                             DMODEL*DMODEL/4, DMODEL*DMODEL/4, DFFN*DMODEL/4, DMODEL*DFFN/4};
        int cum = 0;
        for (int i = 0; i < CVT_SEGS; i++) {
            a.src[i] = srcs[i]; a.dst[i] = dsts[i]; a.n4[i] = n4s[i];
            cum += (n4s[i] + CVT_CHUNK - 1) / CVT_CHUNK;
            a.blk_end[i] = cum;
        }
        cvt_multi_kernel<<<cum, 256>>>(a);
    }

    dim3 gProj(DMODEL / 128, NTOK / 128);    // 8 x 64
    dim3 gQKV(3 * DMODEL / 128, NTOK / 128); // 24 x 64
    dim3 gFF1(DFFN / 128, NTOK / 128);       // 32 x 64

    // ---- fused QKV projection (Q pre-scaled; RN bf16 out) ----
    gemm_qkv_kernel<<<gQKV, 256, GEMM_SMEM>>>(dXf, dWQKVf,
        WQb, WKb, WVb, Q, K, V);

    // ---- V transpose for PV operand ----
    transpose_v_kernel<<<dim3(SLEN/32, DMODEL/64, BATCH), 256>>>(V, VT);

    // ---- attention (bf16 1-term, ctx out fp16) ----
    attn_mma_kernel<<<dim3(SLEN/128, BATCH*NHEAD), 256, ATT_SMEM>>>(
        dQ, dK, dVT, CTXf);

    // ---- output projection + residual LN1 ----
    gemm_mma_kernel<1,0,0><<<gProj, 256, GEMM_SMEM>>>(dCTXf, dWOf, WOb, Y, nullptr, DMODEL, DMODEL);
    add_ln_kernel<1><<<NTOK, 256>>>(Y, X, ln1g, ln1b, X1, X1f);

    // ---- MLP ----
    gemm_mma_kernel<0,1,1><<<gFF1, 256, GEMM_SMEM>>>(dX1f, dW1f, b1, nullptr, HIDf, DFFN, DMODEL);
    gemm_mma_kernel<1,0,0><<<gProj, 256, GEMM_SMEM>>>(dHIDf, dW2f, b2, M, nullptr, DMODEL, DFFN);
    add_ln_kernel<0><<<NTOK, 256>>>(M, X1, ln2g, ln2b, out, nullptr);
}

// round 16
// speedup vs baseline: 2.5031x; 1.0016x over previous
#include <cuda_runtime.h>
#include <cuda.h>
#include <cuda_bf16.h>
#include <cuda_fp16.h>
#include <cstdint>

#define SLEN 2048
#define BATCH 4
#define DMODEL 1024
#define NHEAD 16
#define DKH 64
#define DFFN 4096
#define NTOK (SLEN*BATCH)   // 8192
#define LN_EPS 1e-5f
#define QSCALE 0.18033688011112042f   // 0.125 * log2(e)

// ---------------- scratch (device globals) ----------------------------------
__device__ __align__(1024) float g_Y[NTOK*DMODEL];
__device__ __align__(1024) float g_X1[NTOK*DMODEL];
__device__ __align__(1024) float g_M[NTOK*DMODEL];

// fp16 GEMM operands (all 1-term RN)
__device__ __align__(1024) __half g_Xf[NTOK*DMODEL];
__device__ __align__(1024) __half g_X1f[NTOK*DMODEL];
__device__ __align__(1024) __half g_CTXf[NTOK*DMODEL];
__device__ __align__(1024) __half g_HIDf[NTOK*DFFN];
__device__ __align__(1024) __half g_WQKVf[3*DMODEL*DMODEL];
__device__ __align__(1024) __half g_WOf[DMODEL*DMODEL];
__device__ __align__(1024) __half g_W1f[DFFN*DMODEL];
__device__ __align__(1024) __half g_W2f[DMODEL*DFFN];

// bf16 attention operands
__device__ __align__(1024) __nv_bfloat16 g_Q[NTOK*DMODEL];
__device__ __align__(1024) __nv_bfloat16 g_K[NTOK*DMODEL];
__device__ __align__(1024) __nv_bfloat16 g_V[NTOK*DMODEL];
__device__ __align__(1024) __nv_bfloat16 g_VT[NTOK*DMODEL];

// ---------------- PTX helpers (base-ISA only) --------------------------------
__device__ __forceinline__ uint32_t smem_to_u32(const void* p) {
    uint32_t a;
    asm("{ .reg .u64 t; cvta.to.shared.u64 t, %1; cvt.u32.u64 %0, t; }" : "=r"(a) : "l"(p));
    return a;
}
#define MBARRIER_INIT(mbar, cnt) \
    asm volatile("mbarrier.init.shared.b64 [%0], %1;" :: "r"((uint32_t)(mbar)), "r"((uint32_t)(cnt)) : "memory")
#define MBARRIER_EXPECT_TX(mbar, bytes) \
    asm volatile("mbarrier.arrive.expect_tx.shared.b64 _, [%0], %1;" :: "r"((uint32_t)(mbar)), "r"((uint32_t)(bytes)) : "memory")
#define MBARRIER_ARRIVE(mbar) \
    asm volatile("mbarrier.arrive.shared.b64 _, [%0];" :: "r"((uint32_t)(mbar)) : "memory")
#define FENCE_ASYNC_SHARED() asm volatile("fence.proxy.async.shared::cta;" ::: "memory")

#define MBARRIER_WAIT_PARITY(mbar_smem_addr, phase_parity) do { \
    uint32_t _mbar = (uint32_t)(mbar_smem_addr); \
    uint32_t _parity = (uint32_t)(phase_parity); \
    uint32_t _done; \
    asm volatile("{ .reg .pred p; mbarrier.try_wait.parity.acquire.cta.shared::cta.b64 p, [%1], %2; selp.b32 %0, 1, 0, p; }" \
        : "=r"(_done) : "r"(_mbar), "r"(_parity) : "memory"); \
    if (!_done) { \
        asm volatile("{ .reg .pred P1; WAIT_LOOP_%=: mbarrier.try_wait.parity.acquire.cta.shared::cta.b64 P1, [%0], %1, 0x989680; @P1 bra.uni WAIT_DONE_%=; bra.uni WAIT_LOOP_%=; WAIT_DONE_%=: }" \
            :: "r"(_mbar), "r"(_parity) : "memory"); \
    } \
} while(0)

__device__ __forceinline__ void tma_load_2d(uint32_t dst_smem, const CUtensorMap* m,
                                            int x, int y, uint32_t mbar) {
    asm volatile(
        "cp.async.bulk.tensor.2d.shared::cta.global.tile.mbarrier::complete_tx::bytes "
        "[%0], [%1, {%2, %3}], [%4];"
        :: "r"(dst_smem), "l"(m), "r"(x), "r"(y), "r"(mbar) : "memory");
}

__device__ __forceinline__ void mma_bf16(float* d, const uint32_t* a, const uint32_t* b) {
    asm volatile(
        "mma.sync.aligned.m16n8k16.row.col.f32.bf16.bf16.f32 "
        "{%0,%1,%2,%3},{%4,%5,%6,%7},{%8,%9},{%0,%1,%2,%3};"
        : "+f"(d[0]), "+f"(d[1]), "+f"(d[2]), "+f"(d[3])
        : "r"(a[0]), "r"(a[1]), "r"(a[2]), "r"(a[3]), "r"(b[0]), "r"(b[1]));
}
__device__ __forceinline__ void mma_f16(float* d, const uint32_t* a, const uint32_t* b) {
    asm volatile(
        "mma.sync.aligned.m16n8k16.row.col.f32.f16.f16.f32 "
        "{%0,%1,%2,%3},{%4,%5,%6,%7},{%8,%9},{%0,%1,%2,%3};"
        : "+f"(d[0]), "+f"(d[1]), "+f"(d[2]), "+f"(d[3])
        : "r"(a[0]), "r"(a[1]), "r"(a[2]), "r"(a[3]), "r"(b[0]), "r"(b[1]));
}

__device__ __forceinline__ void ldsm_x4(uint32_t* r, uint32_t addr) {
    asm volatile("ldmatrix.sync.aligned.m8n8.x4.shared.b16 {%0,%1,%2,%3}, [%4];"
        : "=r"(r[0]), "=r"(r[1]), "=r"(r[2]), "=r"(r[3]) : "r"(addr));
}

__device__ __forceinline__ float ex2f(float x) {
    float y; asm("ex2.approx.f32 %0, %1;" : "=f"(y) : "f"(x)); return y;
}

__device__ __forceinline__ uint32_t rn_pack2_bf16(float a, float b) {
    uint32_t r;
    asm("cvt.rn.bf16x2.f32 %0, %1, %2;" : "=r"(r) : "f"(b), "f"(a));
    return r;
}
__device__ __forceinline__ uint32_t rn_pack2_f16(float a, float b) {
    __half2 h = __floats2half2_rn(a, b);
    return *(uint32_t*)&h;
}

// ---------------- fused fp32 -> fp16 RN convert (multi-segment) --------------
#define CVT_SEGS 7
#define CVT_CHUNK 512
struct CvtArgs {
    const float* src[CVT_SEGS];
    __half* dst[CVT_SEGS];
    int blk_end[CVT_SEGS];
    int n4[CVT_SEGS];
};

__global__ void __launch_bounds__(256) cvt_multi_kernel(const __grid_constant__ CvtArgs a)
{
    int seg = 0;
#pragma unroll
    for (int k = 0; k < CVT_SEGS - 1; k++)
        if (blockIdx.x >= (unsigned)a.blk_end[k]) seg = k + 1;
    const int local = blockIdx.x - (seg ? a.blk_end[seg - 1] : 0);
    const float* src = a.src[seg];
    __half* dst = a.dst[seg];
    const int n4 = a.n4[seg];
#pragma unroll
    for (int p = 0; p < 2; p++) {
        int i = local * CVT_CHUNK + p * 256 + threadIdx.x;
        if (i < n4) {
            float4 v = ((const float4*)src)[i];
            uint2 u;
            u.x = rn_pack2_f16(v.x, v.y);
            u.y = rn_pack2_f16(v.z, v.w);
            ((uint2*)dst)[i] = u;
        }
    }
}

// ---------------- fp16 1-MMA GEMM mainloop: 128x128 tile, occ 2, NPIPE=3 -----
// stage (32KB): A 16K | B 16K. NPIPE=3 -> 96KB/CTA (+ctrl) -> 2 CTAs fit.
#define ST_A 0
#define ST_B 16384
#define ST_BYTES 32768
#define NPIPE 3
#define GEMM_SMEM (NPIPE*ST_BYTES + 64)

__device__ __forceinline__ void gemm_mainloop(
    const CUtensorMap* mA, const CUtensorMap* mB,
    int bm, int bn, int nst, char* smem, float acc[][4][4])
{
    const uint32_t sbase = smem_to_u32(smem);
    const uint32_t mbb = sbase + NPIPE * ST_BYTES;
    const int tid = threadIdx.x;
    const int wid = tid >> 5;
    const int lane = tid & 31;
    const int wm = wid & 1;        // 2 M-groups of 64 rows
    const int wn = wid >> 1;       // 4 N-groups of 32 cols

    if (tid == 0) {
#pragma unroll
        for (int i = 0; i < NPIPE; i++) {
            MBARRIER_INIT(mbb + i * 8, 1);             // full
            MBARRIER_INIT(mbb + NPIPE * 8 + i * 8, 8); // empty (8 warps)
        }
    }
    FENCE_ASYNC_SHARED();
    __syncthreads();

    if (tid == 0) {
#pragma unroll
        for (int s = 0; s < NPIPE; s++) {
            uint32_t mb = mbb + s * 8;
            uint32_t dst = sbase + s * ST_BYTES;
            MBARRIER_EXPECT_TX(mb, ST_BYTES);
            tma_load_2d(dst + ST_A, mA, s * 64, bm, mb);
            tma_load_2d(dst + ST_B, mB, s * 64, bn, mb);
        }
    }

    const uint32_t m16 = (lane & 7) * 16;
    const int rA = (lane & 7) + ((lane >> 3) & 1) * 8;
    const uint32_t hA = ((lane >> 4) & 1) * 16;
    const int rB = (lane & 7) + ((lane >> 4) & 1) * 8;
    const uint32_t hB = ((lane >> 3) & 1) * 16;
    uint32_t aoff[4], boff[2];
#pragma unroll
    for (int t = 0; t < 4; t++) aoff[t] = (uint32_t)(wm * 64 + t * 16 + rA) * 128;
#pragma unroll
    for (int jp = 0; jp < 2; jp++) boff[jp] = (uint32_t)(wn * 32 + jp * 16 + rB) * 128;

    int buf = 0, ph = 0;
    for (int s = 0; s < nst; s++) {
        MBARRIER_WAIT_PARITY(mbb + buf * 8, ph);
        const uint32_t sb = sbase + buf * ST_BYTES;

#pragma unroll
        for (int ks = 0; ks < 4; ks++) {
            const uint32_t cA = (ks * 32 + hA) ^ m16;
            const uint32_t cB = (ks * 32 + hB) ^ m16;
            uint32_t av[4][4];
#pragma unroll
            for (int t = 0; t < 4; t++)
                ldsm_x4(av[t], sb + ST_A + aoff[t] + cA);
            uint32_t bv[2][4];
#pragma unroll
            for (int jp = 0; jp < 2; jp++)
                ldsm_x4(bv[jp], sb + ST_B + boff[jp] + cB);
#pragma unroll
            for (int t = 0; t < 4; t++)
#pragma unroll
                for (int jp = 0; jp < 2; jp++) {
                    mma_f16(acc[t][2*jp],   av[t], &bv[jp][0]);
                    mma_f16(acc[t][2*jp+1], av[t], &bv[jp][2]);
                }
        }

        if (lane == 0) MBARRIER_ARRIVE(mbb + NPIPE * 8 + buf * 8);
        if (tid == 0 && s + NPIPE < nst) {
            MBARRIER_WAIT_PARITY(mbb + NPIPE * 8 + buf * 8, ph);
            uint32_t mb = mbb + buf * 8;
            uint32_t dst = sbase + buf * ST_BYTES;
            MBARRIER_EXPECT_TX(mb, ST_BYTES);
            tma_load_2d(dst + ST_A, mA, (s + NPIPE) * 64, bm, mb);
            tma_load_2d(dst + ST_B, mB, (s + NPIPE) * 64, bn, mb);
        }
        if (++buf == NPIPE) { buf = 0; ph ^= 1; }
    }
}

// ---------------- generic GEMM kernel (128x128 out per CTA) ------------------
template<int WRITE_F32, int WRITE_F16, int RELU>
__global__ void __launch_bounds__(256, 2) gemm_mma_kernel(
    const __grid_constant__ CUtensorMap mA,
    const __grid_constant__ CUtensorMap mB,
    const float* __restrict__ bias,
    float* __restrict__ C, __half* __restrict__ Cf,
    int N, int K)
{
    extern __shared__ char smem[];
    const int bm = blockIdx.y * 128;
    const int bn = blockIdx.x * 128;
    float acc[4][4][4];
#pragma unroll
    for (int t = 0; t < 4; t++)
#pragma unroll
        for (int j = 0; j < 4; j++)
#pragma unroll
            for (int q = 0; q < 4; q++) acc[t][j][q] = 0.f;

    gemm_mainloop(&mA, &mB, bm, bn, K >> 6, smem, acc);

    const int lane = threadIdx.x & 31;
    const int wid = threadIdx.x >> 5;
    const int g = lane >> 2, tq = lane & 3;
    const int wm = wid & 1, wn = wid >> 1;
#pragma unroll
    for (int t = 0; t < 4; t++) {
        int row = bm + wm * 64 + t * 16 + g;
#pragma unroll
        for (int j = 0; j < 4; j++) {
            int col = bn + wn * 32 + j * 8 + tq * 2;
            float2 bj = *(const float2*)&bias[col];
            float v0 = acc[t][j][0] + bj.x;
            float v1 = acc[t][j][1] + bj.y;
            float v2 = acc[t][j][2] + bj.x;
            float v3 = acc[t][j][3] + bj.y;
            if (RELU) {
                v0 = fmaxf(v0, 0.f); v1 = fmaxf(v1, 0.f);
                v2 = fmaxf(v2, 0.f); v3 = fmaxf(v3, 0.f);
            }
            if (WRITE_F32) {
                *(float2*)&C[(size_t)row * N + col]       = make_float2(v0, v1);
                *(float2*)&C[(size_t)(row + 8) * N + col] = make_float2(v2, v3);
            }
            if (WRITE_F16) {
                *(uint32_t*)&Cf[(size_t)row * N + col]       = rn_pack2_f16(v0, v1);
                *(uint32_t*)&Cf[(size_t)(row + 8) * N + col] = rn_pack2_f16(v2, v3);
            }
        }
    }
}

// ---------------- fused QKV GEMM: outputs RN bf16 (attention operands) -------
__global__ void __launch_bounds__(256, 2) gemm_qkv_kernel(
    const __grid_constant__ CUtensorMap mA,
    const __grid_constant__ CUtensorMap mB,
    const float* __restrict__ bQ, const float* __restrict__ bK, const float* __restrict__ bV,
    __nv_bfloat16* __restrict__ Q, __nv_bfloat16* __restrict__ K,
    __nv_bfloat16* __restrict__ V)
{
    extern __shared__ char smem[];
    const int bm = blockIdx.y * 128;
    const int bn = blockIdx.x * 128;
    float acc[4][4][4];
#pragma unroll
    for (int t = 0; t < 4; t++)
#pragma unroll
        for (int j = 0; j < 4; j++)
#pragma unroll
            for (int q = 0; q < 4; q++) acc[t][j][q] = 0.f;

    gemm_mainloop(&mA, &mB, bm, bn, DMODEL >> 6, smem, acc);

    const int part = blockIdx.x >> 3;          // 0=Q 1=K 2=V
    const int nb = (blockIdx.x & 7) * 128;
    const float* bias = (part == 0) ? bQ : (part == 1) ? bK : bV;
    __nv_bfloat16* O = (part == 0) ? Q : (part == 1) ? K : V;
    const float scl = (part == 0) ? QSCALE : 1.0f;

    const int lane = threadIdx.x & 31;
    const int wid = threadIdx.x >> 5;
    const int g = lane >> 2, tq = lane & 3;
    const int wm = wid & 1, wn = wid >> 1;
#pragma unroll
    for (int t = 0; t < 4; t++) {
        int row = bm + wm * 64 + t * 16 + g;
#pragma unroll
        for (int j = 0; j < 4; j++) {
            int col = nb + wn * 32 + j * 8 + tq * 2;
            float2 bj = *(const float2*)&bias[col];
            float v0 = (acc[t][j][0] + bj.x) * scl;
            float v1 = (acc[t][j][1] + bj.y) * scl;
            float v2 = (acc[t][j][2] + bj.x) * scl;
            float v3 = (acc[t][j][3] + bj.y) * scl;
            *(uint32_t*)&O[(size_t)row * DMODEL + col]       = rn_pack2_bf16(v0, v1);
            *(uint32_t*)&O[(size_t)(row + 8) * DMODEL + col] = rn_pack2_bf16(v2, v3);
        }
    }
}

// ---------------- V transpose: V[s*4+b][d] -> VT[(b*DM+d)][s] -----------------
__global__ void __launch_bounds__(256) transpose_v_kernel(
    const __nv_bfloat16* __restrict__ V, __nv_bfloat16* __restrict__ VT)
{
    __shared__ __nv_bfloat16 sh[32][64 + 4];
    const int tid = threadIdx.x;
    const int s0 = blockIdx.x * 32;
    const int d0 = blockIdx.y * 64;
    const int b  = blockIdx.z;

#pragma unroll
    for (int p = 0; p < 2; p++) {
        int idx = tid + p * 256;
        int srow = idx >> 4;
        int dq = idx & 15;
        size_t ga = ((size_t)(s0 + srow) * BATCH + b) * DMODEL + d0 + dq * 4;
        *(uint2*)&sh[srow][dq * 4] = *(const uint2*)(V + ga);
    }
    __syncthreads();
#pragma unroll
    for (int p = 0; p < 2; p++) {
        int idx = tid + p * 256;
        int drow = idx >> 3;
        int sq = idx & 7;
        __nv_bfloat16 oh[4];
#pragma unroll
        for (int k = 0; k < 4; k++) oh[k] = sh[sq * 4 + k][drow];
        size_t ga = ((size_t)(b * DMODEL + d0 + drow)) * SLEN + s0 + sq * 4;
        *(uint2*)(VT + ga) = *(uint2*)oh;
    }
}

// ---------------- Flash attention (1-term RN bf16; NPIPE=3 stages) -----------
#define ATT_Q 0
#define ATT_ST0 16384
#define ATT_STSZ 16384
#define ATT_NPIPE 3
#define ATT_CTRL (ATT_ST0 + ATT_NPIPE*ATT_STSZ)
#define ATT_SMEM (ATT_CTRL + 64)
#define NKT (SLEN/64)

__global__ void __launch_bounds__(256, 2) attn_mma_kernel(
    const __grid_constant__ CUtensorMap mQ,
    const __grid_constant__ CUtensorMap mK,
    const __grid_constant__ CUtensorMap mV,
    __half* __restrict__ Of)
{
    extern __shared__ char smem[];
    const uint32_t sbase = smem_to_u32(smem);
    const uint32_t mbb = sbase + ATT_CTRL;   // full[i]@+8i, empty[i]@+NPIPE*8+8i
    const int tid = threadIdx.x;
    const int w = tid >> 5;
    const int lane = tid & 31;
    const int g = lane >> 2;
    const int t = lane & 3;
    const int q0 = blockIdx.x * 128;
    const int b = blockIdx.y >> 4;
    const int h = blockIdx.y & 15;
    const int xqk = b * DMODEL + h * 64;

    if (tid == 0) {
#pragma unroll
        for (int i = 0; i < ATT_NPIPE; i++) {
            MBARRIER_INIT(mbb + i * 8, 1);
            MBARRIER_INIT(mbb + ATT_NPIPE * 8 + i * 8, 8);
        }
    }
    FENCE_ASYNC_SHARED();
    __syncthreads();

    if (tid == 0) {
        // stage 0 carries Q as well
        MBARRIER_EXPECT_TX(mbb + 0, ATT_STSZ + 16384);
        tma_load_2d(sbase + ATT_Q, &mQ, xqk, q0, mbb + 0);
        tma_load_2d(sbase + ATT_ST0 + 0,    &mK, xqk, 0, mbb + 0);
        tma_load_2d(sbase + ATT_ST0 + 8192, &mV, 0, xqk, mbb + 0);
#pragma unroll
        for (int s = 1; s < ATT_NPIPE; s++) {
            uint32_t mb = mbb + s * 8;
            uint32_t dst = sbase + ATT_ST0 + s * ATT_STSZ;
            MBARRIER_EXPECT_TX(mb, ATT_STSZ);
            tma_load_2d(dst + 0,    &mK, xqk, s * 64, mb);
            tma_load_2d(dst + 8192, &mV, s * 64, xqk, mb);
        }
    }

    const uint32_t m16 = (lane & 7) * 16;
    const int rA = (lane & 7) + ((lane >> 3) & 1) * 8;
    const uint32_t hA = ((lane >> 4) & 1) * 16;
    const int rB = (lane & 7) + ((lane >> 4) & 1) * 8;
    const uint32_t hB = ((lane >> 3) & 1) * 16;
    const uint32_t qoff = (uint32_t)(w * 16 + rA) * 128;
    uint32_t kvoff[4];
#pragma unroll
    for (int jp = 0; jp < 4; jp++) kvoff[jp] = (uint32_t)(jp * 16 + rB) * 128;

    float l_i[2] = {0.f, 0.f};
    float acc[8][4];
#pragma unroll
    for (int j = 0; j < 8; j++)
#pragma unroll
        for (int q = 0; q < 4; q++) acc[j][q] = 0.f;

    int buf = 0, ph = 0;
    for (int s = 0; s < NKT; s++) {
        MBARRIER_WAIT_PARITY(mbb + buf * 8, ph);
        const uint32_t Kbu = sbase + ATT_ST0 + buf * ATT_STSZ;
        const uint32_t Vbu = Kbu + 8192;

        float sc[8][4];
#pragma unroll
        for (int j = 0; j < 8; j++)
#pragma unroll
            for (int q = 0; q < 4; q++) sc[j][q] = 0.f;

#pragma unroll
        for (int ks = 0; ks < 4; ks++) {
            const uint32_t cA = (ks * 32 + hA) ^ m16;
            const uint32_t cB = (ks * 32 + hB) ^ m16;
            uint32_t qh[4];
            ldsm_x4(qh, sbase + ATT_Q + qoff + cA);
#pragma unroll
            for (int jp = 0; jp < 4; jp++) {
                uint32_t kh[4];
                ldsm_x4(kh, Kbu + kvoff[jp] + cB);
                mma_bf16(sc[2*jp],   qh, &kh[0]);
                mma_bf16(sc[2*jp+1], qh, &kh[2]);
            }
        }

        float s0 = 0.f, s1 = 0.f;
#pragma unroll
        for (int j = 0; j < 8; j++) {
            sc[j][0] = ex2f(sc[j][0]);
            sc[j][1] = ex2f(sc[j][1]);
            sc[j][2] = ex2f(sc[j][2]);
            sc[j][3] = ex2f(sc[j][3]);
            s0 += sc[j][0] + sc[j][1];
            s1 += sc[j][2] + sc[j][3];
        }
        l_i[0] += s0;
        l_i[1] += s1;

#pragma unroll
        for (int ks = 0; ks < 4; ks++) {
            uint32_t pah[4];
            pah[0] = rn_pack2_bf16(sc[2*ks][0],   sc[2*ks][1]);
            pah[1] = rn_pack2_bf16(sc[2*ks][2],   sc[2*ks][3]);
            pah[2] = rn_pack2_bf16(sc[2*ks+1][0], sc[2*ks+1][1]);
            pah[3] = rn_pack2_bf16(sc[2*ks+1][2], sc[2*ks+1][3]);
            const uint32_t cB = (ks * 32 + hB) ^ m16;
#pragma unroll
            for (int jp = 0; jp < 4; jp++) {
                uint32_t vh[4];
                ldsm_x4(vh, Vbu + kvoff[jp] + cB);
                mma_bf16(acc[2*jp],   pah, &vh[0]);
                mma_bf16(acc[2*jp+1], pah, &vh[2]);
            }
        }

        if (lane == 0) MBARRIER_ARRIVE(mbb + ATT_NPIPE * 8 + buf * 8);
        if (tid == 0 && s + ATT_NPIPE < NKT) {
            MBARRIER_WAIT_PARITY(mbb + ATT_NPIPE * 8 + buf * 8, ph);
            uint32_t mb = mbb + buf * 8;
            uint32_t dst = sbase + ATT_ST0 + buf * ATT_STSZ;
            MBARRIER_EXPECT_TX(mb, ATT_STSZ);
            tma_load_2d(dst + 0,    &mK, xqk, (s + ATT_NPIPE) * 64, mb);
            tma_load_2d(dst + 8192, &mV, (s + ATT_NPIPE) * 64, xqk, mb);
        }
        if (++buf == ATT_NPIPE) { buf = 0; ph ^= 1; }
    }

    float l0 = l_i[0], l1 = l_i[1];
    l0 += __shfl_xor_sync(0xffffffffu, l0, 1);
    l0 += __shfl_xor_sync(0xffffffffu, l0, 2);
    l1 += __shfl_xor_sync(0xffffffffu, l1, 1);
    l1 += __shfl_xor_sync(0xffffffffu, l1, 2);

    const float inv0 = 1.0f / l0;
    const float inv1 = 1.0f / l1;
    const int row0 = q0 + w * 16 + g;
    const int row1 = row0 + 8;
    const size_t tok0 = (size_t)row0 * BATCH + b;
    const size_t tok1 = (size_t)row1 * BATCH + b;
#pragma unroll
    for (int j = 0; j < 8; j++) {
        const int col = h * 64 + j * 8 + t * 2;
        *(uint32_t*)&Of[tok0 * DMODEL + col] = rn_pack2_f16(acc[j][0] * inv0, acc[j][1] * inv0);
        *(uint32_t*)&Of[tok1 * DMODEL + col] = rn_pack2_f16(acc[j][2] * inv1, acc[j][3] * inv1);
    }
}

// ---------------- fused residual add + LayerNorm -----------------------------
template<int F16OUT>
__global__ void __launch_bounds__(256) add_ln_kernel(
    const float* __restrict__ A, const float* __restrict__ R,
    const float* __restrict__ gam, const float* __restrict__ bet,
    float* __restrict__ out, __half* __restrict__ Of)
{
    __shared__ float red_s[8];
    __shared__ float red_ss[8];
    __shared__ float s_mu, s_rstd;
    const int row = blockIdx.x;
    const int t = threadIdx.x;
    float4 v = ((const float4*)(A + (size_t)row * DMODEL))[t];
    float4 w = ((const float4*)(R + (size_t)row * DMODEL))[t];
    v.x += w.x; v.y += w.y; v.z += w.z; v.w += w.w;
    float s = v.x + v.y + v.z + v.w;
    float ss = v.x * v.x + v.y * v.y + v.z * v.z + v.w * v.w;
#pragma unroll
    for (int off = 16; off >= 1; off >>= 1) {
        s  += __shfl_xor_sync(0xffffffffu, s, off);
        ss += __shfl_xor_sync(0xffffffffu, ss, off);
    }
    if ((t & 31) == 0) { red_s[t >> 5] = s; red_ss[t >> 5] = ss; }
    __syncthreads();
    if (t == 0) {
        float ts = 0.f, tss = 0.f;
#pragma unroll
        for (int i = 0; i < 8; i++) { ts += red_s[i]; tss += red_ss[i]; }
        float mu = ts * (1.0f / DMODEL);
        float var = tss * (1.0f / DMODEL) - mu * mu;
        s_mu = mu;
        s_rstd = rsqrtf(var + LN_EPS);
    }
    __syncthreads();
    float mu = s_mu, rs = s_rstd;
    float4 g = ((const float4*)gam)[t], bb = ((const float4*)bet)[t];
    float4 o;
    o.x = (v.x - mu) * rs * g.x + bb.x;
    o.y = (v.y - mu) * rs * g.y + bb.y;
    o.z = (v.z - mu) * rs * g.z + bb.z;
    o.w = (v.w - mu) * rs * g.w + bb.w;
    ((float4*)(out + (size_t)row * DMODEL))[t] = o;
    if (F16OUT) {
        uint2 u;
        u.x = rn_pack2_f16(o.x, o.y);
        u.y = rn_pack2_f16(o.z, o.w);
        ((uint2*)(Of + (size_t)row * DMODEL))[t] = u;
    }
}

// ---------------- host: tensormap + launch ------------------------------------
typedef CUresult (*EncodeFn)(
    CUtensorMap*, CUtensorMapDataType, cuuint32_t, void*,
    const cuuint64_t*, const cuuint64_t*, const cuuint32_t*, const cuuint32_t*,
    CUtensorMapInterleave, CUtensorMapSwizzle, CUtensorMapL2promotion,
    CUtensorMapFloatOOBfill);

static void make_desc(EncodeFn enc, CUtensorMap* out, void* ptr,
                      uint64_t rows, uint64_t K, uint32_t box1,
                      CUtensorMapDataType dt)
{
    cuuint64_t dims[2]    = {K, rows};
    cuuint64_t strides[1] = {K * 2};
    cuuint32_t box[2]     = {64, box1};
    cuuint32_t estr[2]    = {1, 1};
    enc(out, dt, 2, ptr, dims, strides, box, estr,
        CU_TENSOR_MAP_INTERLEAVE_NONE, CU_TENSOR_MAP_SWIZZLE_128B,
        CU_TENSOR_MAP_L2_PROMOTION_L2_128B, CU_TENSOR_MAP_FLOAT_OOB_FILL_NONE);
}

extern "C" void kernel_launch(void* const* d_in, const int* in_sizes, int n_in,
                              void* d_out, int out_size)
{
    const float* X    = (const float*)d_in[0];
    const float* WQw  = (const float*)d_in[1];
    const float* WQb  = (const float*)d_in[2];
    const float* WKw  = (const float*)d_in[3];
    const float* WKb  = (const float*)d_in[4];
    const float* WVw  = (const float*)d_in[5];
    const float* WVb  = (const float*)d_in[6];
    const float* WOw  = (const float*)d_in[7];
    const float* WOb  = (const float*)d_in[8];
    const float* ln1g = (const float*)d_in[9];
    const float* ln1b = (const float*)d_in[10];
    const float* W1   = (const float*)d_in[11];
    const float* b1   = (const float*)d_in[12];
    const float* W2   = (const float*)d_in[13];
    const float* b2   = (const float*)d_in[14];
    const float* ln2g = (const float*)d_in[15];
    const float* ln2b = (const float*)d_in[16];
    float* out = (float*)d_out;

    float *Y, *X1, *M;
    cudaGetSymbolAddress((void**)&Y,  g_Y);
    cudaGetSymbolAddress((void**)&X1, g_X1);
    cudaGetSymbolAddress((void**)&M,  g_M);

    __half *Xf,*X1f,*CTXf,*HIDf,*WQKVf,*WOf,*W1f,*W2f;
    __nv_bfloat16 *Q,*K,*V,*VT;
    cudaGetSymbolAddress((void**)&Xf,   g_Xf);
    cudaGetSymbolAddress((void**)&X1f,  g_X1f);
    cudaGetSymbolAddress((void**)&CTXf, g_CTXf);
    cudaGetSymbolAddress((void**)&HIDf, g_HIDf);
    cudaGetSymbolAddress((void**)&WQKVf, g_WQKVf);
    cudaGetSymbolAddress((void**)&WOf, g_WOf);
    cudaGetSymbolAddress((void**)&W1f, g_W1f);
    cudaGetSymbolAddress((void**)&W2f, g_W2f);
    cudaGetSymbolAddress((void**)&Q,  g_Q);
    cudaGetSymbolAddress((void**)&K,  g_K);
    cudaGetSymbolAddress((void**)&V,  g_V);
    cudaGetSymbolAddress((void**)&VT, g_VT);

    EncodeFn enc = nullptr;
    {
        void* fp = nullptr;
        cudaDriverEntryPointQueryResult qr;
        cudaGetDriverEntryPoint("cuTensorMapEncodeTiled", &fp, cudaEnableDefault, &qr);
        enc = (EncodeFn)fp;
    }

    const CUtensorMapDataType F16 = CU_TENSOR_MAP_DATA_TYPE_FLOAT16;
    const CUtensorMapDataType BF16 = CU_TENSOR_MAP_DATA_TYPE_BFLOAT16;

    CUtensorMap dXf, dWQKVf, dCTXf, dWOf, dX1f, dW1f, dHIDf, dW2f;
    make_desc(enc, &dXf,  Xf,  NTOK, DMODEL, 128, F16);
    make_desc(enc, &dWQKVf, WQKVf, 3*DMODEL, DMODEL, 128, F16);
    make_desc(enc, &dCTXf, CTXf, NTOK, DMODEL, 128, F16);
    make_desc(enc, &dWOf, WOf, DMODEL, DMODEL, 128, F16);
    make_desc(enc, &dX1f, X1f, NTOK, DMODEL, 128, F16);
    make_desc(enc, &dW1f, W1f, DFFN, DMODEL, 128, F16);
    make_desc(enc, &dHIDf, HIDf, NTOK, DFFN, 128, F16);
    make_desc(enc, &dW2f, W2f, DMODEL, DFFN, 128, F16);

    CUtensorMap dQ, dK, dVT;
    make_desc(enc, &dQ, Q, SLEN, BATCH*DMODEL, 128, BF16);
    make_desc(enc, &dK, K, SLEN, BATCH*DMODEL, 64, BF16);
    make_desc(enc, &dVT, VT, BATCH*DMODEL, SLEN, 64, BF16);

    cudaFuncSetAttribute(gemm_mma_kernel<1,0,0>, cudaFuncAttributeMaxDynamicSharedMemorySize, GEMM_SMEM);
    cudaFuncSetAttribute(gemm_mma_kernel<0,1,1>, cudaFuncAttributeMaxDynamicSharedMemorySize, GEMM_SMEM);
    cudaFuncSetAttribute(gemm_qkv_kernel, cudaFuncAttributeMaxDynamicSharedMemorySize, GEMM_SMEM);
    cudaFuncSetAttribute(attn_mma_kernel, cudaFuncAttributeMaxDynamicSharedMemorySize, ATT_SMEM);

    // ---- fused fp32 -> fp16 RN converts (all 1-term) ----
    {
        CvtArgs a;
        const float* srcs[CVT_SEGS] = {X, WQw, WKw, WVw, WOw, W1, W2};
        __half* dsts[CVT_SEGS] = {Xf, WQKVf, WQKVf + DMODEL*DMODEL,
                                  WQKVf + 2*DMODEL*DMODEL, WOf, W1f, W2f};
        int n4s[CVT_SEGS] = {NTOK*DMODEL/4, DMODEL*DMODEL/4, DMODEL*DMODEL/4,
                             DMODEL*DMODEL/4, DMODEL*DMODEL/4, DFFN*DMODEL/4, DMODEL*DFFN/4};
        int cum = 0;
        for (int i = 0; i < CVT_SEGS; i++) {
            a.src[i] = srcs[i]; a.dst[i] = dsts[i]; a.n4[i] = n4s[i];
            cum += (n4s[i] + CVT_CHUNK - 1) / CVT_CHUNK;
            a.blk_end[i] = cum;
        }
        cvt_multi_kernel<<<cum, 256>>>(a);
    }

    dim3 gProj(DMODEL / 128, NTOK / 128);    // 8 x 64
    dim3 gQKV(3 * DMODEL / 128, NTOK / 128); // 24 x 64
    dim3 gFF1(DFFN / 128, NTOK / 128);       // 32 x 64

    // ---- fused QKV projection (Q pre-scaled; RN bf16 out) ----
    gemm_qkv_kernel<<<gQKV, 256, GEMM_SMEM>>>(dXf, dWQKVf,
        WQb, WKb, WVb, Q, K, V);

    // ---- V transpose for PV operand ----
    transpose_v_kernel<<<dim3(SLEN/32, DMODEL/64, BATCH), 256>>>(V, VT);

    // ---- attention (bf16 1-term, ctx out fp16) ----
    attn_mma_kernel<<<dim3(SLEN/128, BATCH*NHEAD), 256, ATT_SMEM>>>(
        dQ, dK, dVT, CTXf);

    // ---- output projection + residual LN1 ----
    gemm_mma_kernel<1,0,0><<<gProj, 256, GEMM_SMEM>>>(dCTXf, dWOf, WOb, Y, nullptr, DMODEL, DMODEL);
    add_ln_kernel<1><<<NTOK, 256>>>(Y, X, ln1g, ln1b, X1, X1f);

    // ---- MLP ----
    gemm_mma_kernel<0,1,1><<<gFF1, 256, GEMM_SMEM>>>(dX1f, dW1f, b1, nullptr, HIDf, DFFN, DMODEL);
    gemm_mma_kernel<1,0,0><<<gProj, 256, GEMM_SMEM>>>(dHIDf, dW2f, b2, M, nullptr, DMODEL, DFFN);
    add_ln_kernel<0><<<NTOK, 256>>>(M, X1, ln2g, ln2b, out, nullptr);
}

// round 17
// speedup vs baseline: 2.5344x; 1.0125x over previous
#include <cuda_runtime.h>
#include <cuda.h>
#include <cuda_bf16.h>
#include <cuda_fp16.h>
#include <cstdint>

#define SLEN 2048
#define BATCH 4
#define DMODEL 1024
#define NHEAD 16
#define DKH 64
#define DFFN 4096
#define NTOK (SLEN*BATCH)   // 8192
#define LN_EPS 1e-5f
#define QSCALE 0.18033688011112042f   // 0.125 * log2(e)

// ---------------- scratch (device globals) ----------------------------------
__device__ __align__(1024) float g_Y[NTOK*DMODEL];
__device__ __align__(1024) float g_X1[NTOK*DMODEL];
__device__ __align__(1024) float g_M[NTOK*DMODEL];

// fp16 GEMM operands (all 1-term RN)
__device__ __align__(1024) __half g_Xf[NTOK*DMODEL];
__device__ __align__(1024) __half g_X1f[NTOK*DMODEL];
__device__ __align__(1024) __half g_CTXf[NTOK*DMODEL];
__device__ __align__(1024) __half g_HIDf[NTOK*DFFN];
__device__ __align__(1024) __half g_WQKVf[3*DMODEL*DMODEL];
__device__ __align__(1024) __half g_WOf[DMODEL*DMODEL];
__device__ __align__(1024) __half g_W1f[DFFN*DMODEL];
__device__ __align__(1024) __half g_W2f[DMODEL*DFFN];

// bf16 attention operands (V consumed in natural [s][d] layout via ldmatrix.trans)
__device__ __align__(1024) __nv_bfloat16 g_Q[NTOK*DMODEL];
__device__ __align__(1024) __nv_bfloat16 g_K[NTOK*DMODEL];
__device__ __align__(1024) __nv_bfloat16 g_V[NTOK*DMODEL];

// ---------------- PTX helpers (base-ISA only) --------------------------------
__device__ __forceinline__ uint32_t smem_to_u32(const void* p) {
    uint32_t a;
    asm("{ .reg .u64 t; cvta.to.shared.u64 t, %1; cvt.u32.u64 %0, t; }" : "=r"(a) : "l"(p));
    return a;
}
#define MBARRIER_INIT(mbar, cnt) \
    asm volatile("mbarrier.init.shared.b64 [%0], %1;" :: "r"((uint32_t)(mbar)), "r"((uint32_t)(cnt)) : "memory")
#define MBARRIER_EXPECT_TX(mbar, bytes) \
    asm volatile("mbarrier.arrive.expect_tx.shared.b64 _, [%0], %1;" :: "r"((uint32_t)(mbar)), "r"((uint32_t)(bytes)) : "memory")
#define MBARRIER_ARRIVE(mbar) \
    asm volatile("mbarrier.arrive.shared.b64 _, [%0];" :: "r"((uint32_t)(mbar)) : "memory")
#define FENCE_ASYNC_SHARED() asm volatile("fence.proxy.async.shared::cta;" ::: "memory")

#define MBARRIER_WAIT_PARITY(mbar_smem_addr, phase_parity) do { \
    uint32_t _mbar = (uint32_t)(mbar_smem_addr); \
    uint32_t _parity = (uint32_t)(phase_parity); \
    uint32_t _done; \
    asm volatile("{ .reg .pred p; mbarrier.try_wait.parity.acquire.cta.shared::cta.b64 p, [%1], %2; selp.b32 %0, 1, 0, p; }" \
        : "=r"(_done) : "r"(_mbar), "r"(_parity) : "memory"); \
    if (!_done) { \
        asm volatile("{ .reg .pred P1; WAIT_LOOP_%=: mbarrier.try_wait.parity.acquire.cta.shared::cta.b64 P1, [%0], %1, 0x989680; @P1 bra.uni WAIT_DONE_%=; bra.uni WAIT_LOOP_%=; WAIT_DONE_%=: }" \
            :: "r"(_mbar), "r"(_parity) : "memory"); \
    } \
} while(0)

__device__ __forceinline__ void tma_load_2d(uint32_t dst_smem, const CUtensorMap* m,
                                            int x, int y, uint32_t mbar) {
    asm volatile(
        "cp.async.bulk.tensor.2d.shared::cta.global.tile.mbarrier::complete_tx::bytes "
        "[%0], [%1, {%2, %3}], [%4];"
        :: "r"(dst_smem), "l"(m), "r"(x), "r"(y), "r"(mbar) : "memory");
}

__device__ __forceinline__ void mma_bf16(float* d, const uint32_t* a, const uint32_t* b) {
    asm volatile(
        "mma.sync.aligned.m16n8k16.row.col.f32.bf16.bf16.f32 "
        "{%0,%1,%2,%3},{%4,%5,%6,%7},{%8,%9},{%0,%1,%2,%3};"
        : "+f"(d[0]), "+f"(d[1]), "+f"(d[2]), "+f"(d[3])
        : "r"(a[0]), "r"(a[1]), "r"(a[2]), "r"(a[3]), "r"(b[0]), "r"(b[1]));
}
__device__ __forceinline__ void mma_f16(float* d, const uint32_t* a, const uint32_t* b) {
    asm volatile(
        "mma.sync.aligned.m16n8k16.row.col.f32.f16.f16.f32 "
        "{%0,%1,%2,%3},{%4,%5,%6,%7},{%8,%9},{%0,%1,%2,%3};"
        : "+f"(d[0]), "+f"(d[1]), "+f"(d[2]), "+f"(d[3])
        : "r"(a[0]), "r"(a[1]), "r"(a[2]), "r"(a[3]), "r"(b[0]), "r"(b[1]));
}

__device__ __forceinline__ void ldsm_x4(uint32_t* r, uint32_t addr) {
    asm volatile("ldmatrix.sync.aligned.m8n8.x4.shared.b16 {%0,%1,%2,%3}, [%4];"
        : "=r"(r[0]), "=r"(r[1]), "=r"(r[2]), "=r"(r[3]) : "r"(addr));
}
__device__ __forceinline__ void ldsm_x4_trans(uint32_t* r, uint32_t addr) {
    asm volatile("ldmatrix.sync.aligned.m8n8.x4.trans.shared.b16 {%0,%1,%2,%3}, [%4];"
        : "=r"(r[0]), "=r"(r[1]), "=r"(r[2]), "=r"(r[3]) : "r"(addr));
}

__device__ __forceinline__ float ex2f(float x) {
    float y; asm("ex2.approx.f32 %0, %1;" : "=f"(y) : "f"(x)); return y;
}

__device__ __forceinline__ uint32_t rn_pack2_bf16(float a, float b) {
    uint32_t r;
    asm("cvt.rn.bf16x2.f32 %0, %1, %2;" : "=r"(r) : "f"(b), "f"(a));
    return r;
}
__device__ __forceinline__ uint32_t rn_pack2_f16(float a, float b) {
    __half2 h = __floats2half2_rn(a, b);
    return *(uint32_t*)&h;
}

// ---------------- fused fp32 -> fp16 RN convert (multi-segment) --------------
#define CVT_SEGS 7
#define CVT_CHUNK 512
struct CvtArgs {
    const float* src[CVT_SEGS];
    __half* dst[CVT_SEGS];
    int blk_end[CVT_SEGS];
    int n4[CVT_SEGS];
};

__global__ void __launch_bounds__(256) cvt_multi_kernel(const __grid_constant__ CvtArgs a)
{
    int seg = 0;
#pragma unroll
    for (int k = 0; k < CVT_SEGS - 1; k++)
        if (blockIdx.x >= (unsigned)a.blk_end[k]) seg = k + 1;
    const int local = blockIdx.x - (seg ? a.blk_end[seg - 1] : 0);
    const float* src = a.src[seg];
    __half* dst = a.dst[seg];
    const int n4 = a.n4[seg];
#pragma unroll
    for (int p = 0; p < 2; p++) {
        int i = local * CVT_CHUNK + p * 256 + threadIdx.x;
        if (i < n4) {
            float4 v = ((const float4*)src)[i];
            uint2 u;
            u.x = rn_pack2_f16(v.x, v.y);
            u.y = rn_pack2_f16(v.z, v.w);
            ((uint2*)dst)[i] = u;
        }
    }
}

// ---------------- fp16 1-MMA GEMM mainloop: 128x128 tile, occ 2, NPIPE=3 -----
#define ST_A 0
#define ST_B 16384
#define ST_BYTES 32768
#define NPIPE 3
#define GEMM_SMEM (NPIPE*ST_BYTES + 64)

__device__ __forceinline__ void gemm_mainloop(
    const CUtensorMap* mA, const CUtensorMap* mB,
    int bm, int bn, int nst, char* smem, float acc[][4][4])
{
    const uint32_t sbase = smem_to_u32(smem);
    const uint32_t mbb = sbase + NPIPE * ST_BYTES;
    const int tid = threadIdx.x;
    const int wid = tid >> 5;
    const int lane = tid & 31;
    const int wm = wid & 1;
    const int wn = wid >> 1;

    if (tid == 0) {
#pragma unroll
        for (int i = 0; i < NPIPE; i++) {
            MBARRIER_INIT(mbb + i * 8, 1);
            MBARRIER_INIT(mbb + NPIPE * 8 + i * 8, 8);
        }
    }
    FENCE_ASYNC_SHARED();
    __syncthreads();

    if (tid == 0) {
#pragma unroll
        for (int s = 0; s < NPIPE; s++) {
            uint32_t mb = mbb + s * 8;
            uint32_t dst = sbase + s * ST_BYTES;
            MBARRIER_EXPECT_TX(mb, ST_BYTES);
            tma_load_2d(dst + ST_A, mA, s * 64, bm, mb);
            tma_load_2d(dst + ST_B, mB, s * 64, bn, mb);
        }
    }

    const uint32_t m16 = (lane & 7) * 16;
    const int rA = (lane & 7) + ((lane >> 3) & 1) * 8;
    const uint32_t hA = ((lane >> 4) & 1) * 16;
    const int rB = (lane & 7) + ((lane >> 4) & 1) * 8;
    const uint32_t hB = ((lane >> 3) & 1) * 16;
    uint32_t aoff[4], boff[2];
#pragma unroll
    for (int t = 0; t < 4; t++) aoff[t] = (uint32_t)(wm * 64 + t * 16 + rA) * 128;
#pragma unroll
    for (int jp = 0; jp < 2; jp++) boff[jp] = (uint32_t)(wn * 32 + jp * 16 + rB) * 128;

    int buf = 0, ph = 0;
    for (int s = 0; s < nst; s++) {
        MBARRIER_WAIT_PARITY(mbb + buf * 8, ph);
        const uint32_t sb = sbase + buf * ST_BYTES;

#pragma unroll
        for (int ks = 0; ks < 4; ks++) {
            const uint32_t cA = (ks * 32 + hA) ^ m16;
            const uint32_t cB = (ks * 32 + hB) ^ m16;
            uint32_t av[4][4];
#pragma unroll
            for (int t = 0; t < 4; t++)
                ldsm_x4(av[t], sb + ST_A + aoff[t] + cA);
            uint32_t bv[2][4];
#pragma unroll
            for (int jp = 0; jp < 2; jp++)
                ldsm_x4(bv[jp], sb + ST_B + boff[jp] + cB);
#pragma unroll
            for (int t = 0; t < 4; t++)
#pragma unroll
                for (int jp = 0; jp < 2; jp++) {
                    mma_f16(acc[t][2*jp],   av[t], &bv[jp][0]);
                    mma_f16(acc[t][2*jp+1], av[t], &bv[jp][2]);
                }
        }

        if (lane == 0) MBARRIER_ARRIVE(mbb + NPIPE * 8 + buf * 8);
        if (tid == 0 && s + NPIPE < nst) {
            MBARRIER_WAIT_PARITY(mbb + NPIPE * 8 + buf * 8, ph);
            uint32_t mb = mbb + buf * 8;
            uint32_t dst = sbase + buf * ST_BYTES;
            MBARRIER_EXPECT_TX(mb, ST_BYTES);
            tma_load_2d(dst + ST_A, mA, (s + NPIPE) * 64, bm, mb);
            tma_load_2d(dst + ST_B, mB, (s + NPIPE) * 64, bn, mb);
        }
        if (++buf == NPIPE) { buf = 0; ph ^= 1; }
    }
}

// ---------------- generic GEMM kernel (128x128 out per CTA) ------------------
template<int WRITE_F32, int WRITE_F16, int RELU>
__global__ void __launch_bounds__(256, 2) gemm_mma_kernel(
    const __grid_constant__ CUtensorMap mA,
    const __grid_constant__ CUtensorMap mB,
    const float* __restrict__ bias,
    float* __restrict__ C, __half* __restrict__ Cf,
    int N, int K)
{
    extern __shared__ char smem[];
    const int bm = blockIdx.y * 128;
    const int bn = blockIdx.x * 128;
    float acc[4][4][4];
#pragma unroll
    for (int t = 0; t < 4; t++)
#pragma unroll
        for (int j = 0; j < 4; j++)
#pragma unroll
            for (int q = 0; q < 4; q++) acc[t][j][q] = 0.f;

    gemm_mainloop(&mA, &mB, bm, bn, K >> 6, smem, acc);

    const int lane = threadIdx.x & 31;
    const int wid = threadIdx.x >> 5;
    const int g = lane >> 2, tq = lane & 3;
    const int wm = wid & 1, wn = wid >> 1;
#pragma unroll
    for (int t = 0; t < 4; t++) {
        int row = bm + wm * 64 + t * 16 + g;
#pragma unroll
        for (int j = 0; j < 4; j++) {
            int col = bn + wn * 32 + j * 8 + tq * 2;
            float2 bj = *(const float2*)&bias[col];
            float v0 = acc[t][j][0] + bj.x;
            float v1 = acc[t][j][1] + bj.y;
            float v2 = acc[t][j][2] + bj.x;
            float v3 = acc[t][j][3] + bj.y;
            if (RELU) {
                v0 = fmaxf(v0, 0.f); v1 = fmaxf(v1, 0.f);
                v2 = fmaxf(v2, 0.f); v3 = fmaxf(v3, 0.f);
            }
            if (WRITE_F32) {
                *(float2*)&C[(size_t)row * N + col]       = make_float2(v0, v1);
                *(float2*)&C[(size_t)(row + 8) * N + col] = make_float2(v2, v3);
            }
            if (WRITE_F16) {
                *(uint32_t*)&Cf[(size_t)row * N + col]       = rn_pack2_f16(v0, v1);
                *(uint32_t*)&Cf[(size_t)(row + 8) * N + col] = rn_pack2_f16(v2, v3);
            }
        }
    }
}

// ---------------- fused QKV GEMM: outputs RN bf16 (attention operands) -------
__global__ void __launch_bounds__(256, 2) gemm_qkv_kernel(
    const __grid_constant__ CUtensorMap mA,
    const __grid_constant__ CUtensorMap mB,
    const float* __restrict__ bQ, const float* __restrict__ bK, const float* __restrict__ bV,
    __nv_bfloat16* __restrict__ Q, __nv_bfloat16* __restrict__ K,
    __nv_bfloat16* __restrict__ V)
{
    extern __shared__ char smem[];
    const int bm = blockIdx.y * 128;
    const int bn = blockIdx.x * 128;
    float acc[4][4][4];
#pragma unroll
    for (int t = 0; t < 4; t++)
#pragma unroll
        for (int j = 0; j < 4; j++)
#pragma unroll
            for (int q = 0; q < 4; q++) acc[t][j][q] = 0.f;

    gemm_mainloop(&mA, &mB, bm, bn, DMODEL >> 6, smem, acc);

    const int part = blockIdx.x >> 3;          // 0=Q 1=K 2=V
    const int nb = (blockIdx.x & 7) * 128;
    const float* bias = (part == 0) ? bQ : (part == 1) ? bK : bV;
    __nv_bfloat16* O = (part == 0) ? Q : (part == 1) ? K : V;
    const float scl = (part == 0) ? QSCALE : 1.0f;

    const int lane = threadIdx.x & 31;
    const int wid = threadIdx.x >> 5;
    const int g = lane >> 2, tq = lane & 3;
    const int wm = wid & 1, wn = wid >> 1;
#pragma unroll
    for (int t = 0; t < 4; t++) {
        int row = bm + wm * 64 + t * 16 + g;
#pragma unroll
        for (int j = 0; j < 4; j++) {
            int col = nb + wn * 32 + j * 8 + tq * 2;
            float2 bj = *(const float2*)&bias[col];
            float v0 = (acc[t][j][0] + bj.x) * scl;
            float v1 = (acc[t][j][1] + bj.y) * scl;
            float v2 = (acc[t][j][2] + bj.x) * scl;
            float v3 = (acc[t][j][3] + bj.y) * scl;
            *(uint32_t*)&O[(size_t)row * DMODEL + col]       = rn_pack2_bf16(v0, v1);
            *(uint32_t*)&O[(size_t)(row + 8) * DMODEL + col] = rn_pack2_bf16(v2, v3);
        }
    }
}

// ---------------- Flash attention (1-term RN bf16; V via ldmatrix.trans) -----
#define ATT_Q 0
#define ATT_ST0 16384
#define ATT_STSZ 16384
#define ATT_NPIPE 3
#define ATT_CTRL (ATT_ST0 + ATT_NPIPE*ATT_STSZ)
#define ATT_SMEM (ATT_CTRL + 64)
#define NKT (SLEN/64)

__global__ void __launch_bounds__(256, 2) attn_mma_kernel(
    const __grid_constant__ CUtensorMap mQ,
    const __grid_constant__ CUtensorMap mK,
    const __grid_constant__ CUtensorMap mV,
    __half* __restrict__ Of)
{
    extern __shared__ char smem[];
    const uint32_t sbase = smem_to_u32(smem);
    const uint32_t mbb = sbase + ATT_CTRL;
    const int tid = threadIdx.x;
    const int w = tid >> 5;
    const int lane = tid & 31;
    const int g = lane >> 2;
    const int t = lane & 3;
    const int q0 = blockIdx.x * 128;
    const int b = blockIdx.y >> 4;
    const int h = blockIdx.y & 15;
    const int xqk = b * DMODEL + h * 64;

    if (tid == 0) {
#pragma unroll
        for (int i = 0; i < ATT_NPIPE; i++) {
            MBARRIER_INIT(mbb + i * 8, 1);
            MBARRIER_INIT(mbb + ATT_NPIPE * 8 + i * 8, 8);
        }
    }
    FENCE_ASYNC_SHARED();
    __syncthreads();

    if (tid == 0) {
        MBARRIER_EXPECT_TX(mbb + 0, ATT_STSZ + 16384);
        tma_load_2d(sbase + ATT_Q, &mQ, xqk, q0, mbb + 0);
        tma_load_2d(sbase + ATT_ST0 + 0,    &mK, xqk, 0, mbb + 0);
        tma_load_2d(sbase + ATT_ST0 + 8192, &mV, xqk, 0, mbb + 0);
#pragma unroll
        for (int s = 1; s < ATT_NPIPE; s++) {
            uint32_t mb = mbb + s * 8;
            uint32_t dst = sbase + ATT_ST0 + s * ATT_STSZ;
            MBARRIER_EXPECT_TX(mb, ATT_STSZ);
            tma_load_2d(dst + 0,    &mK, xqk, s * 64, mb);
            tma_load_2d(dst + 8192, &mV, xqk, s * 64, mb);
        }
    }

    const uint32_t m16 = (lane & 7) * 16;
    const int rA = (lane & 7) + ((lane >> 3) & 1) * 8;
    const uint32_t hA = ((lane >> 4) & 1) * 16;
    const int rB = (lane & 7) + ((lane >> 4) & 1) * 8;
    const uint32_t hB = ((lane >> 3) & 1) * 16;
    const uint32_t qoff = (uint32_t)(w * 16 + rA) * 128;
    uint32_t kvoff[4];
#pragma unroll
    for (int jp = 0; jp < 4; jp++) kvoff[jp] = (uint32_t)(jp * 16 + rB) * 128;

    // trans-ldmatrix lane geometry for V in natural [s][d] layout:
    // rows = s (k-dim), byte col = d offset; tiles 0/1 = k0-7/k8-15 n0-7,
    // tiles 2/3 = same k rows at n8-15 -> {r0,r1} and {r2,r3} B frags.
    const int rV = lane & 15;                 // s row within k16 block
    const uint32_t hV = ((lane >> 4) & 1) * 16;  // d byte-half (8 cols)

    float l_i[2] = {0.f, 0.f};
    float acc[8][4];
#pragma unroll
    for (int j = 0; j < 8; j++)
#pragma unroll
        for (int q = 0; q < 4; q++) acc[j][q] = 0.f;

    int buf = 0, ph = 0;
    for (int s = 0; s < NKT; s++) {
        MBARRIER_WAIT_PARITY(mbb + buf * 8, ph);
        const uint32_t Kbu = sbase + ATT_ST0 + buf * ATT_STSZ;
        const uint32_t Vbu = Kbu + 8192;

        float sc[8][4];
#pragma unroll
        for (int j = 0; j < 8; j++)
#pragma unroll
            for (int q = 0; q < 4; q++) sc[j][q] = 0.f;

#pragma unroll
        for (int ks = 0; ks < 4; ks++) {
            const uint32_t cA = (ks * 32 + hA) ^ m16;
            const uint32_t cB = (ks * 32 + hB) ^ m16;
            uint32_t qh[4];
            ldsm_x4(qh, sbase + ATT_Q + qoff + cA);
#pragma unroll
            for (int jp = 0; jp < 4; jp++) {
                uint32_t kh[4];
                ldsm_x4(kh, Kbu + kvoff[jp] + cB);
                mma_bf16(sc[2*jp],   qh, &kh[0]);
                mma_bf16(sc[2*jp+1], qh, &kh[2]);
            }
        }

        float s0 = 0.f, s1 = 0.f;
#pragma unroll
        for (int j = 0; j < 8; j++) {
            sc[j][0] = ex2f(sc[j][0]);
            sc[j][1] = ex2f(sc[j][1]);
            sc[j][2] = ex2f(sc[j][2]);
            sc[j][3] = ex2f(sc[j][3]);
            s0 += sc[j][0] + sc[j][1];
            s1 += sc[j][2] + sc[j][3];
        }
        l_i[0] += s0;
        l_i[1] += s1;

        // ctx += P V : V tiles loaded transposed from [s][d]
#pragma unroll
        for (int ks = 0; ks < 4; ks++) {
            uint32_t pah[4];
            pah[0] = rn_pack2_bf16(sc[2*ks][0],   sc[2*ks][1]);
            pah[1] = rn_pack2_bf16(sc[2*ks][2],   sc[2*ks][3]);
            pah[2] = rn_pack2_bf16(sc[2*ks+1][0], sc[2*ks+1][1]);
            pah[3] = rn_pack2_bf16(sc[2*ks+1][2], sc[2*ks+1][3]);
            const int vrow = ks * 16 + rV;                 // s index
            const uint32_t vrbase = Vbu + (uint32_t)vrow * 128;
            const uint32_t vsw = ((uint32_t)(vrow & 7)) * 16;
#pragma unroll
            for (int jp = 0; jp < 4; jp++) {
                uint32_t vh[4];
                const uint32_t vcol = ((uint32_t)(jp * 32) + hV) ^ vsw;
                ldsm_x4_trans(vh, vrbase + vcol);
                mma_bf16(acc[2*jp],   pah, &vh[0]);
                mma_bf16(acc[2*jp+1], pah, &vh[2]);
            }
        }

        if (lane == 0) MBARRIER_ARRIVE(mbb + ATT_NPIPE * 8 + buf * 8);
        if (tid == 0 && s + ATT_NPIPE < NKT) {
            MBARRIER_WAIT_PARITY(mbb + ATT_NPIPE * 8 + buf * 8, ph);
            uint32_t mb = mbb + buf * 8;
            uint32_t dst = sbase + ATT_ST0 + buf * ATT_STSZ;
            MBARRIER_EXPECT_TX(mb, ATT_STSZ);
            tma_load_2d(dst + 0,    &mK, xqk, (s + ATT_NPIPE) * 64, mb);
            tma_load_2d(dst + 8192, &mV, xqk, (s + ATT_NPIPE) * 64, mb);
        }
        if (++buf == ATT_NPIPE) { buf = 0; ph ^= 1; }
    }

    float l0 = l_i[0], l1 = l_i[1];
    l0 += __shfl_xor_sync(0xffffffffu, l0, 1);
    l0 += __shfl_xor_sync(0xffffffffu, l0, 2);
    l1 += __shfl_xor_sync(0xffffffffu, l1, 1);
    l1 += __shfl_xor_sync(0xffffffffu, l1, 2);

    const float inv0 = 1.0f / l0;
    const float inv1 = 1.0f / l1;
    const int row0 = q0 + w * 16 + g;
    const int row1 = row0 + 8;
    const size_t tok0 = (size_t)row0 * BATCH + b;
    const size_t tok1 = (size_t)row1 * BATCH + b;
#pragma unroll
    for (int j = 0; j < 8; j++) {
        const int col = h * 64 + j * 8 + t * 2;
        *(uint32_t*)&Of[tok0 * DMODEL + col] = rn_pack2_f16(acc[j][0] * inv0, acc[j][1] * inv0);
        *(uint32_t*)&Of[tok1 * DMODEL + col] = rn_pack2_f16(acc[j][2] * inv1, acc[j][3] * inv1);
    }
}

// ---------------- fused residual add + LayerNorm -----------------------------
template<int F16OUT>
__global__ void __launch_bounds__(256) add_ln_kernel(
    const float* __restrict__ A, const float* __restrict__ R,
    const float* __restrict__ gam, const float* __restrict__ bet,
    float* __restrict__ out, __half* __restrict__ Of)
{
    __shared__ float red_s[8];
    __shared__ float red_ss[8];
    __shared__ float s_mu, s_rstd;
    const int row = blockIdx.x;
    const int t = threadIdx.x;
    float4 v = ((const float4*)(A + (size_t)row * DMODEL))[t];
    float4 w = ((const float4*)(R + (size_t)row * DMODEL))[t];
    v.x += w.x; v.y += w.y; v.z += w.z; v.w += w.w;
    float s = v.x + v.y + v.z + v.w;
    float ss = v.x * v.x + v.y * v.y + v.z * v.z + v.w * v.w;
#pragma unroll
    for (int off = 16; off >= 1; off >>= 1) {
        s  += __shfl_xor_sync(0xffffffffu, s, off);
        ss += __shfl_xor_sync(0xffffffffu, ss, off);
    }
    if ((t & 31) == 0) { red_s[t >> 5] = s; red_ss[t >> 5] = ss; }
    __syncthreads();
    if (t == 0) {
        float ts = 0.f, tss = 0.f;
#pragma unroll
        for (int i = 0; i < 8; i++) { ts += red_s[i]; tss += red_ss[i]; }
        float mu = ts * (1.0f / DMODEL);
        float var = tss * (1.0f / DMODEL) - mu * mu;
        s_mu = mu;
        s_rstd = rsqrtf(var + LN_EPS);
    }
    __syncthreads();
    float mu = s_mu, rs = s_rstd;
    float4 g = ((const float4*)gam)[t], bb = ((const float4*)bet)[t];
    float4 o;
    o.x = (v.x - mu) * rs * g.x + bb.x;
    o.y = (v.y - mu) * rs * g.y + bb.y;
    o.z = (v.z - mu) * rs * g.z + bb.z;
    o.w = (v.w - mu) * rs * g.w + bb.w;
    ((float4*)(out + (size_t)row * DMODEL))[t] = o;
    if (F16OUT) {
        uint2 u;
        u.x = rn_pack2_f16(o.x, o.y);
        u.y = rn_pack2_f16(o.z, o.w);
        ((uint2*)(Of + (size_t)row * DMODEL))[t] = u;
    }
}

// ---------------- host: tensormap + launch ------------------------------------
typedef CUresult (*EncodeFn)(
    CUtensorMap*, CUtensorMapDataType, cuuint32_t, void*,
    const cuuint64_t*, const cuuint64_t*, const cuuint32_t*, const cuuint32_t*,
    CUtensorMapInterleave, CUtensorMapSwizzle, CUtensorMapL2promotion,
    CUtensorMapFloatOOBfill);

static void make_desc(EncodeFn enc, CUtensorMap* out, void* ptr,
                      uint64_t rows, uint64_t K, uint32_t box1,
                      CUtensorMapDataType dt)
{
    cuuint64_t dims[2]    = {K, rows};
    cuuint64_t strides[1] = {K * 2};
    cuuint32_t box[2]     = {64, box1};
    cuuint32_t estr[2]    = {1, 1};
    enc(out, dt, 2, ptr, dims, strides, box, estr,
        CU_TENSOR_MAP_INTERLEAVE_NONE, CU_TENSOR_MAP_SWIZZLE_128B,
        CU_TENSOR_MAP_L2_PROMOTION_L2_128B, CU_TENSOR_MAP_FLOAT_OOB_FILL_NONE);
}

extern "C" void kernel_launch(void* const* d_in, const int* in_sizes, int n_in,
                              void* d_out, int out_size)
{
    const float* X    = (const float*)d_in[0];
    const float* WQw  = (const float*)d_in[1];
    const float* WQb  = (const float*)d_in[2];
    const float* WKw  = (const float*)d_in[3];
    const float* WKb  = (const float*)d_in[4];
    const float* WVw  = (const float*)d_in[5];
    const float* WVb  = (const float*)d_in[6];
    const float* WOw  = (const float*)d_in[7];
    const float* WOb  = (const float*)d_in[8];
    const float* ln1g = (const float*)d_in[9];
    const float* ln1b = (const float*)d_in[10];
    const float* W1   = (const float*)d_in[11];
    const float* b1   = (const float*)d_in[12];
    const float* W2   = (const float*)d_in[13];
    const float* b2   = (const float*)d_in[14];
    const float* ln2g = (const float*)d_in[15];
    const float* ln2b = (const float*)d_in[16];
    float* out = (float*)d_out;

    float *Y, *X1, *M;
    cudaGetSymbolAddress((void**)&Y,  g_Y);
    cudaGetSymbolAddress((void**)&X1, g_X1);
    cudaGetSymbolAddress((void**)&M,  g_M);

    __half *Xf,*X1f,*CTXf,*HIDf,*WQKVf,*WOf,*W1f,*W2f;
    __nv_bfloat16 *Q,*K,*V;
    cudaGetSymbolAddress((void**)&Xf,   g_Xf);
    cudaGetSymbolAddress((void**)&X1f,  g_X1f);
    cudaGetSymbolAddress((void**)&CTXf, g_CTXf);
    cudaGetSymbolAddress((void**)&HIDf, g_HIDf);
    cudaGetSymbolAddress((void**)&WQKVf, g_WQKVf);
    cudaGetSymbolAddress((void**)&WOf, g_WOf);
    cudaGetSymbolAddress((void**)&W1f, g_W1f);
    cudaGetSymbolAddress((void**)&W2f, g_W2f);
    cudaGetSymbolAddress((void**)&Q,  g_Q);
    cudaGetSymbolAddress((void**)&K,  g_K);
    cudaGetSymbolAddress((void**)&V,  g_V);

    EncodeFn enc = nullptr;
    {
        void* fp = nullptr;
        cudaDriverEntryPointQueryResult qr;
        cudaGetDriverEntryPoint("cuTensorMapEncodeTiled", &fp, cudaEnableDefault, &qr);
        enc = (EncodeFn)fp;
    }

    const CUtensorMapDataType F16 = CU_TENSOR_MAP_DATA_TYPE_FLOAT16;
    const CUtensorMapDataType BF16 = CU_TENSOR_MAP_DATA_TYPE_BFLOAT16;

    CUtensorMap dXf, dWQKVf, dCTXf, dWOf, dX1f, dW1f, dHIDf, dW2f;
    make_desc(enc, &dXf,  Xf,  NTOK, DMODEL, 128, F16);
    make_desc(enc, &dWQKVf, WQKVf, 3*DMODEL, DMODEL, 128, F16);
    make_desc(enc, &dCTXf, CTXf, NTOK, DMODEL, 128, F16);
    make_desc(enc, &dWOf, WOf, DMODEL, DMODEL, 128, F16);
    make_desc(enc, &dX1f, X1f, NTOK, DMODEL, 128, F16);
    make_desc(enc, &dW1f, W1f, DFFN, DMODEL, 128, F16);
    make_desc(enc, &dHIDf, HIDf, NTOK, DFFN, 128, F16);
    make_desc(enc, &dW2f, W2f, DMODEL, DFFN, 128, F16);

    CUtensorMap dQ, dK, dV;
    make_desc(enc, &dQ, Q, SLEN, BATCH*DMODEL, 128, BF16);
    make_desc(enc, &dK, K, SLEN, BATCH*DMODEL, 64, BF16);
    make_desc(enc, &dV, V, SLEN, BATCH*DMODEL, 64, BF16);

    cudaFuncSetAttribute(gemm_mma_kernel<1,0,0>, cudaFuncAttributeMaxDynamicSharedMemorySize, GEMM_SMEM);
    cudaFuncSetAttribute(gemm_mma_kernel<0,1,1>, cudaFuncAttributeMaxDynamicSharedMemorySize, GEMM_SMEM);
    cudaFuncSetAttribute(gemm_qkv_kernel, cudaFuncAttributeMaxDynamicSharedMemorySize, GEMM_SMEM);
    cudaFuncSetAttribute(attn_mma_kernel, cudaFuncAttributeMaxDynamicSharedMemorySize, ATT_SMEM);

    // ---- fused fp32 -> fp16 RN converts (all 1-term) ----
    {
        CvtArgs a;
        const float* srcs[CVT_SEGS] = {X, WQw, WKw, WVw, WOw, W1, W2};
        __half* dsts[CVT_SEGS] = {Xf, WQKVf, WQKVf + DMODEL*DMODEL,
                                  WQKVf + 2*DMODEL*DMODEL, WOf, W1f, W2f};
        int n4s[CVT_SEGS] = {NTOK*DMODEL/4, DMODEL*DMODEL/4, DMODEL*DMODEL/4,
                             DMODEL*DMODEL/4, DMODEL*DMODEL/4, DFFN*DMODEL/4, DMODEL*DFFN/4};
        int cum = 0;
        for (int i = 0; i < CVT_SEGS; i++) {
            a.src[i] = srcs[i]; a.dst[i] = dsts[i]; a.n4[i] = n4s[i];
            cum += (n4s[i] + CVT_CHUNK - 1) / CVT_CHUNK;
            a.blk_end[i] = cum;
        }
        cvt_multi_kernel<<<cum, 256>>>(a);
    }

    dim3 gProj(DMODEL / 128, NTOK / 128);    // 8 x 64
    dim3 gQKV(3 * DMODEL / 128, NTOK / 128); // 24 x 64
    dim3 gFF1(DFFN / 128, NTOK / 128);       // 32 x 64

    // ---- fused QKV projection (Q pre-scaled; RN bf16 out) ----
    gemm_qkv_kernel<<<gQKV, 256, GEMM_SMEM>>>(dXf, dWQKVf,
        WQb, WKb, WVb, Q, K, V);

    // ---- attention (bf16 1-term; V consumed via ldmatrix.trans, no VT) ----
    attn_mma_kernel<<<dim3(SLEN/128, BATCH*NHEAD), 256, ATT_SMEM>>>(
        dQ, dK, dV, CTXf);

    // ---- output projection + residual LN1 ----
    gemm_mma_kernel<1,0,0><<<gProj, 256, GEMM_SMEM>>>(dCTXf, dWOf, WOb, Y, nullptr, DMODEL, DMODEL);
    add_ln_kernel<1><<<NTOK, 256>>>(Y, X, ln1g, ln1b, X1, X1f);

    // ---- MLP ----
    gemm_mma_kernel<0,1,1><<<gFF1, 256, GEMM_SMEM>>>(dX1f, dW1f, b1, nullptr, HIDf, DFFN, DMODEL);
    gemm_mma_kernel<1,0,0><<<gProj, 256, GEMM_SMEM>>>(dHIDf, dW2f, b2, M, nullptr, DMODEL, DFFN);
    add_ln_kernel<0><<<NTOK, 256>>>(M, X1, ln2g, ln2b, out, nullptr);
}